// round 1
// baseline (speedup 1.0000x reference)
#include <cuda_runtime.h>

// Problem constants
#define NQ    3136
#define CC    256
#define BZV   2
#define NH    8
#define HD    32
#define LL    56
#define DFFN  1024
#define SCALE 0.17677669529663687f   // 32^-0.5
#define NEGF  (-3.402823466e38f)

// ---------------- scratch (single big device buffer, offsets in floats) ----
#define SZ_BQC   (BZV*NQ*CC)          // 1,605,632
#define SZ_POOL  (BZV*LL*CC)          // 28,672
#define SZ_AW    (BZV*NH*NQ*LL)       // 2,809,856
#define SZ_FFN   (BZV*NQ*DFFN)        // 6,422,528

#define O_X       ((size_t)0)
#define O_XPR     (O_X      + SZ_BQC)
#define O_XPC     (O_XPR    + SZ_BQC)
#define O_QROW    (O_XPC    + SZ_BQC)
#define O_QCOL    (O_QROW   + SZ_BQC)
#define O_V       (O_QCOL   + SZ_BQC)
#define O_ATTN    (O_V      + SZ_BQC)
#define O_ATTNOUT (O_ATTN   + SZ_BQC)
#define O_X1      (O_ATTNOUT+ SZ_BQC)
#define O_Y       (O_X1     + SZ_BQC)
#define O_PR      (O_Y      + SZ_BQC)
#define O_PC      (O_PR     + SZ_POOL)
#define O_KROW    (O_PC     + SZ_POOL)
#define O_KCOL    (O_KROW   + SZ_POOL)
#define O_AWROW   (O_KCOL   + SZ_POOL)
#define O_AWCOL   (O_AWROW  + SZ_AW)
#define O_FFN     (O_AWCOL  + SZ_AW)
#define SZ_TOTAL  (O_FFN    + SZ_FFN)

__device__ float g_buf[SZ_TOTAL];

// ---------------- prep: transpose src (b,c,h,w)->(b,q,c); add posembs -------
__global__ __launch_bounds__(256) void prep_kernel(
    const float* __restrict__ src, const float* __restrict__ pr,
    const float* __restrict__ pc, float* __restrict__ x,
    float* __restrict__ xpr, float* __restrict__ xpc)
{
    int idx = blockIdx.x * 256 + threadIdx.x;      // over BZV*NQ*CC
    int c = idx & 255;
    int t = idx >> 8;            // b*NQ + q
    int q = t % NQ;
    int b = t / NQ;
    int i = q / LL, j = q % LL;
    float val = src[((size_t)(b * CC + c)) * NQ + q];
    x[idx] = val;
    xpr[idx] = val + pr[(b * LL + j) * CC + c];
    xpc[idx] = val + pc[(b * LL + i) * CC + c];
}

// ---------------- pooling for K path: mean over rows / cols + posemb --------
__global__ __launch_bounds__(256) void pool_kernel(
    const float* __restrict__ x, const float* __restrict__ pr,
    const float* __restrict__ pc, float* __restrict__ pooled_r,
    float* __restrict__ pooled_c)
{
    int idx = blockIdx.x * 256 + threadIdx.x;      // over BZV*LL*CC
    int c = idx & 255;
    int t = idx >> 8;
    int rc = t % LL;
    int b = t / LL;
    if (blockIdx.y == 0) {
        // pooled_r[b, j=rc, c] = mean_i x[b,(i,j),c] + posemb_row[b,j,c]
        float s = 0.f;
        #pragma unroll 8
        for (int i = 0; i < LL; i++)
            s += x[((size_t)(b * NQ) + i * LL + rc) * CC + c];
        pooled_r[idx] = s * (1.0f / LL) + pr[idx];
    } else {
        // pooled_c[b, i=rc, c] = mean_j x[b,(i,j),c] + posemb_col[b,i,c]
        float s = 0.f;
        #pragma unroll 8
        for (int j = 0; j < LL; j++)
            s += x[((size_t)(b * NQ) + rc * LL + j) * CC + c];
        pooled_c[idx] = s * (1.0f / LL) + pc[idx];
    }
}

// ---------------- generic SGEMM: out = alpha*(A[M,K] @ B[N,K]^T + bias) -----
__global__ __launch_bounds__(256) void gemm_kernel(
    const float* __restrict__ A, const float* __restrict__ B,
    const float* __restrict__ bias, float* __restrict__ out,
    int M, int N, int K, float alpha, int relu)
{
    __shared__ float As[16][128];
    __shared__ float Bs[16][64];
    int bm = blockIdx.y * 128;
    int bn = blockIdx.x * 64;
    int tid = threadIdx.x;
    int tx = tid & 15;           // n dir, 4 cols each
    int ty = tid >> 4;           // m dir, 8 rows each

    float acc[8][4];
    #pragma unroll
    for (int i = 0; i < 8; i++)
        #pragma unroll
        for (int j = 0; j < 4; j++) acc[i][j] = 0.f;

    int lr = tid >> 2;           // 0..63 row within half-tile
    int lk = tid & 3;            // float4 index along K-tile

    for (int k0 = 0; k0 < K; k0 += 16) {
        #pragma unroll
        for (int r = 0; r < 2; r++) {
            int m = lr + r * 64;
            float4 v = make_float4(0.f, 0.f, 0.f, 0.f);
            if (bm + m < M)
                v = *(const float4*)(A + (size_t)(bm + m) * K + k0 + lk * 4);
            As[lk * 4 + 0][m] = v.x; As[lk * 4 + 1][m] = v.y;
            As[lk * 4 + 2][m] = v.z; As[lk * 4 + 3][m] = v.w;
        }
        {
            float4 v = *(const float4*)(B + (size_t)(bn + lr) * K + k0 + lk * 4);
            Bs[lk * 4 + 0][lr] = v.x; Bs[lk * 4 + 1][lr] = v.y;
            Bs[lk * 4 + 2][lr] = v.z; Bs[lk * 4 + 3][lr] = v.w;
        }
        __syncthreads();
        #pragma unroll
        for (int k = 0; k < 16; k++) {
            float4 a0 = *(const float4*)&As[k][ty * 8];
            float4 a1 = *(const float4*)&As[k][ty * 8 + 4];
            float4 b0 = *(const float4*)&Bs[k][tx * 4];
            float a[8] = {a0.x, a0.y, a0.z, a0.w, a1.x, a1.y, a1.z, a1.w};
            float bb[4] = {b0.x, b0.y, b0.z, b0.w};
            #pragma unroll
            for (int i = 0; i < 8; i++)
                #pragma unroll
                for (int j = 0; j < 4; j++)
                    acc[i][j] += a[i] * bb[j];
        }
        __syncthreads();
    }

    #pragma unroll
    for (int i = 0; i < 8; i++) {
        int m = bm + ty * 8 + i;
        if (m >= M) continue;
        int n = bn + tx * 4;
        float4 o;
        o.x = (acc[i][0] + bias[n + 0]) * alpha;
        o.y = (acc[i][1] + bias[n + 1]) * alpha;
        o.z = (acc[i][2] + bias[n + 2]) * alpha;
        o.w = (acc[i][3] + bias[n + 3]) * alpha;
        if (relu) {
            o.x = fmaxf(o.x, 0.f); o.y = fmaxf(o.y, 0.f);
            o.z = fmaxf(o.z, 0.f); o.w = fmaxf(o.w, 0.f);
        }
        *(float4*)(out + (size_t)m * N + n) = o;
    }
}

// ---------------- attention scores + mask + softmax --------------------------
// aw[b,n,q,l] = softmax_l( q[b,q,n,:] . k[b,l,n,:]  masked )
__global__ __launch_bounds__(128) void scores_kernel(
    const float* __restrict__ q, const float* __restrict__ kk,
    const unsigned char* __restrict__ mask, int mstride,
    float* __restrict__ aw)
{
    __shared__ float4 Ks[LL * 8];          // 56 keys x 32 dims
    __shared__ float Sc[128][57];
    __shared__ unsigned char Ms[LL];
    int b = blockIdx.z, n = blockIdx.y;
    int q0 = blockIdx.x * 128;
    int tid = threadIdx.x;

    for (int i = tid; i < LL * 8; i += 128) {
        int w = i >> 3, d4 = i & 7;
        Ks[i] = *(const float4*)(kk + ((size_t)(b * LL + w)) * CC + n * HD + d4 * 4);
    }
    if (tid < LL) Ms[tid] = mask[b * NQ + tid * mstride];
    __syncthreads();

    int qi = q0 + tid;
    if (qi >= NQ) return;

    float4 qv[8];
    const float4* qp = (const float4*)(q + ((size_t)b * NQ + qi) * CC + n * HD);
    #pragma unroll
    for (int i = 0; i < 8; i++) qv[i] = qp[i];

    float mx = -3.0e38f;
    #pragma unroll 4
    for (int w = 0; w < LL; w++) {
        float s = 0.f;
        #pragma unroll
        for (int i = 0; i < 8; i++) {
            float4 k4 = Ks[w * 8 + i];
            s += qv[i].x * k4.x + qv[i].y * k4.y + qv[i].z * k4.z + qv[i].w * k4.w;
        }
        if (Ms[w]) s = NEGF;
        Sc[tid][w] = s;
        mx = fmaxf(mx, s);
    }
    float sum = 0.f;
    #pragma unroll 4
    for (int w = 0; w < LL; w++) {
        float e = __expf(Sc[tid][w] - mx);
        Sc[tid][w] = e;
        sum += e;
    }
    float inv = 1.0f / sum;
    float* dst = aw + (((size_t)(b * NH + n)) * NQ + qi) * LL;
    #pragma unroll 4
    for (int w = 0; w < LL; w++) dst[w] = Sc[tid][w] * inv;
}

// ---------------- RCDA recombination ----------------------------------------
// attn[b,q,n,d] = sum_h awc[b,n,q,h] * sum_w awr[b,n,q,w] * v[b,(h,w),n,d]
__global__ __launch_bounds__(64) void combine_kernel(
    const float* __restrict__ awr, const float* __restrict__ awc,
    const float* __restrict__ v, float* __restrict__ attn)
{
    __shared__ float ARs[64 * 57];
    __shared__ float ACs[64 * 57];
    __shared__ float4 Vs[LL * 8];          // one h-slab: 56 w x 32 d
    int b = blockIdx.z, n = blockIdx.y;
    int q0 = blockIdx.x * 64;              // NQ % 64 == 0
    int tid = threadIdx.x;

    const float* arg = awr + (((size_t)(b * NH + n)) * NQ + q0) * LL;
    const float* acg = awc + (((size_t)(b * NH + n)) * NQ + q0) * LL;
    for (int i = tid; i < 64 * LL; i += 64) {
        int qi = i / LL, w = i % LL;
        ARs[qi * 57 + w] = arg[i];
        ACs[qi * 57 + w] = acg[i];
    }

    float4 acc[8];
    #pragma unroll
    for (int j = 0; j < 8; j++) acc[j] = make_float4(0.f, 0.f, 0.f, 0.f);

    for (int h = 0; h < LL; h++) {
        __syncthreads();
        const float4* vg = (const float4*)(v + ((size_t)(b * NQ) + h * LL) * CC + n * HD);
        for (int jj = tid; jj < LL * 8; jj += 64) {
            int w = jj >> 3, d4 = jj & 7;
            Vs[jj] = vg[w * 64 + d4];      // row stride = 256 floats = 64 float4
        }
        __syncthreads();

        float ac = ACs[tid * 57 + h];
        #pragma unroll 4
        for (int w = 0; w < LL; w++) {
            float c2 = ac * ARs[tid * 57 + w];
            const float4* vr = &Vs[w * 8];
            #pragma unroll
            for (int j = 0; j < 8; j++) {
                float4 vv = vr[j];
                acc[j].x += c2 * vv.x;
                acc[j].y += c2 * vv.y;
                acc[j].z += c2 * vv.z;
                acc[j].w += c2 * vv.w;
            }
        }
    }

    float4* dst = (float4*)(attn + ((size_t)(b * NQ) + q0 + tid) * CC + n * HD);
    #pragma unroll
    for (int j = 0; j < 8; j++) dst[j] = acc[j];
}

// ---------------- residual + layernorm (optional transposed output) ---------
__global__ __launch_bounds__(256) void add_ln_kernel(
    const float* __restrict__ A, const float* __restrict__ B,
    const float* __restrict__ g, const float* __restrict__ be,
    float* __restrict__ out, int transpose_out)
{
    int row = blockIdx.x;                  // b*NQ + q
    int c = threadIdx.x;                   // 0..255
    size_t idx = (size_t)row * CC + c;
    float v = A[idx] + B[idx];
    float s = v, s2 = v * v;
    #pragma unroll
    for (int o = 16; o; o >>= 1) {
        s  += __shfl_xor_sync(0xffffffffu, s,  o);
        s2 += __shfl_xor_sync(0xffffffffu, s2, o);
    }
    __shared__ float rs[8], rs2[8];
    __shared__ float mean_s, rstd_s;
    int w = c >> 5;
    if ((c & 31) == 0) { rs[w] = s; rs2[w] = s2; }
    __syncthreads();
    if (c == 0) {
        float S = 0.f, S2 = 0.f;
        #pragma unroll
        for (int i = 0; i < 8; i++) { S += rs[i]; S2 += rs2[i]; }
        float m = S * (1.0f / CC);
        float var = S2 * (1.0f / CC) - m * m;
        mean_s = m;
        rstd_s = rsqrtf(var + 1e-5f);
    }
    __syncthreads();
    float res = (v - mean_s) * rstd_s * g[c] + be[c];
    if (transpose_out) {
        int q = row % NQ, b = row / NQ;
        out[((size_t)(b * CC + c)) * NQ + q] = res;
    } else {
        out[idx] = res;
    }
}

// ---------------- launch ------------------------------------------------------
extern "C" void kernel_launch(void* const* d_in, const int* in_sizes, int n_in,
                              void* d_out, int out_size)
{
    const float* src   = (const float*)d_in[0];
    const unsigned char* pm = (const unsigned char*)d_in[1];
    const float* pr    = (const float*)d_in[2];
    const float* pc    = (const float*)d_in[3];
    const float* w_q_row = (const float*)d_in[4];
    const float* b_q_row = (const float*)d_in[5];
    const float* w_q_col = (const float*)d_in[6];
    const float* b_q_col = (const float*)d_in[7];
    const float* w_k_row = (const float*)d_in[8];
    const float* b_k_row = (const float*)d_in[9];
    const float* w_k_col = (const float*)d_in[10];
    const float* b_k_col = (const float*)d_in[11];
    const float* w_v   = (const float*)d_in[12];
    const float* b_v   = (const float*)d_in[13];
    const float* w_out = (const float*)d_in[14];
    const float* b_out = (const float*)d_in[15];
    const float* n1g   = (const float*)d_in[16];
    const float* n1b   = (const float*)d_in[17];
    const float* l1w   = (const float*)d_in[18];
    const float* l1b   = (const float*)d_in[19];
    const float* l2w   = (const float*)d_in[20];
    const float* l2b   = (const float*)d_in[21];
    const float* n2g   = (const float*)d_in[22];
    const float* n2b   = (const float*)d_in[23];
    float* out = (float*)d_out;

    float* buf = nullptr;
    cudaGetSymbolAddress((void**)&buf, g_buf);

    float* x       = buf + O_X;
    float* xpr     = buf + O_XPR;
    float* xpc     = buf + O_XPC;
    float* qrow    = buf + O_QROW;
    float* qcol    = buf + O_QCOL;
    float* v       = buf + O_V;
    float* attn    = buf + O_ATTN;
    float* attnout = buf + O_ATTNOUT;
    float* x1      = buf + O_X1;
    float* y       = buf + O_Y;
    float* pooled_r = buf + O_PR;
    float* pooled_c = buf + O_PC;
    float* krow    = buf + O_KROW;
    float* kcol    = buf + O_KCOL;
    float* awrow   = buf + O_AWROW;
    float* awcol   = buf + O_AWCOL;
    float* ffn     = buf + O_FFN;

    const int MQ = BZV * NQ;   // 6272

    prep_kernel<<<MQ, 256>>>(src, pr, pc, x, xpr, xpc);
    pool_kernel<<<dim3(BZV * LL * CC / 256, 2), 256>>>(x, pr, pc, pooled_r, pooled_c);

    // projections
    gemm_kernel<<<dim3(CC / 64, (MQ + 127) / 128), 256>>>(xpr, w_q_row, b_q_row, qrow, MQ, CC, CC, SCALE, 0);
    gemm_kernel<<<dim3(CC / 64, (MQ + 127) / 128), 256>>>(xpc, w_q_col, b_q_col, qcol, MQ, CC, CC, SCALE, 0);
    gemm_kernel<<<dim3(CC / 64, (MQ + 127) / 128), 256>>>(x,   w_v,     b_v,     v,    MQ, CC, CC, 1.0f, 0);
    gemm_kernel<<<dim3(CC / 64, 1), 256>>>(pooled_r, w_k_row, b_k_row, krow, BZV * LL, CC, CC, 1.0f, 0);
    gemm_kernel<<<dim3(CC / 64, 1), 256>>>(pooled_c, w_k_col, b_k_col, kcol, BZV * LL, CC, CC, 1.0f, 0);

    // attention weights (row: keys = columns w, mask stride 1; col: keys = rows h, mask stride LL)
    scores_kernel<<<dim3((NQ + 127) / 128, NH, BZV), 128>>>(qrow, krow, pm, 1,  awrow);
    scores_kernel<<<dim3((NQ + 127) / 128, NH, BZV), 128>>>(qcol, kcol, pm, LL, awcol);

    // RCDA recombination
    combine_kernel<<<dim3(NQ / 64, NH, BZV), 64>>>(awrow, awcol, v, attn);

    // output projection + LN1
    gemm_kernel<<<dim3(CC / 64, (MQ + 127) / 128), 256>>>(attn, w_out, b_out, attnout, MQ, CC, CC, 1.0f, 0);
    add_ln_kernel<<<MQ, 256>>>(x, attnout, n1g, n1b, x1, 0);

    // FFN + LN2 (+ transpose to (b,c,h,w))
    gemm_kernel<<<dim3(DFFN / 64, (MQ + 127) / 128), 256>>>(x1, l1w, l1b, ffn, MQ, DFFN, CC, 1.0f, 1);
    gemm_kernel<<<dim3(CC / 64, (MQ + 127) / 128), 256>>>(ffn, l2w, l2b, y, MQ, CC, DFFN, 1.0f, 0);
    add_ln_kernel<<<MQ, 256>>>(x1, y, n2g, n2b, out, 1);
}

// round 3
// speedup vs baseline: 1.6858x; 1.6858x over previous
#include <cuda_runtime.h>
#include <cuda_bf16.h>
#include <cstdint>
#include <cstddef>

// Problem constants
#define NQ    3136
#define CC    256
#define BZV   2
#define NH    8
#define HD    32
#define LL    56
#define DFFN  1024
#define SCALE 0.17677669529663687f   // 32^-0.5
#define NEGF  (-3.402823466e38f)

// ---------------- scratch ----------------------------------------------------
#define SZ_BQC   (BZV*NQ*CC)
#define SZ_POOL  (BZV*LL*CC)
#define SZ_AW    (BZV*NH*NQ*LL)
#define SZ_FFN   (BZV*NQ*DFFN)

#define O_X       ((size_t)0)
#define O_XPR     (O_X      + SZ_BQC)
#define O_XPC     (O_XPR    + SZ_BQC)
#define O_QROW    (O_XPC    + SZ_BQC)
#define O_QCOL    (O_QROW   + SZ_BQC)
#define O_V       (O_QCOL   + SZ_BQC)
#define O_ATTN    (O_V      + SZ_BQC)
#define O_ATTNOUT (O_ATTN   + SZ_BQC)
#define O_X1      (O_ATTNOUT+ SZ_BQC)
#define O_Y       (O_X1     + SZ_BQC)
#define O_PR      (O_Y      + SZ_BQC)
#define O_PC      (O_PR     + SZ_POOL)
#define O_KROW    (O_PC     + SZ_POOL)
#define O_KCOL    (O_KROW   + SZ_POOL)
#define O_AWROW   (O_KCOL   + SZ_POOL)
#define O_AWCOL   (O_AWROW  + SZ_AW)
#define O_FFN     (O_AWCOL  + SZ_AW)
#define SZ_TOTAL  (O_FFN    + SZ_FFN)

__device__ float g_buf[SZ_TOTAL];

// ---------------- small helpers ----------------------------------------------
__device__ __forceinline__ uint32_t f2tf32(float x) {
    uint32_t r;
    asm("cvt.rna.tf32.f32 %0, %1;" : "=r"(r) : "f"(x));
    return r;
}

__device__ __forceinline__ void mma_bf16(float (&c)[4], const uint32_t (&a)[4],
                                         const uint32_t (&b)[2]) {
    asm volatile(
        "mma.sync.aligned.m16n8k16.row.col.f32.bf16.bf16.f32 "
        "{%0,%1,%2,%3},{%4,%5,%6,%7},{%8,%9},{%0,%1,%2,%3};"
        : "+f"(c[0]), "+f"(c[1]), "+f"(c[2]), "+f"(c[3])
        : "r"(a[0]), "r"(a[1]), "r"(a[2]), "r"(a[3]), "r"(b[0]), "r"(b[1]));
}

__device__ __forceinline__ void mma_tf32(float (&c)[4], const uint32_t (&a)[4],
                                         const uint32_t (&b)[2]) {
    asm volatile(
        "mma.sync.aligned.m16n8k8.row.col.f32.tf32.tf32.f32 "
        "{%0,%1,%2,%3},{%4,%5,%6,%7},{%8,%9},{%0,%1,%2,%3};"
        : "+f"(c[0]), "+f"(c[1]), "+f"(c[2]), "+f"(c[3])
        : "r"(a[0]), "r"(a[1]), "r"(a[2]), "r"(a[3]), "r"(b[0]), "r"(b[1]));
}

// ---------------- prep -------------------------------------------------------
__global__ __launch_bounds__(256) void prep_kernel(
    const float* __restrict__ src, const float* __restrict__ pr,
    const float* __restrict__ pc, float* __restrict__ x,
    float* __restrict__ xpr, float* __restrict__ xpc)
{
    int idx = blockIdx.x * 256 + threadIdx.x;
    int c = idx & 255;
    int t = idx >> 8;
    int q = t % NQ;
    int b = t / NQ;
    int i = q / LL, j = q % LL;
    float val = src[((size_t)(b * CC + c)) * NQ + q];
    x[idx] = val;
    xpr[idx] = val + pr[(b * LL + j) * CC + c];
    xpc[idx] = val + pc[(b * LL + i) * CC + c];
}

// ---------------- pooling ----------------------------------------------------
__global__ __launch_bounds__(256) void pool_kernel(
    const float* __restrict__ x, const float* __restrict__ pr,
    const float* __restrict__ pc, float* __restrict__ pooled_r,
    float* __restrict__ pooled_c)
{
    int idx = blockIdx.x * 256 + threadIdx.x;
    int c = idx & 255;
    int t = idx >> 8;
    int rc = t % LL;
    int b = t / LL;
    if (blockIdx.y == 0) {
        float s = 0.f;
        #pragma unroll 8
        for (int i = 0; i < LL; i++)
            s += x[((size_t)(b * NQ) + i * LL + rc) * CC + c];
        pooled_r[idx] = s * (1.0f / LL) + pr[idx];
    } else {
        float s = 0.f;
        #pragma unroll 8
        for (int j = 0; j < LL; j++)
            s += x[((size_t)(b * NQ) + rc * LL + j) * CC + c];
        pooled_c[idx] = s * (1.0f / LL) + pc[idx];
    }
}

// ---------------- bf16 split-precision tensor-core GEMM -----------------------
// C[M,N] = alpha*(A[M,K] @ B[N,K]^T + bias), optional relu.
// Block tile 128x64, K-step 32. 8 warps: 4 (m) x 2 (n), warp tile 32x32.
__global__ __launch_bounds__(256) void gemm_tc(
    const float* __restrict__ A, const float* __restrict__ B,
    const float* __restrict__ bias, float* __restrict__ C,
    int M, int N, int K, float alpha, int relu)
{
    __shared__ __nv_bfloat16 Ah[128 * 40], Al[128 * 40];
    __shared__ __nv_bfloat16 Bh[64 * 40],  Bl[64 * 40];

    int bm = blockIdx.y * 128, bn = blockIdx.x * 64;
    int tid = threadIdx.x;
    int warp = tid >> 5, lane = tid & 31;
    int wm = warp & 3, wn = warp >> 2;
    int g = lane >> 2, tq = lane & 3;

    float acc[2][4][4];
    #pragma unroll
    for (int mt = 0; mt < 2; mt++)
        #pragma unroll
        for (int nt = 0; nt < 4; nt++)
            #pragma unroll
            for (int i = 0; i < 4; i++) acc[mt][nt][i] = 0.f;

    int ar = tid >> 1, ac = (tid & 1) * 16;   // A loads: 128 rows x 32 cols
    int br = tid >> 2, bc = (tid & 3) * 8;    // B loads: 64 rows x 32 cols

    for (int k0 = 0; k0 < K; k0 += 32) {
        #pragma unroll
        for (int j = 0; j < 4; j++) {
            float4 va = make_float4(0.f, 0.f, 0.f, 0.f);
            if (bm + ar < M)
                va = *(const float4*)(A + (size_t)(bm + ar) * K + k0 + ac + j * 4);
            float vv[4] = {va.x, va.y, va.z, va.w};
            #pragma unroll
            for (int e = 0; e < 4; e++) {
                __nv_bfloat16 h = __float2bfloat16(vv[e]);
                __nv_bfloat16 l = __float2bfloat16(vv[e] - __bfloat162float(h));
                Ah[ar * 40 + ac + j * 4 + e] = h;
                Al[ar * 40 + ac + j * 4 + e] = l;
            }
        }
        #pragma unroll
        for (int j = 0; j < 2; j++) {
            float4 vb = *(const float4*)(B + (size_t)(bn + br) * K + k0 + bc + j * 4);
            float vv[4] = {vb.x, vb.y, vb.z, vb.w};
            #pragma unroll
            for (int e = 0; e < 4; e++) {
                __nv_bfloat16 h = __float2bfloat16(vv[e]);
                __nv_bfloat16 l = __float2bfloat16(vv[e] - __bfloat162float(h));
                Bh[br * 40 + bc + j * 4 + e] = h;
                Bl[br * 40 + bc + j * 4 + e] = l;
            }
        }
        __syncthreads();

        #pragma unroll
        for (int ks = 0; ks < 2; ks++) {
            int kk = ks * 16;
            uint32_t ah[2][4], al_[2][4], bh[4][2], bl_[4][2];
            #pragma unroll
            for (int mt = 0; mt < 2; mt++) {
                int r = wm * 32 + mt * 16 + g;
                ah[mt][0] = *(const uint32_t*)&Ah[r * 40 + kk + tq * 2];
                ah[mt][1] = *(const uint32_t*)&Ah[(r + 8) * 40 + kk + tq * 2];
                ah[mt][2] = *(const uint32_t*)&Ah[r * 40 + kk + tq * 2 + 8];
                ah[mt][3] = *(const uint32_t*)&Ah[(r + 8) * 40 + kk + tq * 2 + 8];
                al_[mt][0] = *(const uint32_t*)&Al[r * 40 + kk + tq * 2];
                al_[mt][1] = *(const uint32_t*)&Al[(r + 8) * 40 + kk + tq * 2];
                al_[mt][2] = *(const uint32_t*)&Al[r * 40 + kk + tq * 2 + 8];
                al_[mt][3] = *(const uint32_t*)&Al[(r + 8) * 40 + kk + tq * 2 + 8];
            }
            #pragma unroll
            for (int nt = 0; nt < 4; nt++) {
                int rn = wn * 32 + nt * 8 + g;
                bh[nt][0] = *(const uint32_t*)&Bh[rn * 40 + kk + tq * 2];
                bh[nt][1] = *(const uint32_t*)&Bh[rn * 40 + kk + tq * 2 + 8];
                bl_[nt][0] = *(const uint32_t*)&Bl[rn * 40 + kk + tq * 2];
                bl_[nt][1] = *(const uint32_t*)&Bl[rn * 40 + kk + tq * 2 + 8];
            }
            #pragma unroll
            for (int mt = 0; mt < 2; mt++)
                #pragma unroll
                for (int nt = 0; nt < 4; nt++) {
                    mma_bf16(acc[mt][nt], ah[mt], bh[nt]);
                    mma_bf16(acc[mt][nt], ah[mt], bl_[nt]);
                    mma_bf16(acc[mt][nt], al_[mt], bh[nt]);
                }
        }
        __syncthreads();
    }

    #pragma unroll
    for (int mt = 0; mt < 2; mt++)
        #pragma unroll
        for (int nt = 0; nt < 4; nt++) {
            int r = bm + wm * 32 + mt * 16 + g;
            int cn = bn + wn * 32 + nt * 8 + tq * 2;
            float b0 = bias[cn], b1 = bias[cn + 1];
            float o0 = (acc[mt][nt][0] + b0) * alpha;
            float o1 = (acc[mt][nt][1] + b1) * alpha;
            float o2 = (acc[mt][nt][2] + b0) * alpha;
            float o3 = (acc[mt][nt][3] + b1) * alpha;
            if (relu) {
                o0 = fmaxf(o0, 0.f); o1 = fmaxf(o1, 0.f);
                o2 = fmaxf(o2, 0.f); o3 = fmaxf(o3, 0.f);
            }
            if (r < M)     *(float2*)(C + (size_t)r * N + cn)       = make_float2(o0, o1);
            if (r + 8 < M) *(float2*)(C + (size_t)(r + 8) * N + cn) = make_float2(o2, o3);
        }
}

// ---------------- scores + softmax --------------------------------------------
__global__ __launch_bounds__(128) void scores_kernel(
    const float* __restrict__ q, const float* __restrict__ kk,
    const unsigned char* __restrict__ mask, int mstride,
    float* __restrict__ aw)
{
    __shared__ float4 Ks[LL * 8];
    __shared__ float Sc[128][57];
    __shared__ unsigned char Ms[LL];
    int b = blockIdx.z, n = blockIdx.y;
    int q0 = blockIdx.x * 128;
    int tid = threadIdx.x;

    for (int i = tid; i < LL * 8; i += 128) {
        int w = i >> 3, d4 = i & 7;
        Ks[i] = *(const float4*)(kk + ((size_t)(b * LL + w)) * CC + n * HD + d4 * 4);
    }
    if (tid < LL) Ms[tid] = mask[b * NQ + tid * mstride];
    __syncthreads();

    int qi = q0 + tid;
    if (qi >= NQ) return;

    float4 qv[8];
    const float4* qp = (const float4*)(q + ((size_t)b * NQ + qi) * CC + n * HD);
    #pragma unroll
    for (int i = 0; i < 8; i++) qv[i] = qp[i];

    float mx = -3.0e38f;
    #pragma unroll 4
    for (int w = 0; w < LL; w++) {
        float s = 0.f;
        #pragma unroll
        for (int i = 0; i < 8; i++) {
            float4 k4 = Ks[w * 8 + i];
            s += qv[i].x * k4.x + qv[i].y * k4.y + qv[i].z * k4.z + qv[i].w * k4.w;
        }
        if (Ms[w]) s = NEGF;
        Sc[tid][w] = s;
        mx = fmaxf(mx, s);
    }
    float sum = 0.f;
    #pragma unroll 4
    for (int w = 0; w < LL; w++) {
        float e = __expf(Sc[tid][w] - mx);
        Sc[tid][w] = e;
        sum += e;
    }
    float inv = 1.0f / sum;
    float* dst = aw + (((size_t)(b * NH + n)) * NQ + qi) * LL;
    #pragma unroll 4
    for (int w = 0; w < LL; w++) dst[w] = Sc[tid][w] * inv;
}

// ---------------- RCDA recombination on tensor cores (tf32) -------------------
// Per block: (b, n, 64 q's). Loop h: P = AWR[64x56(->64)] @ V_h[56x32] (tf32 mma),
// then out_acc += awc[q,h] * P.
__global__ __launch_bounds__(64) void combine_tc(
    const float* __restrict__ awr, const float* __restrict__ awc,
    const float* __restrict__ v, float* __restrict__ out_attn)
{
    __shared__ uint32_t ARs[64 * 68];   // tf32, pitch 68 (conflict-free)
    __shared__ float    ACs[64 * 57];
    __shared__ uint32_t Vs[64 * 40];    // tf32, pitch 40 (conflict-free)

    int b = blockIdx.z, n = blockIdx.y;
    int q0 = blockIdx.x * 64;           // NQ = 64 * 49, exact
    int tid = threadIdx.x;
    int warp = tid >> 5, lane = tid & 31;
    int g = lane >> 2, tq = lane & 3;

    const float* arg = awr + (((size_t)(b * NH + n)) * NQ + q0) * LL;
    const float* acg = awc + (((size_t)(b * NH + n)) * NQ + q0) * LL;

    // load AWR (tf32, zero-padded K 56->64) + AWC
    for (int i = tid; i < 64 * 64; i += 64) {
        int qi = i >> 6, k = i & 63;
        float va = (k < LL) ? arg[qi * LL + k] : 0.f;
        ARs[qi * 68 + k] = f2tf32(va);
        if (k < LL) ACs[qi * 57 + k] = acg[qi * LL + k];
    }
    // zero-pad V rows 56..63 once
    for (int i = tid; i < 8 * 40; i += 64) Vs[56 * 40 + i] = 0;
    __syncthreads();

    // hoist A fragments (h-invariant): 8 k-steps x 2 m-tiles x 4 regs
    uint32_t af[8][2][4];
    #pragma unroll
    for (int ks = 0; ks < 8; ks++)
        #pragma unroll
        for (int mt = 0; mt < 2; mt++) {
            int r = warp * 32 + mt * 16 + g;
            af[ks][mt][0] = ARs[r * 68 + ks * 8 + tq];
            af[ks][mt][1] = ARs[(r + 8) * 68 + ks * 8 + tq];
            af[ks][mt][2] = ARs[r * 68 + ks * 8 + tq + 4];
            af[ks][mt][3] = ARs[(r + 8) * 68 + ks * 8 + tq + 4];
        }

    float oacc[2][4][4];
    #pragma unroll
    for (int mt = 0; mt < 2; mt++)
        #pragma unroll
        for (int nt = 0; nt < 4; nt++)
            #pragma unroll
            for (int i = 0; i < 4; i++) oacc[mt][nt][i] = 0.f;

    // prefetch V slab for h=0
    float4 vbuf[7];
    {
        const float* vg = v + ((size_t)(b * NQ)) * CC + n * HD;   // h = 0
        #pragma unroll
        for (int j = 0; j < 7; j++) {
            int i4 = tid + j * 64;
            int w = i4 >> 3, d4 = i4 & 7;
            vbuf[j] = *(const float4*)(vg + (size_t)w * CC + d4 * 4);
        }
    }
    // store to Vs
    #pragma unroll
    for (int j = 0; j < 7; j++) {
        int i4 = tid + j * 64;
        int w = i4 >> 3, d4 = i4 & 7;
        Vs[w * 40 + d4 * 4 + 0] = f2tf32(vbuf[j].x);
        Vs[w * 40 + d4 * 4 + 1] = f2tf32(vbuf[j].y);
        Vs[w * 40 + d4 * 4 + 2] = f2tf32(vbuf[j].z);
        Vs[w * 40 + d4 * 4 + 3] = f2tf32(vbuf[j].w);
    }
    __syncthreads();

    for (int h = 0; h < LL; h++) {
        // prefetch next slab into registers (overlap with mma)
        if (h + 1 < LL) {
            const float* vg = v + ((size_t)(b * NQ) + (h + 1) * LL) * CC + n * HD;
            #pragma unroll
            for (int j = 0; j < 7; j++) {
                int i4 = tid + j * 64;
                int w = i4 >> 3, d4 = i4 & 7;
                vbuf[j] = *(const float4*)(vg + (size_t)w * CC + d4 * 4);
            }
        }

        float p[2][4][4];
        #pragma unroll
        for (int mt = 0; mt < 2; mt++)
            #pragma unroll
            for (int nt = 0; nt < 4; nt++)
                #pragma unroll
                for (int i = 0; i < 4; i++) p[mt][nt][i] = 0.f;

        #pragma unroll
        for (int ks = 0; ks < 8; ks++) {
            uint32_t bf[4][2];
            #pragma unroll
            for (int nt = 0; nt < 4; nt++) {
                bf[nt][0] = Vs[(ks * 8 + tq) * 40 + nt * 8 + g];
                bf[nt][1] = Vs[(ks * 8 + tq + 4) * 40 + nt * 8 + g];
            }
            #pragma unroll
            for (int mt = 0; mt < 2; mt++)
                #pragma unroll
                for (int nt = 0; nt < 4; nt++)
                    mma_tf32(p[mt][nt], af[ks][mt], bf[nt]);
        }

        #pragma unroll
        for (int mt = 0; mt < 2; mt++) {
            int r = warp * 32 + mt * 16 + g;
            float c0 = ACs[r * 57 + h];
            float c1 = ACs[(r + 8) * 57 + h];
            #pragma unroll
            for (int nt = 0; nt < 4; nt++) {
                oacc[mt][nt][0] += c0 * p[mt][nt][0];
                oacc[mt][nt][1] += c0 * p[mt][nt][1];
                oacc[mt][nt][2] += c1 * p[mt][nt][2];
                oacc[mt][nt][3] += c1 * p[mt][nt][3];
            }
        }

        __syncthreads();
        if (h + 1 < LL) {
            #pragma unroll
            for (int j = 0; j < 7; j++) {
                int i4 = tid + j * 64;
                int w = i4 >> 3, d4 = i4 & 7;
                Vs[w * 40 + d4 * 4 + 0] = f2tf32(vbuf[j].x);
                Vs[w * 40 + d4 * 4 + 1] = f2tf32(vbuf[j].y);
                Vs[w * 40 + d4 * 4 + 2] = f2tf32(vbuf[j].z);
                Vs[w * 40 + d4 * 4 + 3] = f2tf32(vbuf[j].w);
            }
            __syncthreads();
        }
    }

    #pragma unroll
    for (int mt = 0; mt < 2; mt++)
        #pragma unroll
        for (int nt = 0; nt < 4; nt++) {
            int r = q0 + warp * 32 + mt * 16 + g;
            int col = n * HD + nt * 8 + tq * 2;
            *(float2*)(out_attn + ((size_t)(b * NQ) + r) * CC + col)
                = make_float2(oacc[mt][nt][0], oacc[mt][nt][1]);
            *(float2*)(out_attn + ((size_t)(b * NQ) + r + 8) * CC + col)
                = make_float2(oacc[mt][nt][2], oacc[mt][nt][3]);
        }
}

// ---------------- residual + layernorm ----------------------------------------
__global__ __launch_bounds__(256) void add_ln_kernel(
    const float* __restrict__ A, const float* __restrict__ B,
    const float* __restrict__ g, const float* __restrict__ be,
    float* __restrict__ out, int transpose_out)
{
    int row = blockIdx.x;
    int c = threadIdx.x;
    size_t idx = (size_t)row * CC + c;
    float v = A[idx] + B[idx];
    float s = v, s2 = v * v;
    #pragma unroll
    for (int o = 16; o; o >>= 1) {
        s  += __shfl_xor_sync(0xffffffffu, s,  o);
        s2 += __shfl_xor_sync(0xffffffffu, s2, o);
    }
    __shared__ float rs[8], rs2[8];
    __shared__ float mean_s, rstd_s;
    int w = c >> 5;
    if ((c & 31) == 0) { rs[w] = s; rs2[w] = s2; }
    __syncthreads();
    if (c == 0) {
        float S = 0.f, S2 = 0.f;
        #pragma unroll
        for (int i = 0; i < 8; i++) { S += rs[i]; S2 += rs2[i]; }
        float m = S * (1.0f / CC);
        float var = S2 * (1.0f / CC) - m * m;
        mean_s = m;
        rstd_s = rsqrtf(var + 1e-5f);
    }
    __syncthreads();
    float res = (v - mean_s) * rstd_s * g[c] + be[c];
    if (transpose_out) {
        int q = row % NQ, b = row / NQ;
        out[((size_t)(b * CC + c)) * NQ + q] = res;
    } else {
        out[idx] = res;
    }
}

// ---------------- launch -------------------------------------------------------
extern "C" void kernel_launch(void* const* d_in, const int* in_sizes, int n_in,
                              void* d_out, int out_size)
{
    const float* src   = (const float*)d_in[0];
    const unsigned char* pm = (const unsigned char*)d_in[1];
    const float* pr    = (const float*)d_in[2];
    const float* pc    = (const float*)d_in[3];
    const float* w_q_row = (const float*)d_in[4];
    const float* b_q_row = (const float*)d_in[5];
    const float* w_q_col = (const float*)d_in[6];
    const float* b_q_col = (const float*)d_in[7];
    const float* w_k_row = (const float*)d_in[8];
    const float* b_k_row = (const float*)d_in[9];
    const float* w_k_col = (const float*)d_in[10];
    const float* b_k_col = (const float*)d_in[11];
    const float* w_v   = (const float*)d_in[12];
    const float* b_v   = (const float*)d_in[13];
    const float* w_out = (const float*)d_in[14];
    const float* b_out = (const float*)d_in[15];
    const float* n1g   = (const float*)d_in[16];
    const float* n1b   = (const float*)d_in[17];
    const float* l1w   = (const float*)d_in[18];
    const float* l1b   = (const float*)d_in[19];
    const float* l2w   = (const float*)d_in[20];
    const float* l2b   = (const float*)d_in[21];
    const float* n2g   = (const float*)d_in[22];
    const float* n2b   = (const float*)d_in[23];
    float* out = (float*)d_out;

    float* buf = nullptr;
    cudaGetSymbolAddress((void**)&buf, g_buf);

    float* x       = buf + O_X;
    float* xpr     = buf + O_XPR;
    float* xpc     = buf + O_XPC;
    float* qrow    = buf + O_QROW;
    float* qcol    = buf + O_QCOL;
    float* v       = buf + O_V;
    float* attn    = buf + O_ATTN;
    float* attnout = buf + O_ATTNOUT;
    float* x1      = buf + O_X1;
    float* y       = buf + O_Y;
    float* pooled_r = buf + O_PR;
    float* pooled_c = buf + O_PC;
    float* krow    = buf + O_KROW;
    float* kcol    = buf + O_KCOL;
    float* awrow   = buf + O_AWROW;
    float* awcol   = buf + O_AWCOL;
    float* ffn     = buf + O_FFN;

    const int MQ = BZV * NQ;   // 6272

    prep_kernel<<<MQ, 256>>>(src, pr, pc, x, xpr, xpc);
    pool_kernel<<<dim3(BZV * LL * CC / 256, 2), 256>>>(x, pr, pc, pooled_r, pooled_c);

    // projections (bf16-split tensor cores)
    gemm_tc<<<dim3(CC / 64, MQ / 128), 256>>>(xpr, w_q_row, b_q_row, qrow, MQ, CC, CC, SCALE, 0);
    gemm_tc<<<dim3(CC / 64, MQ / 128), 256>>>(xpc, w_q_col, b_q_col, qcol, MQ, CC, CC, SCALE, 0);
    gemm_tc<<<dim3(CC / 64, MQ / 128), 256>>>(x,   w_v,     b_v,     v,    MQ, CC, CC, 1.0f, 0);
    gemm_tc<<<dim3(CC / 64, 1), 256>>>(pooled_r, w_k_row, b_k_row, krow, BZV * LL, CC, CC, 1.0f, 0);
    gemm_tc<<<dim3(CC / 64, 1), 256>>>(pooled_c, w_k_col, b_k_col, kcol, BZV * LL, CC, CC, 1.0f, 0);

    // attention weights
    scores_kernel<<<dim3((NQ + 127) / 128, NH, BZV), 128>>>(qrow, krow, pm, 1,  awrow);
    scores_kernel<<<dim3((NQ + 127) / 128, NH, BZV), 128>>>(qcol, kcol, pm, LL, awcol);

    // RCDA recombination (tf32 tensor cores)
    combine_tc<<<dim3(NQ / 64, NH, BZV), 64>>>(awrow, awcol, v, attn);

    // output projection + LN1
    gemm_tc<<<dim3(CC / 64, MQ / 128), 256>>>(attn, w_out, b_out, attnout, MQ, CC, CC, 1.0f, 0);
    add_ln_kernel<<<MQ, 256>>>(x, attnout, n1g, n1b, x1, 0);

    // FFN + LN2 (+ transpose back to (b,c,h,w))
    gemm_tc<<<dim3(DFFN / 64, MQ / 128), 256>>>(x1, l1w, l1b, ffn, MQ, DFFN, CC, 1.0f, 1);
    gemm_tc<<<dim3(CC / 64, MQ / 128), 256>>>(ffn, l2w, l2b, y, MQ, CC, DFFN, 1.0f, 0);
    add_ln_kernel<<<MQ, 256>>>(x1, y, n2g, n2b, out, 1);
}

// round 4
// speedup vs baseline: 2.4480x; 1.4521x over previous
#include <cuda_runtime.h>
#include <cuda_bf16.h>
#include <cstdint>
#include <cstddef>

#define NQ    3136
#define CC    256
#define BZV   2
#define NH    8
#define HD    32
#define LL    56
#define DFFN  1024
#define MQ    (BZV*NQ)
#define SCALE 0.17677669529663687f
#define NEGF  (-3.402823466e38f)

// ------------------------- scratch buffers -----------------------------------
#define SZ_BQC (MQ*CC)            // 1,605,632
#define SZ_KP  (BZV*LL*CC)        // 28,672
#define SZ_AW  (BZV*NH*NQ*LL)     // 2,809,856
#define SZ_FFN (MQ*DFFN)          // 6,422,528

// f32 scratch
#define F_X       ((size_t)0)
#define F_QROW    (F_X    + SZ_BQC)
#define F_QCOL    (F_QROW + SZ_BQC)
#define F_V       (F_QCOL + SZ_BQC)
#define F_ATTNOUT (F_V    + SZ_BQC)
#define F_X1      (F_ATTNOUT + SZ_BQC)
#define F_Y       (F_X1   + SZ_BQC)
#define F_KROW    (F_Y    + SZ_BQC)
#define F_KCOL    (F_KROW + SZ_KP)
#define F_AWROW   (F_KCOL + SZ_KP)
#define F_AWCOL   (F_AWROW + SZ_AW)
#define F_TOTAL   (F_AWCOL + SZ_AW)
__device__ float g_f[F_TOTAL];

// bf16 scratch
#define H_XH    ((size_t)0)
#define H_XL    (H_XH  + SZ_BQC)
#define H_XPRH  (H_XL  + SZ_BQC)
#define H_XPRL  (H_XPRH+ SZ_BQC)
#define H_XPCH  (H_XPRL+ SZ_BQC)
#define H_XPCL  (H_XPCH+ SZ_BQC)
#define H_PRH   (H_XPCL+ SZ_BQC)
#define H_PRL   (H_PRH + SZ_KP)
#define H_PCH   (H_PRL + SZ_KP)
#define H_PCL   (H_PCH + SZ_KP)
#define H_ATTNH (H_PCL + SZ_KP)
#define H_ATTNL (H_ATTNH + SZ_BQC)
#define H_X1H   (H_ATTNL + SZ_BQC)
#define H_X1L   (H_X1H + SZ_BQC)
#define H_FFNH  (H_X1L + SZ_BQC)
#define H_FFNL  (H_FFNH + SZ_FFN)
#define H_WQRH  (H_FFNL + SZ_FFN)
#define H_WQRL  (H_WQRH + CC*CC)
#define H_WQCH  (H_WQRL + CC*CC)
#define H_WQCL  (H_WQCH + CC*CC)
#define H_WKRH  (H_WQCL + CC*CC)
#define H_WKRL  (H_WKRH + CC*CC)
#define H_WKCH  (H_WKRL + CC*CC)
#define H_WKCL  (H_WKCH + CC*CC)
#define H_WVH   (H_WKCL + CC*CC)
#define H_WVL   (H_WVH  + CC*CC)
#define H_WOH   (H_WVL  + CC*CC)
#define H_WOL   (H_WOH  + CC*CC)
#define H_L1H   (H_WOL  + CC*CC)
#define H_L1L   (H_L1H  + DFFN*CC)
#define H_L2H   (H_L1L  + DFFN*CC)
#define H_L2L   (H_L2H  + CC*DFFN)
#define H_TOTAL (H_L2L  + CC*DFFN)
__device__ __nv_bfloat16 g_h[H_TOTAL];

// ------------------------- helpers -------------------------------------------
__device__ __forceinline__ uint32_t f2tf32(float x) {
    uint32_t r; asm("cvt.rna.tf32.f32 %0, %1;" : "=r"(r) : "f"(x)); return r;
}
__device__ __forceinline__ void mma_bf16(float (&c)[4], const uint32_t (&a)[4],
                                         const uint32_t (&b)[2]) {
    asm volatile("mma.sync.aligned.m16n8k16.row.col.f32.bf16.bf16.f32 "
        "{%0,%1,%2,%3},{%4,%5,%6,%7},{%8,%9},{%0,%1,%2,%3};"
        : "+f"(c[0]), "+f"(c[1]), "+f"(c[2]), "+f"(c[3])
        : "r"(a[0]), "r"(a[1]), "r"(a[2]), "r"(a[3]), "r"(b[0]), "r"(b[1]));
}
__device__ __forceinline__ void mma_tf32(float (&c)[4], const uint32_t (&a)[4],
                                         const uint32_t (&b)[2]) {
    asm volatile("mma.sync.aligned.m16n8k8.row.col.f32.tf32.tf32.f32 "
        "{%0,%1,%2,%3},{%4,%5,%6,%7},{%8,%9},{%0,%1,%2,%3};"
        : "+f"(c[0]), "+f"(c[1]), "+f"(c[2]), "+f"(c[3])
        : "r"(a[0]), "r"(a[1]), "r"(a[2]), "r"(a[3]), "r"(b[0]), "r"(b[1]));
}
__device__ __forceinline__ void split2(float a, float b, uint32_t& hi, uint32_t& lo) {
    __nv_bfloat16 ha = __float2bfloat16(a), hb = __float2bfloat16(b);
    __nv_bfloat16 la = __float2bfloat16(a - __bfloat162float(ha));
    __nv_bfloat16 lb = __float2bfloat16(b - __bfloat162float(hb));
    hi = (uint32_t)__bfloat16_as_ushort(ha) | ((uint32_t)__bfloat16_as_ushort(hb) << 16);
    lo = (uint32_t)__bfloat16_as_ushort(la) | ((uint32_t)__bfloat16_as_ushort(lb) << 16);
}

// ------------------------- weight conversion ----------------------------------
struct WJobs { const float* s[8]; __nv_bfloat16* h[8]; __nv_bfloat16* l[8]; int n[8]; };
__global__ __launch_bounds__(256) void convert_w(WJobs w) {
    int j = blockIdx.y;
    int i = (blockIdx.x * 256 + threadIdx.x) * 4;
    if (i >= w.n[j]) return;
    float4 v = *(const float4*)(w.s[j] + i);
    uint32_t h0, l0, h1, l1;
    split2(v.x, v.y, h0, l0);
    split2(v.z, v.w, h1, l1);
    uint32_t* ph = (uint32_t*)(w.h[j] + i);
    uint32_t* pl = (uint32_t*)(w.l[j] + i);
    ph[0] = h0; ph[1] = h1; pl[0] = l0; pl[1] = l1;
}

// ------------------------- prep: tiled transpose + posemb + splits ------------
__global__ __launch_bounds__(256) void prep_kernel(
    const float* __restrict__ src, const float* __restrict__ pr,
    const float* __restrict__ pc, float* __restrict__ x,
    __nv_bfloat16* __restrict__ xh, __nv_bfloat16* __restrict__ xl,
    __nv_bfloat16* __restrict__ xprh, __nv_bfloat16* __restrict__ xprl,
    __nv_bfloat16* __restrict__ xpch, __nv_bfloat16* __restrict__ xpcl)
{
    __shared__ float tile[64 * 65];
    int b = blockIdx.z;
    int q0 = blockIdx.x * 64, c0 = blockIdx.y * 64;
    int tid = threadIdx.x;

    // read phase: 64 c-rows x 64 q (coalesced along q)
    int cl_ = tid >> 2, qs = (tid & 3) * 16;
    const float* sp = src + ((size_t)(b * CC + c0 + cl_)) * NQ + q0 + qs;
    #pragma unroll
    for (int j = 0; j < 4; j++) {
        float4 vv = *(const float4*)(sp + j * 4);
        tile[cl_ * 65 + qs + j * 4 + 0] = vv.x;
        tile[cl_ * 65 + qs + j * 4 + 1] = vv.y;
        tile[cl_ * 65 + qs + j * 4 + 2] = vv.z;
        tile[cl_ * 65 + qs + j * 4 + 3] = vv.w;
    }
    __syncthreads();

    // write phase: 64 q-rows x 64 c (coalesced along c)
    int ql = tid >> 2, cs = (tid & 3) * 16;
    int q = q0 + ql;
    int irow = q / LL, jcol = q % LL;
    const float* prp = pr + (size_t)(b * LL + jcol) * CC + c0 + cs;
    const float* pcp = pc + (size_t)(b * LL + irow) * CC + c0 + cs;
    size_t ob = ((size_t)(b * NQ + q)) * CC + c0 + cs;
    #pragma unroll
    for (int j = 0; j < 4; j++) {
        float v0 = tile[(cs + j * 4 + 0) * 65 + ql];
        float v1 = tile[(cs + j * 4 + 1) * 65 + ql];
        float v2 = tile[(cs + j * 4 + 2) * 65 + ql];
        float v3 = tile[(cs + j * 4 + 3) * 65 + ql];
        float4 p4 = *(const float4*)(prp + j * 4);
        float4 c4 = *(const float4*)(pcp + j * 4);
        *(float4*)(x + ob + j * 4) = make_float4(v0, v1, v2, v3);
        uint32_t h0, l0, h1, l1;
        split2(v0, v1, h0, l0); split2(v2, v3, h1, l1);
        ((uint32_t*)(xh + ob + j * 4))[0] = h0; ((uint32_t*)(xh + ob + j * 4))[1] = h1;
        ((uint32_t*)(xl + ob + j * 4))[0] = l0; ((uint32_t*)(xl + ob + j * 4))[1] = l1;
        split2(v0 + p4.x, v1 + p4.y, h0, l0); split2(v2 + p4.z, v3 + p4.w, h1, l1);
        ((uint32_t*)(xprh + ob + j * 4))[0] = h0; ((uint32_t*)(xprh + ob + j * 4))[1] = h1;
        ((uint32_t*)(xprl + ob + j * 4))[0] = l0; ((uint32_t*)(xprl + ob + j * 4))[1] = l1;
        split2(v0 + c4.x, v1 + c4.y, h0, l0); split2(v2 + c4.z, v3 + c4.w, h1, l1);
        ((uint32_t*)(xpch + ob + j * 4))[0] = h0; ((uint32_t*)(xpch + ob + j * 4))[1] = h1;
        ((uint32_t*)(xpcl + ob + j * 4))[0] = l0; ((uint32_t*)(xpcl + ob + j * 4))[1] = l1;
    }
}

// ------------------------- pooling + splits -----------------------------------
__global__ __launch_bounds__(256) void pool_kernel(
    const float* __restrict__ x, const float* __restrict__ pr,
    const float* __restrict__ pc,
    __nv_bfloat16* __restrict__ prh, __nv_bfloat16* __restrict__ prl,
    __nv_bfloat16* __restrict__ pch, __nv_bfloat16* __restrict__ pcl)
{
    int idx = blockIdx.x * 256 + threadIdx.x;   // over BZV*LL*CC
    int c = idx & 255;
    int t = idx >> 8;
    int rc = t % LL;
    int b = t / LL;
    float sr = 0.f, sc = 0.f;
    #pragma unroll 8
    for (int i = 0; i < LL; i++) {
        sr += x[((size_t)(b * NQ) + i * LL + rc) * CC + c];
        sc += x[((size_t)(b * NQ) + rc * LL + i) * CC + c];
    }
    float vr = sr * (1.0f / LL) + pr[idx];
    float vc = sc * (1.0f / LL) + pc[idx];
    __nv_bfloat16 h = __float2bfloat16(vr);
    prh[idx] = h; prl[idx] = __float2bfloat16(vr - __bfloat162float(h));
    h = __float2bfloat16(vc);
    pch[idx] = h; pcl[idx] = __float2bfloat16(vc - __bfloat162float(h));
}

// ------------------------- batched bf16 split GEMM -----------------------------
// C = alpha*(A[M,K] @ B[N,K]^T + bias); 3 MMAs per tile (hh, hl, lh).
struct GemmJob {
    const __nv_bfloat16 *Ah, *Al, *Bh, *Bl;
    const float* bias;
    float* C;
    __nv_bfloat16 *Ch, *Cl;
    float alpha;
    int relu;
};
struct GemmArgs { GemmJob j[3]; };

__global__ __launch_bounds__(256) void gemm_bf16(GemmArgs args, int M, int N, int K)
{
    extern __shared__ uint32_t sm[];
    const GemmJob jb = args.j[blockIdx.z];
    const int STG = 7680;           // u32 per stage
    int bm = blockIdx.y * 128, bn = blockIdx.x * 64;
    int tid = threadIdx.x, warp = tid >> 5, lane = tid & 31;
    int wm = warp & 3, wn = warp >> 2, g = lane >> 2, tq = lane & 3;

    float acc[2][4][4];
    #pragma unroll
    for (int mt = 0; mt < 2; mt++)
        #pragma unroll
        for (int nt = 0; nt < 4; nt++)
            #pragma unroll
            for (int i = 0; i < 4; i++) acc[mt][nt][i] = 0.f;

    int ar = tid >> 1, ahf = tid & 1;     // A: 128 rows, 2 halves of 16 bf16
    int br = tid >> 2, bqt = tid & 3;     // B: 64 rows, 4 quarters of 8 bf16
    int KT = K >> 5;

    uint4 rAh[2], rAl[2], rBh, rBl;
    // --- load tile 0 into regs
    {
        int row = bm + ar;
        if (row < M) {
            const uint4* p = (const uint4*)(jb.Ah + (size_t)row * K + ahf * 16);
            rAh[0] = p[0]; rAh[1] = p[1];
            p = (const uint4*)(jb.Al + (size_t)row * K + ahf * 16);
            rAl[0] = p[0]; rAl[1] = p[1];
        } else {
            rAh[0] = rAh[1] = rAl[0] = rAl[1] = make_uint4(0, 0, 0, 0);
        }
        rBh = *(const uint4*)(jb.Bh + (size_t)(bn + br) * K + bqt * 8);
        rBl = *(const uint4*)(jb.Bl + (size_t)(bn + br) * K + bqt * 8);
    }
    // store stage 0
    {
        uint32_t* sA = sm;
        *(uint4*)(sA + ar * 20 + ahf * 8)     = rAh[0];
        *(uint4*)(sA + ar * 20 + ahf * 8 + 4) = rAh[1];
        *(uint4*)(sA + 2560 + ar * 20 + ahf * 8)     = rAl[0];
        *(uint4*)(sA + 2560 + ar * 20 + ahf * 8 + 4) = rAl[1];
        *(uint4*)(sA + 5120 + br * 20 + bqt * 4) = rBh;
        *(uint4*)(sA + 6400 + br * 20 + bqt * 4) = rBl;
    }
    __syncthreads();

    for (int kt = 0; kt < KT; kt++) {
        int s = kt & 1;
        if (kt + 1 < KT) {
            int k0 = (kt + 1) * 32;
            int row = bm + ar;
            if (row < M) {
                const uint4* p = (const uint4*)(jb.Ah + (size_t)row * K + k0 + ahf * 16);
                rAh[0] = p[0]; rAh[1] = p[1];
                p = (const uint4*)(jb.Al + (size_t)row * K + k0 + ahf * 16);
                rAl[0] = p[0]; rAl[1] = p[1];
            }
            rBh = *(const uint4*)(jb.Bh + (size_t)(bn + br) * K + k0 + bqt * 8);
            rBl = *(const uint4*)(jb.Bl + (size_t)(bn + br) * K + k0 + bqt * 8);
        }

        const uint32_t* sAh = sm + s * STG;
        const uint32_t* sAl = sAh + 2560;
        const uint32_t* sBh = sAh + 5120;
        const uint32_t* sBl = sAh + 6400;
        #pragma unroll
        for (int ks = 0; ks < 2; ks++) {
            int ko = ks * 8;
            uint32_t aH[2][4], aL[2][4], bH[4][2], bL[4][2];
            #pragma unroll
            for (int mt = 0; mt < 2; mt++) {
                int r = wm * 32 + mt * 16 + g;
                aH[mt][0] = sAh[r * 20 + ko + tq];
                aH[mt][1] = sAh[(r + 8) * 20 + ko + tq];
                aH[mt][2] = sAh[r * 20 + ko + tq + 4];
                aH[mt][3] = sAh[(r + 8) * 20 + ko + tq + 4];
                aL[mt][0] = sAl[r * 20 + ko + tq];
                aL[mt][1] = sAl[(r + 8) * 20 + ko + tq];
                aL[mt][2] = sAl[r * 20 + ko + tq + 4];
                aL[mt][3] = sAl[(r + 8) * 20 + ko + tq + 4];
            }
            #pragma unroll
            for (int nt = 0; nt < 4; nt++) {
                int rn = wn * 32 + nt * 8 + g;
                bH[nt][0] = sBh[rn * 20 + ko + tq];
                bH[nt][1] = sBh[rn * 20 + ko + tq + 4];
                bL[nt][0] = sBl[rn * 20 + ko + tq];
                bL[nt][1] = sBl[rn * 20 + ko + tq + 4];
            }
            #pragma unroll
            for (int mt = 0; mt < 2; mt++)
                #pragma unroll
                for (int nt = 0; nt < 4; nt++) {
                    mma_bf16(acc[mt][nt], aH[mt], bH[nt]);
                    mma_bf16(acc[mt][nt], aH[mt], bL[nt]);
                    mma_bf16(acc[mt][nt], aL[mt], bH[nt]);
                }
        }
        if (kt + 1 < KT) {
            uint32_t* dA = sm + (s ^ 1) * STG;
            *(uint4*)(dA + ar * 20 + ahf * 8)     = rAh[0];
            *(uint4*)(dA + ar * 20 + ahf * 8 + 4) = rAh[1];
            *(uint4*)(dA + 2560 + ar * 20 + ahf * 8)     = rAl[0];
            *(uint4*)(dA + 2560 + ar * 20 + ahf * 8 + 4) = rAl[1];
            *(uint4*)(dA + 5120 + br * 20 + bqt * 4) = rBh;
            *(uint4*)(dA + 6400 + br * 20 + bqt * 4) = rBl;
            __syncthreads();
        }
    }

    // epilogue
    #pragma unroll
    for (int mt = 0; mt < 2; mt++)
        #pragma unroll
        for (int nt = 0; nt < 4; nt++) {
            int r = bm + wm * 32 + mt * 16 + g;
            int cn = bn + wn * 32 + nt * 8 + tq * 2;
            float b0 = jb.bias[cn], b1 = jb.bias[cn + 1];
            float o0 = (acc[mt][nt][0] + b0) * jb.alpha;
            float o1 = (acc[mt][nt][1] + b1) * jb.alpha;
            float o2 = (acc[mt][nt][2] + b0) * jb.alpha;
            float o3 = (acc[mt][nt][3] + b1) * jb.alpha;
            if (jb.relu) {
                o0 = fmaxf(o0, 0.f); o1 = fmaxf(o1, 0.f);
                o2 = fmaxf(o2, 0.f); o3 = fmaxf(o3, 0.f);
            }
            if (r < M) {
                size_t o = (size_t)r * N + cn;
                if (jb.C) *(float2*)(jb.C + o) = make_float2(o0, o1);
                if (jb.Ch) {
                    uint32_t hi, lo; split2(o0, o1, hi, lo);
                    *(uint32_t*)(jb.Ch + o) = hi; *(uint32_t*)(jb.Cl + o) = lo;
                }
            }
            if (r + 8 < M) {
                size_t o = (size_t)(r + 8) * N + cn;
                if (jb.C) *(float2*)(jb.C + o) = make_float2(o2, o3);
                if (jb.Ch) {
                    uint32_t hi, lo; split2(o2, o3, hi, lo);
                    *(uint32_t*)(jb.Ch + o) = hi; *(uint32_t*)(jb.Cl + o) = lo;
                }
            }
        }
}

// ------------------------- scores on tensor cores (tf32) -----------------------
__global__ __launch_bounds__(128) void scores_tc(
    const float* __restrict__ qr, const float* __restrict__ qc,
    const float* __restrict__ kr, const float* __restrict__ kc,
    const unsigned char* __restrict__ mask,
    float* __restrict__ awr, float* __restrict__ awc)
{
    __shared__ uint32_t Qs[64 * 36];
    __shared__ uint32_t Ks[32 * 72];
    __shared__ unsigned char Ms[LL];
    int z = blockIdx.z;
    int b = z & 1, which = z >> 1;
    const float* q  = which ? qc : qr;
    const float* kk = which ? kc : kr;
    float* aw       = which ? awc : awr;
    int mstride     = which ? LL : 1;
    int n = blockIdx.y, q0 = blockIdx.x * 64;
    int tid = threadIdx.x, warp = tid >> 5, lane = tid & 31;
    int g = lane >> 2, tq = lane & 3;

    // load Q tile 64x32 -> tf32
    {
        int rq = tid >> 1, hf = (tid & 1) * 16;
        const float* qp = q + ((size_t)(b * NQ + q0 + rq)) * CC + n * HD + hf;
        #pragma unroll
        for (int j = 0; j < 4; j++) {
            float4 v = *(const float4*)(qp + j * 4);
            Qs[rq * 36 + hf + j * 4 + 0] = f2tf32(v.x);
            Qs[rq * 36 + hf + j * 4 + 1] = f2tf32(v.y);
            Qs[rq * 36 + hf + j * 4 + 2] = f2tf32(v.z);
            Qs[rq * 36 + hf + j * 4 + 3] = f2tf32(v.w);
        }
    }
    // load K transposed: Ks[d][l]
    for (int i = tid; i < LL * HD; i += 128) {
        int l = i >> 5, d = i & 31;
        Ks[d * 72 + l] = f2tf32(kk[((size_t)(b * LL + l)) * CC + n * HD + d]);
    }
    if (tid < LL) Ms[tid] = mask[b * NQ + tid * mstride];
    __syncthreads();

    uint32_t a[4][4];
    int rb = warp * 16;
    #pragma unroll
    for (int ks = 0; ks < 4; ks++) {
        a[ks][0] = Qs[(rb + g) * 36 + ks * 8 + tq];
        a[ks][1] = Qs[(rb + g + 8) * 36 + ks * 8 + tq];
        a[ks][2] = Qs[(rb + g) * 36 + ks * 8 + tq + 4];
        a[ks][3] = Qs[(rb + g + 8) * 36 + ks * 8 + tq + 4];
    }
    float c[7][4];
    #pragma unroll
    for (int nt = 0; nt < 7; nt++)
        #pragma unroll
        for (int i = 0; i < 4; i++) c[nt][i] = 0.f;
    #pragma unroll
    for (int nt = 0; nt < 7; nt++)
        #pragma unroll
        for (int ks = 0; ks < 4; ks++) {
            uint32_t bf[2] = { Ks[(ks * 8 + tq) * 72 + nt * 8 + g],
                               Ks[(ks * 8 + tq + 4) * 72 + nt * 8 + g] };
            mma_tf32(c[nt], a[ks], bf);
        }

    // mask + softmax (rows g and g+8)
    float m0 = -3.0e38f, m1 = -3.0e38f;
    #pragma unroll
    for (int nt = 0; nt < 7; nt++) {
        int col = nt * 8 + tq * 2;
        if (Ms[col])     { c[nt][0] = NEGF; c[nt][2] = NEGF; }
        if (Ms[col + 1]) { c[nt][1] = NEGF; c[nt][3] = NEGF; }
        m0 = fmaxf(m0, fmaxf(c[nt][0], c[nt][1]));
        m1 = fmaxf(m1, fmaxf(c[nt][2], c[nt][3]));
    }
    #pragma unroll
    for (int o = 1; o <= 2; o <<= 1) {
        m0 = fmaxf(m0, __shfl_xor_sync(0xffffffffu, m0, o));
        m1 = fmaxf(m1, __shfl_xor_sync(0xffffffffu, m1, o));
    }
    float s0 = 0.f, s1 = 0.f;
    #pragma unroll
    for (int nt = 0; nt < 7; nt++) {
        c[nt][0] = __expf(c[nt][0] - m0);
        c[nt][1] = __expf(c[nt][1] - m0);
        c[nt][2] = __expf(c[nt][2] - m1);
        c[nt][3] = __expf(c[nt][3] - m1);
        s0 += c[nt][0] + c[nt][1];
        s1 += c[nt][2] + c[nt][3];
    }
    #pragma unroll
    for (int o = 1; o <= 2; o <<= 1) {
        s0 += __shfl_xor_sync(0xffffffffu, s0, o);
        s1 += __shfl_xor_sync(0xffffffffu, s1, o);
    }
    float i0 = 1.0f / s0, i1 = 1.0f / s1;
    float* d0 = aw + ((size_t)((b * NH + n)) * NQ + q0 + rb + g) * LL + tq * 2;
    float* d1 = aw + ((size_t)((b * NH + n)) * NQ + q0 + rb + g + 8) * LL + tq * 2;
    #pragma unroll
    for (int nt = 0; nt < 7; nt++) {
        *(float2*)(d0 + nt * 8) = make_float2(c[nt][0] * i0, c[nt][1] * i0);
        *(float2*)(d1 + nt * 8) = make_float2(c[nt][2] * i1, c[nt][3] * i1);
    }
}

// ------------------------- RCDA recombination (tf32, 4 warps) ------------------
__global__ __launch_bounds__(128) void combine_tc(
    const float* __restrict__ awr, const float* __restrict__ awc,
    const float* __restrict__ v,
    __nv_bfloat16* __restrict__ attnh, __nv_bfloat16* __restrict__ attnl)
{
    __shared__ float    ACs[64 * 57];
    __shared__ uint32_t ub[2 * 64 * 40];    // V stages; also AR staging (64x68 fits)

    int b = blockIdx.z, n = blockIdx.y, q0 = blockIdx.x * 64;
    int tid = threadIdx.x, warp = tid >> 5, lane = tid & 31;
    int g = lane >> 2, tq = lane & 3;
    int rb = warp * 16;

    const float* arg = awr + ((size_t)((b * NH + n)) * NQ + q0) * LL;
    const float* acg = awc + ((size_t)((b * NH + n)) * NQ + q0) * LL;
    for (int i = tid; i < 64 * 64; i += 128) {
        int qi = i >> 6, k = i & 63;
        float va = (k < LL) ? arg[qi * LL + k] : 0.f;
        ub[qi * 68 + k] = f2tf32(va);
        if (k < LL) ACs[qi * 57 + k] = acg[qi * LL + k];
    }
    __syncthreads();

    uint32_t af[8][4];
    #pragma unroll
    for (int ks = 0; ks < 8; ks++) {
        af[ks][0] = ub[(rb + g) * 68 + ks * 8 + tq];
        af[ks][1] = ub[(rb + g + 8) * 68 + ks * 8 + tq];
        af[ks][2] = ub[(rb + g) * 68 + ks * 8 + tq + 4];
        af[ks][3] = ub[(rb + g + 8) * 68 + ks * 8 + tq + 4];
    }
    __syncthreads();

    // zero pad V rows 56..63 in both stages
    for (int i = tid; i < 640; i += 128) {
        int s = i / 320, rr = i % 320;
        ub[s * 2560 + 2240 + rr] = 0;
    }

    float2 vb[7];
    {
        const float* vg = v + ((size_t)(b * NQ)) * CC + n * HD;
        #pragma unroll
        for (int j = 0; j < 7; j++) {
            int i2 = tid + j * 128;
            int w = i2 >> 4, d2 = i2 & 15;
            vb[j] = *(const float2*)(vg + (size_t)w * CC + d2 * 2);
        }
        #pragma unroll
        for (int j = 0; j < 7; j++) {
            int i2 = tid + j * 128;
            int w = i2 >> 4, d2 = i2 & 15;
            ub[w * 40 + d2 * 2]     = f2tf32(vb[j].x);
            ub[w * 40 + d2 * 2 + 1] = f2tf32(vb[j].y);
        }
    }
    __syncthreads();

    float oacc[4][4];
    #pragma unroll
    for (int nt = 0; nt < 4; nt++)
        #pragma unroll
        for (int i = 0; i < 4; i++) oacc[nt][i] = 0.f;

    for (int h = 0; h < LL; h++) {
        int s = h & 1;
        if (h + 1 < LL) {
            const float* vg = v + ((size_t)(b * NQ) + (h + 1) * LL) * CC + n * HD;
            #pragma unroll
            for (int j = 0; j < 7; j++) {
                int i2 = tid + j * 128;
                int w = i2 >> 4, d2 = i2 & 15;
                vb[j] = *(const float2*)(vg + (size_t)w * CC + d2 * 2);
            }
        }
        float p[4][4];
        #pragma unroll
        for (int nt = 0; nt < 4; nt++)
            #pragma unroll
            for (int i = 0; i < 4; i++) p[nt][i] = 0.f;

        const uint32_t* Vst = ub + s * 2560;
        #pragma unroll
        for (int ks = 0; ks < 8; ks++)
            #pragma unroll
            for (int nt = 0; nt < 4; nt++) {
                uint32_t bf[2] = { Vst[(ks * 8 + tq) * 40 + nt * 8 + g],
                                   Vst[(ks * 8 + tq + 4) * 40 + nt * 8 + g] };
                mma_tf32(p[nt], af[ks], bf);
            }

        float ac0 = ACs[(rb + g) * 57 + h];
        float ac1 = ACs[(rb + g + 8) * 57 + h];
        #pragma unroll
        for (int nt = 0; nt < 4; nt++) {
            oacc[nt][0] += ac0 * p[nt][0];
            oacc[nt][1] += ac0 * p[nt][1];
            oacc[nt][2] += ac1 * p[nt][2];
            oacc[nt][3] += ac1 * p[nt][3];
        }
        if (h + 1 < LL) {
            uint32_t* dst = ub + (s ^ 1) * 2560;
            #pragma unroll
            for (int j = 0; j < 7; j++) {
                int i2 = tid + j * 128;
                int w = i2 >> 4, d2 = i2 & 15;
                dst[w * 40 + d2 * 2]     = f2tf32(vb[j].x);
                dst[w * 40 + d2 * 2 + 1] = f2tf32(vb[j].y);
            }
            __syncthreads();
        }
    }

    #pragma unroll
    for (int nt = 0; nt < 4; nt++) {
        int r = q0 + rb + g;
        int col = n * HD + nt * 8 + tq * 2;
        uint32_t hi, lo;
        split2(oacc[nt][0], oacc[nt][1], hi, lo);
        *(uint32_t*)(attnh + ((size_t)(b * NQ) + r) * CC + col) = hi;
        *(uint32_t*)(attnl + ((size_t)(b * NQ) + r) * CC + col) = lo;
        split2(oacc[nt][2], oacc[nt][3], hi, lo);
        *(uint32_t*)(attnh + ((size_t)(b * NQ) + r + 8) * CC + col) = hi;
        *(uint32_t*)(attnl + ((size_t)(b * NQ) + r + 8) * CC + col) = lo;
    }
}

// ------------------------- residual + layernorm --------------------------------
__global__ __launch_bounds__(256) void add_ln(
    const float* __restrict__ A, const float* __restrict__ B,
    const float* __restrict__ gg, const float* __restrict__ be,
    float* __restrict__ out,
    __nv_bfloat16* __restrict__ oh, __nv_bfloat16* __restrict__ ol,
    int transpose_out)
{
    __shared__ float tile[256 * 33];
    int row0 = blockIdx.x * 32;
    int b = row0 / NQ;
    int qg0 = row0 % NQ;
    int tid = threadIdx.x, warp = tid >> 5, lane = tid & 31;

    float4 g0 = *(const float4*)(gg + lane * 4);
    float4 g1 = *(const float4*)(gg + 128 + lane * 4);
    float4 e0 = *(const float4*)(be + lane * 4);
    float4 e1 = *(const float4*)(be + 128 + lane * 4);

    #pragma unroll
    for (int rr = 0; rr < 4; rr++) {
        int rloc = warp * 4 + rr;
        size_t base = (size_t)(row0 + rloc) * CC;
        float4 a0 = *(const float4*)(A + base + lane * 4);
        float4 b0 = *(const float4*)(B + base + lane * 4);
        float4 a1 = *(const float4*)(A + base + 128 + lane * 4);
        float4 b1 = *(const float4*)(B + base + 128 + lane * 4);
        float v0x = a0.x + b0.x, v0y = a0.y + b0.y, v0z = a0.z + b0.z, v0w = a0.w + b0.w;
        float v1x = a1.x + b1.x, v1y = a1.y + b1.y, v1z = a1.z + b1.z, v1w = a1.w + b1.w;
        float s  = v0x + v0y + v0z + v0w + v1x + v1y + v1z + v1w;
        float s2 = v0x*v0x + v0y*v0y + v0z*v0z + v0w*v0w
                 + v1x*v1x + v1y*v1y + v1z*v1z + v1w*v1w;
        #pragma unroll
        for (int o = 16; o; o >>= 1) {
            s  += __shfl_xor_sync(0xffffffffu, s,  o);
            s2 += __shfl_xor_sync(0xffffffffu, s2, o);
        }
        float mean = s * (1.0f / CC);
        float var = s2 * (1.0f / CC) - mean * mean;
        float rstd = rsqrtf(var + 1e-5f);
        float r0x = (v0x - mean) * rstd * g0.x + e0.x;
        float r0y = (v0y - mean) * rstd * g0.y + e0.y;
        float r0z = (v0z - mean) * rstd * g0.z + e0.z;
        float r0w = (v0w - mean) * rstd * g0.w + e0.w;
        float r1x = (v1x - mean) * rstd * g1.x + e1.x;
        float r1y = (v1y - mean) * rstd * g1.y + e1.y;
        float r1z = (v1z - mean) * rstd * g1.z + e1.z;
        float r1w = (v1w - mean) * rstd * g1.w + e1.w;
        if (!transpose_out) {
            *(float4*)(out + base + lane * 4) = make_float4(r0x, r0y, r0z, r0w);
            *(float4*)(out + base + 128 + lane * 4) = make_float4(r1x, r1y, r1z, r1w);
            if (oh) {
                uint32_t h0, l0, h1, l1;
                split2(r0x, r0y, h0, l0); split2(r0z, r0w, h1, l1);
                ((uint32_t*)(oh + base + lane * 4))[0] = h0;
                ((uint32_t*)(oh + base + lane * 4))[1] = h1;
                ((uint32_t*)(ol + base + lane * 4))[0] = l0;
                ((uint32_t*)(ol + base + lane * 4))[1] = l1;
                split2(r1x, r1y, h0, l0); split2(r1z, r1w, h1, l1);
                ((uint32_t*)(oh + base + 128 + lane * 4))[0] = h0;
                ((uint32_t*)(oh + base + 128 + lane * 4))[1] = h1;
                ((uint32_t*)(ol + base + 128 + lane * 4))[0] = l0;
                ((uint32_t*)(ol + base + 128 + lane * 4))[1] = l1;
            }
        } else {
            int c = lane * 4;
            tile[(c + 0) * 33 + rloc] = r0x;
            tile[(c + 1) * 33 + rloc] = r0y;
            tile[(c + 2) * 33 + rloc] = r0z;
            tile[(c + 3) * 33 + rloc] = r0w;
            tile[(c + 128) * 33 + rloc] = r1x;
            tile[(c + 129) * 33 + rloc] = r1y;
            tile[(c + 130) * 33 + rloc] = r1z;
            tile[(c + 131) * 33 + rloc] = r1w;
        }
    }
    if (transpose_out) {
        __syncthreads();
        int qv = tid & 31;
        int cb = tid >> 5;
        #pragma unroll 8
        for (int k = 0; k < 32; k++) {
            int c = cb + k * 8;
            out[((size_t)(b * CC + c)) * NQ + qg0 + qv] = tile[c * 33 + qv];
        }
    }
}

// ------------------------- launch ----------------------------------------------
extern "C" void kernel_launch(void* const* d_in, const int* in_sizes, int n_in,
                              void* d_out, int out_size)
{
    const float* src   = (const float*)d_in[0];
    const unsigned char* pm = (const unsigned char*)d_in[1];
    const float* pr    = (const float*)d_in[2];
    const float* pc    = (const float*)d_in[3];
    const float* w_q_row = (const float*)d_in[4];
    const float* b_q_row = (const float*)d_in[5];
    const float* w_q_col = (const float*)d_in[6];
    const float* b_q_col = (const float*)d_in[7];
    const float* w_k_row = (const float*)d_in[8];
    const float* b_k_row = (const float*)d_in[9];
    const float* w_k_col = (const float*)d_in[10];
    const float* b_k_col = (const float*)d_in[11];
    const float* w_v   = (const float*)d_in[12];
    const float* b_v   = (const float*)d_in[13];
    const float* w_out = (const float*)d_in[14];
    const float* b_out = (const float*)d_in[15];
    const float* n1g   = (const float*)d_in[16];
    const float* n1b   = (const float*)d_in[17];
    const float* l1w   = (const float*)d_in[18];
    const float* l1b   = (const float*)d_in[19];
    const float* l2w   = (const float*)d_in[20];
    const float* l2b   = (const float*)d_in[21];
    const float* n2g   = (const float*)d_in[22];
    const float* n2b   = (const float*)d_in[23];
    float* out = (float*)d_out;

    float* F = nullptr;
    __nv_bfloat16* Hh = nullptr;
    cudaGetSymbolAddress((void**)&F, g_f);
    cudaGetSymbolAddress((void**)&Hh, g_h);

    cudaFuncSetAttribute(gemm_bf16, cudaFuncAttributeMaxDynamicSharedMemorySize, 61440);

    // 1. convert weights
    {
        WJobs w;
        const float* ss[8] = {w_q_row, w_q_col, w_k_row, w_k_col, w_v, w_out, l1w, l2w};
        size_t ho[8] = {H_WQRH, H_WQCH, H_WKRH, H_WKCH, H_WVH, H_WOH, H_L1H, H_L2H};
        size_t lo_[8] = {H_WQRL, H_WQCL, H_WKRL, H_WKCL, H_WVL, H_WOL, H_L1L, H_L2L};
        int nn[8] = {CC*CC, CC*CC, CC*CC, CC*CC, CC*CC, CC*CC, DFFN*CC, CC*DFFN};
        for (int i = 0; i < 8; i++) {
            w.s[i] = ss[i]; w.h[i] = Hh + ho[i]; w.l[i] = Hh + lo_[i]; w.n[i] = nn[i];
        }
        convert_w<<<dim3(DFFN * CC / 1024, 8), 256>>>(w);
    }

    // 2. prep
    prep_kernel<<<dim3(NQ / 64, CC / 64, BZV), 256>>>(
        src, pr, pc, F + F_X,
        Hh + H_XH, Hh + H_XL, Hh + H_XPRH, Hh + H_XPRL, Hh + H_XPCH, Hh + H_XPCL);

    // 3. pool
    pool_kernel<<<BZV * LL * CC / 256, 256>>>(
        F + F_X, pr, pc, Hh + H_PRH, Hh + H_PRL, Hh + H_PCH, Hh + H_PCL);

    // 4. projections (batched z=3)
    {
        GemmArgs a;
        a.j[0] = {Hh+H_XPRH, Hh+H_XPRL, Hh+H_WQRH, Hh+H_WQRL, b_q_row, F+F_QROW, nullptr, nullptr, SCALE, 0};
        a.j[1] = {Hh+H_XPCH, Hh+H_XPCL, Hh+H_WQCH, Hh+H_WQCL, b_q_col, F+F_QCOL, nullptr, nullptr, SCALE, 0};
        a.j[2] = {Hh+H_XH,   Hh+H_XL,   Hh+H_WVH,  Hh+H_WVL,  b_v,     F+F_V,    nullptr, nullptr, 1.0f, 0};
        gemm_bf16<<<dim3(CC/64, MQ/128, 3), 256, 61440>>>(a, MQ, CC, CC);
    }
    // 5. k projections (batched z=2)
    {
        GemmArgs a;
        a.j[0] = {Hh+H_PRH, Hh+H_PRL, Hh+H_WKRH, Hh+H_WKRL, b_k_row, F+F_KROW, nullptr, nullptr, 1.0f, 0};
        a.j[1] = {Hh+H_PCH, Hh+H_PCL, Hh+H_WKCH, Hh+H_WKCL, b_k_col, F+F_KCOL, nullptr, nullptr, 1.0f, 0};
        a.j[2] = a.j[0];
        gemm_bf16<<<dim3(CC/64, 1, 2), 256, 61440>>>(a, BZV*LL, CC, CC);
    }

    // 6. scores (row + col batched, z = 4)
    scores_tc<<<dim3(NQ/64, NH, 4), 128>>>(
        F+F_QROW, F+F_QCOL, F+F_KROW, F+F_KCOL, pm, F+F_AWROW, F+F_AWCOL);

    // 7. combine
    combine_tc<<<dim3(NQ/64, NH, BZV), 128>>>(
        F+F_AWROW, F+F_AWCOL, F+F_V, Hh+H_ATTNH, Hh+H_ATTNL);

    // 8. out projection
    {
        GemmArgs a;
        a.j[0] = {Hh+H_ATTNH, Hh+H_ATTNL, Hh+H_WOH, Hh+H_WOL, b_out, F+F_ATTNOUT, nullptr, nullptr, 1.0f, 0};
        a.j[1] = a.j[0]; a.j[2] = a.j[0];
        gemm_bf16<<<dim3(CC/64, MQ/128, 1), 256, 61440>>>(a, MQ, CC, CC);
    }
    // 9. LN1 (+ x1 hi/lo)
    add_ln<<<MQ/32, 256>>>(F+F_X, F+F_ATTNOUT, n1g, n1b, F+F_X1,
                           Hh+H_X1H, Hh+H_X1L, 0);
    // 10. FFN1 (relu, hi/lo only)
    {
        GemmArgs a;
        a.j[0] = {Hh+H_X1H, Hh+H_X1L, Hh+H_L1H, Hh+H_L1L, l1b, nullptr, Hh+H_FFNH, Hh+H_FFNL, 1.0f, 1};
        a.j[1] = a.j[0]; a.j[2] = a.j[0];
        gemm_bf16<<<dim3(DFFN/64, MQ/128, 1), 256, 61440>>>(a, MQ, DFFN, CC);
    }
    // 11. FFN2
    {
        GemmArgs a;
        a.j[0] = {Hh+H_FFNH, Hh+H_FFNL, Hh+H_L2H, Hh+H_L2L, l2b, F+F_Y, nullptr, nullptr, 1.0f, 0};
        a.j[1] = a.j[0]; a.j[2] = a.j[0];
        gemm_bf16<<<dim3(CC/64, MQ/128, 1), 256, 61440>>>(a, MQ, CC, DFFN);
    }
    // 12. LN2 + transpose to (b,c,h,w)
    add_ln<<<MQ/32, 256>>>(F+F_X1, F+F_Y, n2g, n2b, out, nullptr, nullptr, 1);
}

// round 5
// speedup vs baseline: 2.7566x; 1.1261x over previous
#include <cuda_runtime.h>
#include <cuda_bf16.h>
#include <cstdint>
#include <cstddef>

#define NQ    3136
#define CC    256
#define BZV   2
#define NH    8
#define HD    32
#define LL    56
#define DFFN  1024
#define MQ    (BZV*NQ)
#define SCALE 0.17677669529663687f
#define NEGF  (-3.402823466e38f)

// ------------------------- scratch buffers -----------------------------------
#define SZ_BQC (MQ*CC)
#define SZ_KP  (BZV*LL*CC)
#define SZ_AW  (BZV*NH*NQ*LL)
#define SZ_FFN (MQ*DFFN)

#define F_X       ((size_t)0)
#define F_QROW    (F_X    + SZ_BQC)
#define F_QCOL    (F_QROW + SZ_BQC)
#define F_V       (F_QCOL + SZ_BQC)
#define F_ATTNOUT (F_V    + SZ_BQC)
#define F_X1      (F_ATTNOUT + SZ_BQC)
#define F_Y       (F_X1   + SZ_BQC)
#define F_KROW    (F_Y    + SZ_BQC)
#define F_KCOL    (F_KROW + SZ_KP)
#define F_AWROW   (F_KCOL + SZ_KP)
#define F_AWCOL   (F_AWROW + SZ_AW)
#define F_TOTAL   (F_AWCOL + SZ_AW)
__device__ float g_f[F_TOTAL];

#define H_XH    ((size_t)0)
#define H_XL    (H_XH  + SZ_BQC)
#define H_XPRH  (H_XL  + SZ_BQC)
#define H_XPRL  (H_XPRH+ SZ_BQC)
#define H_XPCH  (H_XPRL+ SZ_BQC)
#define H_XPCL  (H_XPCH+ SZ_BQC)
#define H_PRH   (H_XPCL+ SZ_BQC)
#define H_PRL   (H_PRH + SZ_KP)
#define H_PCH   (H_PRL + SZ_KP)
#define H_PCL   (H_PCH + SZ_KP)
#define H_ATTNH (H_PCL + SZ_KP)
#define H_ATTNL (H_ATTNH + SZ_BQC)
#define H_X1H   (H_ATTNL + SZ_BQC)
#define H_X1L   (H_X1H + SZ_BQC)
#define H_FFNH  (H_X1L + SZ_BQC)
#define H_FFNL  (H_FFNH + SZ_FFN)
#define H_WQRH  (H_FFNL + SZ_FFN)
#define H_WQRL  (H_WQRH + CC*CC)
#define H_WQCH  (H_WQRL + CC*CC)
#define H_WQCL  (H_WQCH + CC*CC)
#define H_WKRH  (H_WQCL + CC*CC)
#define H_WKRL  (H_WKRH + CC*CC)
#define H_WKCH  (H_WKRL + CC*CC)
#define H_WKCL  (H_WKCH + CC*CC)
#define H_WVH   (H_WKCL + CC*CC)
#define H_WVL   (H_WVH  + CC*CC)
#define H_WOH   (H_WVL  + CC*CC)
#define H_WOL   (H_WOH  + CC*CC)
#define H_L1H   (H_WOL  + CC*CC)
#define H_L1L   (H_L1H  + DFFN*CC)
#define H_L2H   (H_L1L  + DFFN*CC)
#define H_L2L   (H_L2H  + CC*DFFN)
#define H_TOTAL (H_L2L  + CC*DFFN)
__device__ __nv_bfloat16 g_h[H_TOTAL];

// ------------------------- helpers -------------------------------------------
__device__ __forceinline__ uint32_t f2tf32(float x) {
    uint32_t r; asm("cvt.rna.tf32.f32 %0, %1;" : "=r"(r) : "f"(x)); return r;
}
__device__ __forceinline__ void mma_bf16(float (&c)[4], const uint32_t (&a)[4],
                                         const uint32_t (&b)[2]) {
    asm volatile("mma.sync.aligned.m16n8k16.row.col.f32.bf16.bf16.f32 "
        "{%0,%1,%2,%3},{%4,%5,%6,%7},{%8,%9},{%0,%1,%2,%3};"
        : "+f"(c[0]), "+f"(c[1]), "+f"(c[2]), "+f"(c[3])
        : "r"(a[0]), "r"(a[1]), "r"(a[2]), "r"(a[3]), "r"(b[0]), "r"(b[1]));
}
__device__ __forceinline__ void mma_tf32(float (&c)[4], const uint32_t (&a)[4],
                                         const uint32_t (&b)[2]) {
    asm volatile("mma.sync.aligned.m16n8k8.row.col.f32.tf32.tf32.f32 "
        "{%0,%1,%2,%3},{%4,%5,%6,%7},{%8,%9},{%0,%1,%2,%3};"
        : "+f"(c[0]), "+f"(c[1]), "+f"(c[2]), "+f"(c[3])
        : "r"(a[0]), "r"(a[1]), "r"(a[2]), "r"(a[3]), "r"(b[0]), "r"(b[1]));
}
__device__ __forceinline__ void split2(float a, float b, uint32_t& hi, uint32_t& lo) {
    __nv_bfloat16 ha = __float2bfloat16(a), hb = __float2bfloat16(b);
    __nv_bfloat16 la = __float2bfloat16(a - __bfloat162float(ha));
    __nv_bfloat16 lb = __float2bfloat16(b - __bfloat162float(hb));
    hi = (uint32_t)__bfloat16_as_ushort(ha) | ((uint32_t)__bfloat16_as_ushort(hb) << 16);
    lo = (uint32_t)__bfloat16_as_ushort(la) | ((uint32_t)__bfloat16_as_ushort(lb) << 16);
}
__device__ __forceinline__ void ldsm_x4(uint32_t& r0, uint32_t& r1,
                                        uint32_t& r2, uint32_t& r3,
                                        const uint32_t* p) {
    uint32_t addr = (uint32_t)__cvta_generic_to_shared(p);
    asm volatile("ldmatrix.sync.aligned.m8n8.x4.shared.b16 {%0,%1,%2,%3},[%4];"
        : "=r"(r0), "=r"(r1), "=r"(r2), "=r"(r3) : "r"(addr));
}

// ------------------------- weight conversion ----------------------------------
struct WJobs { const float* s[8]; __nv_bfloat16* h[8]; __nv_bfloat16* l[8]; int n[8]; };
__global__ __launch_bounds__(256) void convert_w(WJobs w) {
    int j = blockIdx.y;
    int i = (blockIdx.x * 256 + threadIdx.x) * 4;
    if (i >= w.n[j]) return;
    float4 v = *(const float4*)(w.s[j] + i);
    uint32_t h0, l0, h1, l1;
    split2(v.x, v.y, h0, l0);
    split2(v.z, v.w, h1, l1);
    uint32_t* ph = (uint32_t*)(w.h[j] + i);
    uint32_t* pl = (uint32_t*)(w.l[j] + i);
    ph[0] = h0; ph[1] = h1; pl[0] = l0; pl[1] = l1;
}

// ------------------------- prep ------------------------------------------------
__global__ __launch_bounds__(256) void prep_kernel(
    const float* __restrict__ src, const float* __restrict__ pr,
    const float* __restrict__ pc, float* __restrict__ x,
    __nv_bfloat16* __restrict__ xh, __nv_bfloat16* __restrict__ xl,
    __nv_bfloat16* __restrict__ xprh, __nv_bfloat16* __restrict__ xprl,
    __nv_bfloat16* __restrict__ xpch, __nv_bfloat16* __restrict__ xpcl)
{
    __shared__ float tile[64 * 65];
    int b = blockIdx.z;
    int q0 = blockIdx.x * 64, c0 = blockIdx.y * 64;
    int tid = threadIdx.x;

    int cl_ = tid >> 2, qs = (tid & 3) * 16;
    const float* sp = src + ((size_t)(b * CC + c0 + cl_)) * NQ + q0 + qs;
    #pragma unroll
    for (int j = 0; j < 4; j++) {
        float4 vv = *(const float4*)(sp + j * 4);
        tile[cl_ * 65 + qs + j * 4 + 0] = vv.x;
        tile[cl_ * 65 + qs + j * 4 + 1] = vv.y;
        tile[cl_ * 65 + qs + j * 4 + 2] = vv.z;
        tile[cl_ * 65 + qs + j * 4 + 3] = vv.w;
    }
    __syncthreads();

    int ql = tid >> 2, cs = (tid & 3) * 16;
    int q = q0 + ql;
    int irow = q / LL, jcol = q % LL;
    const float* prp = pr + (size_t)(b * LL + jcol) * CC + c0 + cs;
    const float* pcp = pc + (size_t)(b * LL + irow) * CC + c0 + cs;
    size_t ob = ((size_t)(b * NQ + q)) * CC + c0 + cs;
    #pragma unroll
    for (int j = 0; j < 4; j++) {
        float v0 = tile[(cs + j * 4 + 0) * 65 + ql];
        float v1 = tile[(cs + j * 4 + 1) * 65 + ql];
        float v2 = tile[(cs + j * 4 + 2) * 65 + ql];
        float v3 = tile[(cs + j * 4 + 3) * 65 + ql];
        float4 p4 = *(const float4*)(prp + j * 4);
        float4 c4 = *(const float4*)(pcp + j * 4);
        *(float4*)(x + ob + j * 4) = make_float4(v0, v1, v2, v3);
        uint32_t h0, l0, h1, l1;
        split2(v0, v1, h0, l0); split2(v2, v3, h1, l1);
        ((uint32_t*)(xh + ob + j * 4))[0] = h0; ((uint32_t*)(xh + ob + j * 4))[1] = h1;
        ((uint32_t*)(xl + ob + j * 4))[0] = l0; ((uint32_t*)(xl + ob + j * 4))[1] = l1;
        split2(v0 + p4.x, v1 + p4.y, h0, l0); split2(v2 + p4.z, v3 + p4.w, h1, l1);
        ((uint32_t*)(xprh + ob + j * 4))[0] = h0; ((uint32_t*)(xprh + ob + j * 4))[1] = h1;
        ((uint32_t*)(xprl + ob + j * 4))[0] = l0; ((uint32_t*)(xprl + ob + j * 4))[1] = l1;
        split2(v0 + c4.x, v1 + c4.y, h0, l0); split2(v2 + c4.z, v3 + c4.w, h1, l1);
        ((uint32_t*)(xpch + ob + j * 4))[0] = h0; ((uint32_t*)(xpch + ob + j * 4))[1] = h1;
        ((uint32_t*)(xpcl + ob + j * 4))[0] = l0; ((uint32_t*)(xpcl + ob + j * 4))[1] = l1;
    }
}

// ------------------------- pooling ---------------------------------------------
__global__ __launch_bounds__(256) void pool_kernel(
    const float* __restrict__ x, const float* __restrict__ pr,
    const float* __restrict__ pc,
    __nv_bfloat16* __restrict__ prh, __nv_bfloat16* __restrict__ prl,
    __nv_bfloat16* __restrict__ pch, __nv_bfloat16* __restrict__ pcl)
{
    int idx = blockIdx.x * 256 + threadIdx.x;
    int c = idx & 255;
    int t = idx >> 8;
    int rc = t % LL;
    int b = t / LL;
    float sr = 0.f, sc = 0.f;
    #pragma unroll 8
    for (int i = 0; i < LL; i++) {
        sr += x[((size_t)(b * NQ) + i * LL + rc) * CC + c];
        sc += x[((size_t)(b * NQ) + rc * LL + i) * CC + c];
    }
    float vr = sr * (1.0f / LL) + pr[idx];
    float vc = sc * (1.0f / LL) + pc[idx];
    __nv_bfloat16 h = __float2bfloat16(vr);
    prh[idx] = h; prl[idx] = __float2bfloat16(vr - __bfloat162float(h));
    h = __float2bfloat16(vc);
    pch[idx] = h; pcl[idx] = __float2bfloat16(vc - __bfloat162float(h));
}

// ------------------------- batched bf16 split GEMM (ldmatrix) -------------------
struct GemmJob {
    const __nv_bfloat16 *Ah, *Al, *Bh, *Bl;
    const float* bias;
    float* C;
    __nv_bfloat16 *Ch, *Cl;
    float alpha;
    int relu;
};
struct GemmArgs { GemmJob j[3]; };

__global__ __launch_bounds__(256, 2) void gemm_bf16(GemmArgs args, int M, int N, int K)
{
    extern __shared__ uint32_t sm[];
    const GemmJob jb = args.j[blockIdx.z];
    const int STG = 7680;
    int bm = blockIdx.y * 128, bn = blockIdx.x * 64;
    int tid = threadIdx.x, warp = tid >> 5, lane = tid & 31;
    int wm = warp & 3, wn = warp >> 2, g = lane >> 2, tq = lane & 3;
    int l16 = lane & 15, lhk = (lane >> 4) * 4;   // ldmatrix row / k-half (u32)

    float acc[2][4][4];
    #pragma unroll
    for (int mt = 0; mt < 2; mt++)
        #pragma unroll
        for (int nt = 0; nt < 4; nt++)
            #pragma unroll
            for (int i = 0; i < 4; i++) acc[mt][nt][i] = 0.f;

    int ar = tid >> 1, ahf = tid & 1;
    int br = tid >> 2, bqt = tid & 3;
    int KT = K >> 5;

    uint4 rAh[2], rAl[2], rBh, rBl;
    {
        int row = bm + ar;
        if (row < M) {
            const uint4* p = (const uint4*)(jb.Ah + (size_t)row * K + ahf * 16);
            rAh[0] = p[0]; rAh[1] = p[1];
            p = (const uint4*)(jb.Al + (size_t)row * K + ahf * 16);
            rAl[0] = p[0]; rAl[1] = p[1];
        } else {
            rAh[0] = rAh[1] = rAl[0] = rAl[1] = make_uint4(0, 0, 0, 0);
        }
        rBh = *(const uint4*)(jb.Bh + (size_t)(bn + br) * K + bqt * 8);
        rBl = *(const uint4*)(jb.Bl + (size_t)(bn + br) * K + bqt * 8);
    }
    {
        uint32_t* sA = sm;
        *(uint4*)(sA + ar * 20 + ahf * 8)     = rAh[0];
        *(uint4*)(sA + ar * 20 + ahf * 8 + 4) = rAh[1];
        *(uint4*)(sA + 2560 + ar * 20 + ahf * 8)     = rAl[0];
        *(uint4*)(sA + 2560 + ar * 20 + ahf * 8 + 4) = rAl[1];
        *(uint4*)(sA + 5120 + br * 20 + bqt * 4) = rBh;
        *(uint4*)(sA + 6400 + br * 20 + bqt * 4) = rBl;
    }
    __syncthreads();

    for (int kt = 0; kt < KT; kt++) {
        int s = kt & 1;
        if (kt + 1 < KT) {
            int k0 = (kt + 1) * 32;
            int row = bm + ar;
            if (row < M) {
                const uint4* p = (const uint4*)(jb.Ah + (size_t)row * K + k0 + ahf * 16);
                rAh[0] = p[0]; rAh[1] = p[1];
                p = (const uint4*)(jb.Al + (size_t)row * K + k0 + ahf * 16);
                rAl[0] = p[0]; rAl[1] = p[1];
            }
            rBh = *(const uint4*)(jb.Bh + (size_t)(bn + br) * K + k0 + bqt * 8);
            rBl = *(const uint4*)(jb.Bl + (size_t)(bn + br) * K + k0 + bqt * 8);
        }

        const uint32_t* sAh = sm + s * STG;
        const uint32_t* sAl = sAh + 2560;
        const uint32_t* sBh = sAh + 5120;
        const uint32_t* sBl = sAh + 6400;
        #pragma unroll
        for (int ks = 0; ks < 2; ks++) {
            int ko = ks * 8;
            uint32_t aH[2][4], aL[2][4], bH[4][2], bL[4][2];
            #pragma unroll
            for (int mt = 0; mt < 2; mt++) {
                const uint32_t* pa = sAh + (wm * 32 + mt * 16 + l16) * 20 + ko + lhk;
                ldsm_x4(aH[mt][0], aH[mt][1], aH[mt][2], aH[mt][3], pa);
                pa = sAl + (wm * 32 + mt * 16 + l16) * 20 + ko + lhk;
                ldsm_x4(aL[mt][0], aL[mt][1], aL[mt][2], aL[mt][3], pa);
            }
            #pragma unroll
            for (int np = 0; np < 2; np++) {
                const uint32_t* pb = sBh + (wn * 32 + np * 16 + l16) * 20 + ko + lhk;
                uint32_t r0, r1, r2, r3;
                ldsm_x4(r0, r1, r2, r3, pb);
                bH[np * 2][0] = r0; bH[np * 2][1] = r2;
                bH[np * 2 + 1][0] = r1; bH[np * 2 + 1][1] = r3;
                pb = sBl + (wn * 32 + np * 16 + l16) * 20 + ko + lhk;
                ldsm_x4(r0, r1, r2, r3, pb);
                bL[np * 2][0] = r0; bL[np * 2][1] = r2;
                bL[np * 2 + 1][0] = r1; bL[np * 2 + 1][1] = r3;
            }
            #pragma unroll
            for (int mt = 0; mt < 2; mt++)
                #pragma unroll
                for (int nt = 0; nt < 4; nt++) {
                    mma_bf16(acc[mt][nt], aH[mt], bH[nt]);
                    mma_bf16(acc[mt][nt], aH[mt], bL[nt]);
                    mma_bf16(acc[mt][nt], aL[mt], bH[nt]);
                }
        }
        if (kt + 1 < KT) {
            uint32_t* dA = sm + (s ^ 1) * STG;
            *(uint4*)(dA + ar * 20 + ahf * 8)     = rAh[0];
            *(uint4*)(dA + ar * 20 + ahf * 8 + 4) = rAh[1];
            *(uint4*)(dA + 2560 + ar * 20 + ahf * 8)     = rAl[0];
            *(uint4*)(dA + 2560 + ar * 20 + ahf * 8 + 4) = rAl[1];
            *(uint4*)(dA + 5120 + br * 20 + bqt * 4) = rBh;
            *(uint4*)(dA + 6400 + br * 20 + bqt * 4) = rBl;
            __syncthreads();
        }
    }

    #pragma unroll
    for (int mt = 0; mt < 2; mt++)
        #pragma unroll
        for (int nt = 0; nt < 4; nt++) {
            int r = bm + wm * 32 + mt * 16 + g;
            int cn = bn + wn * 32 + nt * 8 + tq * 2;
            float b0 = jb.bias[cn], b1 = jb.bias[cn + 1];
            float o0 = (acc[mt][nt][0] + b0) * jb.alpha;
            float o1 = (acc[mt][nt][1] + b1) * jb.alpha;
            float o2 = (acc[mt][nt][2] + b0) * jb.alpha;
            float o3 = (acc[mt][nt][3] + b1) * jb.alpha;
            if (jb.relu) {
                o0 = fmaxf(o0, 0.f); o1 = fmaxf(o1, 0.f);
                o2 = fmaxf(o2, 0.f); o3 = fmaxf(o3, 0.f);
            }
            if (r < M) {
                size_t o = (size_t)r * N + cn;
                if (jb.C) *(float2*)(jb.C + o) = make_float2(o0, o1);
                if (jb.Ch) {
                    uint32_t hi, lo; split2(o0, o1, hi, lo);
                    *(uint32_t*)(jb.Ch + o) = hi; *(uint32_t*)(jb.Cl + o) = lo;
                }
            }
            if (r + 8 < M) {
                size_t o = (size_t)(r + 8) * N + cn;
                if (jb.C) *(float2*)(jb.C + o) = make_float2(o2, o3);
                if (jb.Ch) {
                    uint32_t hi, lo; split2(o2, o3, hi, lo);
                    *(uint32_t*)(jb.Ch + o) = hi; *(uint32_t*)(jb.Cl + o) = lo;
                }
            }
        }
}

// ------------------------- scores (tf32) ----------------------------------------
__global__ __launch_bounds__(128) void scores_tc(
    const float* __restrict__ qr, const float* __restrict__ qc,
    const float* __restrict__ kr, const float* __restrict__ kc,
    const unsigned char* __restrict__ mask,
    float* __restrict__ awr, float* __restrict__ awc)
{
    __shared__ uint32_t Qs[64 * 36];
    __shared__ uint32_t Ks[32 * 72];
    __shared__ unsigned char Ms[LL];
    int z = blockIdx.z;
    int b = z & 1, which = z >> 1;
    const float* q  = which ? qc : qr;
    const float* kk = which ? kc : kr;
    float* aw       = which ? awc : awr;
    int mstride     = which ? LL : 1;
    int n = blockIdx.y, q0 = blockIdx.x * 64;
    int tid = threadIdx.x, warp = tid >> 5, lane = tid & 31;
    int g = lane >> 2, tq = lane & 3;

    {
        int rq = tid >> 1, hf = (tid & 1) * 16;
        const float* qp = q + ((size_t)(b * NQ + q0 + rq)) * CC + n * HD + hf;
        #pragma unroll
        for (int j = 0; j < 4; j++) {
            float4 v = *(const float4*)(qp + j * 4);
            Qs[rq * 36 + hf + j * 4 + 0] = f2tf32(v.x);
            Qs[rq * 36 + hf + j * 4 + 1] = f2tf32(v.y);
            Qs[rq * 36 + hf + j * 4 + 2] = f2tf32(v.z);
            Qs[rq * 36 + hf + j * 4 + 3] = f2tf32(v.w);
        }
    }
    for (int i = tid; i < LL * HD; i += 128) {
        int l = i >> 5, d = i & 31;
        Ks[d * 72 + l] = f2tf32(kk[((size_t)(b * LL + l)) * CC + n * HD + d]);
    }
    if (tid < LL) Ms[tid] = mask[b * NQ + tid * mstride];
    __syncthreads();

    uint32_t a[4][4];
    int rb = warp * 16;
    #pragma unroll
    for (int ks = 0; ks < 4; ks++) {
        a[ks][0] = Qs[(rb + g) * 36 + ks * 8 + tq];
        a[ks][1] = Qs[(rb + g + 8) * 36 + ks * 8 + tq];
        a[ks][2] = Qs[(rb + g) * 36 + ks * 8 + tq + 4];
        a[ks][3] = Qs[(rb + g + 8) * 36 + ks * 8 + tq + 4];
    }
    float c[7][4];
    #pragma unroll
    for (int nt = 0; nt < 7; nt++)
        #pragma unroll
        for (int i = 0; i < 4; i++) c[nt][i] = 0.f;
    #pragma unroll
    for (int nt = 0; nt < 7; nt++)
        #pragma unroll
        for (int ks = 0; ks < 4; ks++) {
            uint32_t bf[2] = { Ks[(ks * 8 + tq) * 72 + nt * 8 + g],
                               Ks[(ks * 8 + tq + 4) * 72 + nt * 8 + g] };
            mma_tf32(c[nt], a[ks], bf);
        }

    float m0 = -3.0e38f, m1 = -3.0e38f;
    #pragma unroll
    for (int nt = 0; nt < 7; nt++) {
        int col = nt * 8 + tq * 2;
        if (Ms[col])     { c[nt][0] = NEGF; c[nt][2] = NEGF; }
        if (Ms[col + 1]) { c[nt][1] = NEGF; c[nt][3] = NEGF; }
        m0 = fmaxf(m0, fmaxf(c[nt][0], c[nt][1]));
        m1 = fmaxf(m1, fmaxf(c[nt][2], c[nt][3]));
    }
    #pragma unroll
    for (int o = 1; o <= 2; o <<= 1) {
        m0 = fmaxf(m0, __shfl_xor_sync(0xffffffffu, m0, o));
        m1 = fmaxf(m1, __shfl_xor_sync(0xffffffffu, m1, o));
    }
    float s0 = 0.f, s1 = 0.f;
    #pragma unroll
    for (int nt = 0; nt < 7; nt++) {
        c[nt][0] = __expf(c[nt][0] - m0);
        c[nt][1] = __expf(c[nt][1] - m0);
        c[nt][2] = __expf(c[nt][2] - m1);
        c[nt][3] = __expf(c[nt][3] - m1);
        s0 += c[nt][0] + c[nt][1];
        s1 += c[nt][2] + c[nt][3];
    }
    #pragma unroll
    for (int o = 1; o <= 2; o <<= 1) {
        s0 += __shfl_xor_sync(0xffffffffu, s0, o);
        s1 += __shfl_xor_sync(0xffffffffu, s1, o);
    }
    float i0 = 1.0f / s0, i1 = 1.0f / s1;
    float* d0 = aw + ((size_t)((b * NH + n)) * NQ + q0 + rb + g) * LL + tq * 2;
    float* d1 = aw + ((size_t)((b * NH + n)) * NQ + q0 + rb + g + 8) * LL + tq * 2;
    #pragma unroll
    for (int nt = 0; nt < 7; nt++) {
        *(float2*)(d0 + nt * 8) = make_float2(c[nt][0] * i0, c[nt][1] * i0);
        *(float2*)(d1 + nt * 8) = make_float2(c[nt][2] * i1, c[nt][3] * i1);
    }
}

// ------------------------- RCDA recombination (tf32, 7 k-steps) ----------------
__global__ __launch_bounds__(128) void combine_tc(
    const float* __restrict__ awr, const float* __restrict__ awc,
    const float* __restrict__ v,
    __nv_bfloat16* __restrict__ attnh, __nv_bfloat16* __restrict__ attnl)
{
    __shared__ float    ACs[64 * 57];
    __shared__ uint32_t ub[2 * 56 * 40];    // V stages; AR staging (64x60 = 3840 fits)

    int b = blockIdx.z, n = blockIdx.y, q0 = blockIdx.x * 64;
    int tid = threadIdx.x, warp = tid >> 5, lane = tid & 31;
    int g = lane >> 2, tq = lane & 3;
    int rb = warp * 16;

    const float* arg = awr + ((size_t)((b * NH + n)) * NQ + q0) * LL;
    const float* acg = awc + ((size_t)((b * NH + n)) * NQ + q0) * LL;
    for (int i = tid; i < 64 * LL; i += 128) {
        int qi = i / LL, k = i % LL;
        ub[qi * 60 + k] = f2tf32(arg[i]);
        ACs[qi * 57 + k] = acg[i];
    }
    __syncthreads();

    uint32_t af[7][4];
    #pragma unroll
    for (int ks = 0; ks < 7; ks++) {
        af[ks][0] = ub[(rb + g) * 60 + ks * 8 + tq];
        af[ks][1] = ub[(rb + g + 8) * 60 + ks * 8 + tq];
        af[ks][2] = ub[(rb + g) * 60 + ks * 8 + tq + 4];
        af[ks][3] = ub[(rb + g + 8) * 60 + ks * 8 + tq + 4];
    }
    __syncthreads();

    float2 vb[7];
    {
        const float* vg = v + ((size_t)(b * NQ)) * CC + n * HD;
        #pragma unroll
        for (int j = 0; j < 7; j++) {
            int i2 = tid + j * 128;
            int w = i2 >> 4, d2 = i2 & 15;
            vb[j] = *(const float2*)(vg + (size_t)w * CC + d2 * 2);
        }
        #pragma unroll
        for (int j = 0; j < 7; j++) {
            int i2 = tid + j * 128;
            int w = i2 >> 4, d2 = i2 & 15;
            ub[w * 40 + d2 * 2]     = f2tf32(vb[j].x);
            ub[w * 40 + d2 * 2 + 1] = f2tf32(vb[j].y);
        }
    }
    __syncthreads();

    float oacc[4][4];
    #pragma unroll
    for (int nt = 0; nt < 4; nt++)
        #pragma unroll
        for (int i = 0; i < 4; i++) oacc[nt][i] = 0.f;

    for (int h = 0; h < LL; h++) {
        int s = h & 1;
        if (h + 1 < LL) {
            const float* vg = v + ((size_t)(b * NQ) + (h + 1) * LL) * CC + n * HD;
            #pragma unroll
            for (int j = 0; j < 7; j++) {
                int i2 = tid + j * 128;
                int w = i2 >> 4, d2 = i2 & 15;
                vb[j] = *(const float2*)(vg + (size_t)w * CC + d2 * 2);
            }
        }
        float p[4][4];
        #pragma unroll
        for (int nt = 0; nt < 4; nt++)
            #pragma unroll
            for (int i = 0; i < 4; i++) p[nt][i] = 0.f;

        const uint32_t* Vst = ub + s * 2240;
        #pragma unroll
        for (int ks = 0; ks < 7; ks++)
            #pragma unroll
            for (int nt = 0; nt < 4; nt++) {
                uint32_t bf[2] = { Vst[(ks * 8 + tq) * 40 + nt * 8 + g],
                                   Vst[(ks * 8 + tq + 4) * 40 + nt * 8 + g] };
                mma_tf32(p[nt], af[ks], bf);
            }

        float ac0 = ACs[(rb + g) * 57 + h];
        float ac1 = ACs[(rb + g + 8) * 57 + h];
        #pragma unroll
        for (int nt = 0; nt < 4; nt++) {
            oacc[nt][0] += ac0 * p[nt][0];
            oacc[nt][1] += ac0 * p[nt][1];
            oacc[nt][2] += ac1 * p[nt][2];
            oacc[nt][3] += ac1 * p[nt][3];
        }
        if (h + 1 < LL) {
            uint32_t* dst = ub + (s ^ 1) * 2240;
            #pragma unroll
            for (int j = 0; j < 7; j++) {
                int i2 = tid + j * 128;
                int w = i2 >> 4, d2 = i2 & 15;
                dst[w * 40 + d2 * 2]     = f2tf32(vb[j].x);
                dst[w * 40 + d2 * 2 + 1] = f2tf32(vb[j].y);
            }
            __syncthreads();
        }
    }

    #pragma unroll
    for (int nt = 0; nt < 4; nt++) {
        int r = q0 + rb + g;
        int col = n * HD + nt * 8 + tq * 2;
        uint32_t hi, lo;
        split2(oacc[nt][0], oacc[nt][1], hi, lo);
        *(uint32_t*)(attnh + ((size_t)(b * NQ) + r) * CC + col) = hi;
        *(uint32_t*)(attnl + ((size_t)(b * NQ) + r) * CC + col) = lo;
        split2(oacc[nt][2], oacc[nt][3], hi, lo);
        *(uint32_t*)(attnh + ((size_t)(b * NQ) + r + 8) * CC + col) = hi;
        *(uint32_t*)(attnl + ((size_t)(b * NQ) + r + 8) * CC + col) = lo;
    }
}

// ------------------------- residual + layernorm --------------------------------
__global__ __launch_bounds__(256) void add_ln(
    const float* __restrict__ A, const float* __restrict__ B,
    const float* __restrict__ gg, const float* __restrict__ be,
    float* __restrict__ out,
    __nv_bfloat16* __restrict__ oh, __nv_bfloat16* __restrict__ ol,
    int transpose_out)
{
    __shared__ float tile[256 * 33];
    int row0 = blockIdx.x * 32;
    int b = row0 / NQ;
    int qg0 = row0 % NQ;
    int tid = threadIdx.x, warp = tid >> 5, lane = tid & 31;

    float4 g0 = *(const float4*)(gg + lane * 4);
    float4 g1 = *(const float4*)(gg + 128 + lane * 4);
    float4 e0 = *(const float4*)(be + lane * 4);
    float4 e1 = *(const float4*)(be + 128 + lane * 4);

    #pragma unroll
    for (int rr = 0; rr < 4; rr++) {
        int rloc = warp * 4 + rr;
        size_t base = (size_t)(row0 + rloc) * CC;
        float4 a0 = *(const float4*)(A + base + lane * 4);
        float4 b0 = *(const float4*)(B + base + lane * 4);
        float4 a1 = *(const float4*)(A + base + 128 + lane * 4);
        float4 b1 = *(const float4*)(B + base + 128 + lane * 4);
        float v0x = a0.x + b0.x, v0y = a0.y + b0.y, v0z = a0.z + b0.z, v0w = a0.w + b0.w;
        float v1x = a1.x + b1.x, v1y = a1.y + b1.y, v1z = a1.z + b1.z, v1w = a1.w + b1.w;
        float s  = v0x + v0y + v0z + v0w + v1x + v1y + v1z + v1w;
        float s2 = v0x*v0x + v0y*v0y + v0z*v0z + v0w*v0w
                 + v1x*v1x + v1y*v1y + v1z*v1z + v1w*v1w;
        #pragma unroll
        for (int o = 16; o; o >>= 1) {
            s  += __shfl_xor_sync(0xffffffffu, s,  o);
            s2 += __shfl_xor_sync(0xffffffffu, s2, o);
        }
        float mean = s * (1.0f / CC);
        float var = s2 * (1.0f / CC) - mean * mean;
        float rstd = rsqrtf(var + 1e-5f);
        float r0x = (v0x - mean) * rstd * g0.x + e0.x;
        float r0y = (v0y - mean) * rstd * g0.y + e0.y;
        float r0z = (v0z - mean) * rstd * g0.z + e0.z;
        float r0w = (v0w - mean) * rstd * g0.w + e0.w;
        float r1x = (v1x - mean) * rstd * g1.x + e1.x;
        float r1y = (v1y - mean) * rstd * g1.y + e1.y;
        float r1z = (v1z - mean) * rstd * g1.z + e1.z;
        float r1w = (v1w - mean) * rstd * g1.w + e1.w;
        if (!transpose_out) {
            *(float4*)(out + base + lane * 4) = make_float4(r0x, r0y, r0z, r0w);
            *(float4*)(out + base + 128 + lane * 4) = make_float4(r1x, r1y, r1z, r1w);
            if (oh) {
                uint32_t h0, l0, h1, l1;
                split2(r0x, r0y, h0, l0); split2(r0z, r0w, h1, l1);
                ((uint32_t*)(oh + base + lane * 4))[0] = h0;
                ((uint32_t*)(oh + base + lane * 4))[1] = h1;
                ((uint32_t*)(ol + base + lane * 4))[0] = l0;
                ((uint32_t*)(ol + base + lane * 4))[1] = l1;
                split2(r1x, r1y, h0, l0); split2(r1z, r1w, h1, l1);
                ((uint32_t*)(oh + base + 128 + lane * 4))[0] = h0;
                ((uint32_t*)(oh + base + 128 + lane * 4))[1] = h1;
                ((uint32_t*)(ol + base + 128 + lane * 4))[0] = l0;
                ((uint32_t*)(ol + base + 128 + lane * 4))[1] = l1;
            }
        } else {
            int c = lane * 4;
            tile[(c + 0) * 33 + rloc] = r0x;
            tile[(c + 1) * 33 + rloc] = r0y;
            tile[(c + 2) * 33 + rloc] = r0z;
            tile[(c + 3) * 33 + rloc] = r0w;
            tile[(c + 128) * 33 + rloc] = r1x;
            tile[(c + 129) * 33 + rloc] = r1y;
            tile[(c + 130) * 33 + rloc] = r1z;
            tile[(c + 131) * 33 + rloc] = r1w;
        }
    }
    if (transpose_out) {
        __syncthreads();
        int qv = tid & 31;
        int cb = tid >> 5;
        #pragma unroll 8
        for (int k = 0; k < 32; k++) {
            int c = cb + k * 8;
            out[((size_t)(b * CC + c)) * NQ + qg0 + qv] = tile[c * 33 + qv];
        }
    }
}

// ------------------------- launch ----------------------------------------------
extern "C" void kernel_launch(void* const* d_in, const int* in_sizes, int n_in,
                              void* d_out, int out_size)
{
    const float* src   = (const float*)d_in[0];
    const unsigned char* pm = (const unsigned char*)d_in[1];
    const float* pr    = (const float*)d_in[2];
    const float* pc    = (const float*)d_in[3];
    const float* w_q_row = (const float*)d_in[4];
    const float* b_q_row = (const float*)d_in[5];
    const float* w_q_col = (const float*)d_in[6];
    const float* b_q_col = (const float*)d_in[7];
    const float* w_k_row = (const float*)d_in[8];
    const float* b_k_row = (const float*)d_in[9];
    const float* w_k_col = (const float*)d_in[10];
    const float* b_k_col = (const float*)d_in[11];
    const float* w_v   = (const float*)d_in[12];
    const float* b_v   = (const float*)d_in[13];
    const float* w_out = (const float*)d_in[14];
    const float* b_out = (const float*)d_in[15];
    const float* n1g   = (const float*)d_in[16];
    const float* n1b   = (const float*)d_in[17];
    const float* l1w   = (const float*)d_in[18];
    const float* l1b   = (const float*)d_in[19];
    const float* l2w   = (const float*)d_in[20];
    const float* l2b   = (const float*)d_in[21];
    const float* n2g   = (const float*)d_in[22];
    const float* n2b   = (const float*)d_in[23];
    float* out = (float*)d_out;

    float* F = nullptr;
    __nv_bfloat16* Hh = nullptr;
    cudaGetSymbolAddress((void**)&F, g_f);
    cudaGetSymbolAddress((void**)&Hh, g_h);

    cudaFuncSetAttribute(gemm_bf16, cudaFuncAttributeMaxDynamicSharedMemorySize, 61440);

    {
        WJobs w;
        const float* ss[8] = {w_q_row, w_q_col, w_k_row, w_k_col, w_v, w_out, l1w, l2w};
        size_t ho[8] = {H_WQRH, H_WQCH, H_WKRH, H_WKCH, H_WVH, H_WOH, H_L1H, H_L2H};
        size_t lo_[8] = {H_WQRL, H_WQCL, H_WKRL, H_WKCL, H_WVL, H_WOL, H_L1L, H_L2L};
        int nn[8] = {CC*CC, CC*CC, CC*CC, CC*CC, CC*CC, CC*CC, DFFN*CC, CC*DFFN};
        for (int i = 0; i < 8; i++) {
            w.s[i] = ss[i]; w.h[i] = Hh + ho[i]; w.l[i] = Hh + lo_[i]; w.n[i] = nn[i];
        }
        convert_w<<<dim3(DFFN * CC / 1024, 8), 256>>>(w);
    }

    prep_kernel<<<dim3(NQ / 64, CC / 64, BZV), 256>>>(
        src, pr, pc, F + F_X,
        Hh + H_XH, Hh + H_XL, Hh + H_XPRH, Hh + H_XPRL, Hh + H_XPCH, Hh + H_XPCL);

    pool_kernel<<<BZV * LL * CC / 256, 256>>>(
        F + F_X, pr, pc, Hh + H_PRH, Hh + H_PRL, Hh + H_PCH, Hh + H_PCL);

    {
        GemmArgs a;
        a.j[0] = {Hh+H_XPRH, Hh+H_XPRL, Hh+H_WQRH, Hh+H_WQRL, b_q_row, F+F_QROW, nullptr, nullptr, SCALE, 0};
        a.j[1] = {Hh+H_XPCH, Hh+H_XPCL, Hh+H_WQCH, Hh+H_WQCL, b_q_col, F+F_QCOL, nullptr, nullptr, SCALE, 0};
        a.j[2] = {Hh+H_XH,   Hh+H_XL,   Hh+H_WVH,  Hh+H_WVL,  b_v,     F+F_V,    nullptr, nullptr, 1.0f, 0};
        gemm_bf16<<<dim3(CC/64, MQ/128, 3), 256, 61440>>>(a, MQ, CC, CC);
    }
    {
        GemmArgs a;
        a.j[0] = {Hh+H_PRH, Hh+H_PRL, Hh+H_WKRH, Hh+H_WKRL, b_k_row, F+F_KROW, nullptr, nullptr, 1.0f, 0};
        a.j[1] = {Hh+H_PCH, Hh+H_PCL, Hh+H_WKCH, Hh+H_WKCL, b_k_col, F+F_KCOL, nullptr, nullptr, 1.0f, 0};
        a.j[2] = a.j[0];
        gemm_bf16<<<dim3(CC/64, 1, 2), 256, 61440>>>(a, BZV*LL, CC, CC);
    }

    scores_tc<<<dim3(NQ/64, NH, 4), 128>>>(
        F+F_QROW, F+F_QCOL, F+F_KROW, F+F_KCOL, pm, F+F_AWROW, F+F_AWCOL);

    combine_tc<<<dim3(NQ/64, NH, BZV), 128>>>(
        F+F_AWROW, F+F_AWCOL, F+F_V, Hh+H_ATTNH, Hh+H_ATTNL);

    {
        GemmArgs a;
        a.j[0] = {Hh+H_ATTNH, Hh+H_ATTNL, Hh+H_WOH, Hh+H_WOL, b_out, F+F_ATTNOUT, nullptr, nullptr, 1.0f, 0};
        a.j[1] = a.j[0]; a.j[2] = a.j[0];
        gemm_bf16<<<dim3(CC/64, MQ/128, 1), 256, 61440>>>(a, MQ, CC, CC);
    }
    add_ln<<<MQ/32, 256>>>(F+F_X, F+F_ATTNOUT, n1g, n1b, F+F_X1,
                           Hh+H_X1H, Hh+H_X1L, 0);
    {
        GemmArgs a;
        a.j[0] = {Hh+H_X1H, Hh+H_X1L, Hh+H_L1H, Hh+H_L1L, l1b, nullptr, Hh+H_FFNH, Hh+H_FFNL, 1.0f, 1};
        a.j[1] = a.j[0]; a.j[2] = a.j[0];
        gemm_bf16<<<dim3(DFFN/64, MQ/128, 1), 256, 61440>>>(a, MQ, DFFN, CC);
    }
    {
        GemmArgs a;
        a.j[0] = {Hh+H_FFNH, Hh+H_FFNL, Hh+H_L2H, Hh+H_L2L, l2b, F+F_Y, nullptr, nullptr, 1.0f, 0};
        a.j[1] = a.j[0]; a.j[2] = a.j[0];
        gemm_bf16<<<dim3(CC/64, MQ/128, 1), 256, 61440>>>(a, MQ, CC, DFFN);
    }
    add_ln<<<MQ/32, 256>>>(F+F_X1, F+F_Y, n2g, n2b, out, nullptr, nullptr, 1);
}

// round 6
// speedup vs baseline: 3.1791x; 1.1533x over previous
#include <cuda_runtime.h>
#include <cuda_bf16.h>
#include <cstdint>
#include <cstddef>

#define NQ    3136
#define CC    256
#define BZV   2
#define NH    8
#define HD    32
#define LL    56
#define DFFN  1024
#define MQ    (BZV*NQ)
#define SCALE 0.17677669529663687f
#define NEGF  (-3.402823466e38f)

// ------------------------- scratch -------------------------------------------
#define SZ_BQC (MQ*CC)
#define SZ_KP  (BZV*LL*CC)
#define SZ_AW  (BZV*NH*NQ*LL)
#define SZ_FFN (MQ*DFFN)

#define F_X       ((size_t)0)
#define F_XPR     (F_X    + SZ_BQC)
#define F_XPC     (F_XPR  + SZ_BQC)
#define F_QROW    (F_XPC  + SZ_BQC)
#define F_QCOL    (F_QROW + SZ_BQC)
#define F_V       (F_QCOL + SZ_BQC)
#define F_ATTN    (F_V    + SZ_BQC)
#define F_ATTNOUT (F_ATTN + SZ_BQC)
#define F_X1      (F_ATTNOUT + SZ_BQC)
#define F_Y       (F_X1   + SZ_BQC)
#define F_FFN     (F_Y    + SZ_BQC)
#define F_PR      (F_FFN  + SZ_FFN)
#define F_PC      (F_PR   + SZ_KP)
#define F_KROW    (F_PC   + SZ_KP)
#define F_KCOL    (F_KROW + SZ_KP)
#define F_AWROW   (F_KCOL + SZ_KP)
#define F_AWCOL   (F_AWROW + SZ_AW)
#define F_TOTAL   (F_AWCOL + SZ_AW)
__device__ float g_f[F_TOTAL];

// ------------------------- helpers -------------------------------------------
__device__ __forceinline__ uint32_t f2tf32(float x) {
    uint32_t r; asm("cvt.rna.tf32.f32 %0, %1;" : "=r"(r) : "f"(x)); return r;
}
__device__ __forceinline__ void mma_tf32(float (&c)[4], const uint32_t (&a)[4],
                                         const uint32_t (&b)[2]) {
    asm volatile("mma.sync.aligned.m16n8k8.row.col.f32.tf32.tf32.f32 "
        "{%0,%1,%2,%3},{%4,%5,%6,%7},{%8,%9},{%0,%1,%2,%3};"
        : "+f"(c[0]), "+f"(c[1]), "+f"(c[2]), "+f"(c[3])
        : "r"(a[0]), "r"(a[1]), "r"(a[2]), "r"(a[3]), "r"(b[0]), "r"(b[1]));
}

// ------------------------- prep ------------------------------------------------
__global__ __launch_bounds__(256) void prep_kernel(
    const float* __restrict__ src, const float* __restrict__ pr,
    const float* __restrict__ pc, float* __restrict__ x,
    float* __restrict__ xpr, float* __restrict__ xpc)
{
    __shared__ float tile[64 * 65];
    int b = blockIdx.z;
    int q0 = blockIdx.x * 64, c0 = blockIdx.y * 64;
    int tid = threadIdx.x;

    int cl_ = tid >> 2, qs = (tid & 3) * 16;
    const float* sp = src + ((size_t)(b * CC + c0 + cl_)) * NQ + q0 + qs;
    #pragma unroll
    for (int j = 0; j < 4; j++) {
        float4 vv = *(const float4*)(sp + j * 4);
        tile[cl_ * 65 + qs + j * 4 + 0] = vv.x;
        tile[cl_ * 65 + qs + j * 4 + 1] = vv.y;
        tile[cl_ * 65 + qs + j * 4 + 2] = vv.z;
        tile[cl_ * 65 + qs + j * 4 + 3] = vv.w;
    }
    __syncthreads();

    int ql = tid >> 2, cs = (tid & 3) * 16;
    int q = q0 + ql;
    int irow = q / LL, jcol = q % LL;
    const float* prp = pr + (size_t)(b * LL + jcol) * CC + c0 + cs;
    const float* pcp = pc + (size_t)(b * LL + irow) * CC + c0 + cs;
    size_t ob = ((size_t)(b * NQ + q)) * CC + c0 + cs;
    #pragma unroll
    for (int j = 0; j < 4; j++) {
        float v0 = tile[(cs + j * 4 + 0) * 65 + ql];
        float v1 = tile[(cs + j * 4 + 1) * 65 + ql];
        float v2 = tile[(cs + j * 4 + 2) * 65 + ql];
        float v3 = tile[(cs + j * 4 + 3) * 65 + ql];
        float4 p4 = *(const float4*)(prp + j * 4);
        float4 c4 = *(const float4*)(pcp + j * 4);
        *(float4*)(x + ob + j * 4) = make_float4(v0, v1, v2, v3);
        *(float4*)(xpr + ob + j * 4) = make_float4(v0 + p4.x, v1 + p4.y, v2 + p4.z, v3 + p4.w);
        *(float4*)(xpc + ob + j * 4) = make_float4(v0 + c4.x, v1 + c4.y, v2 + c4.z, v3 + c4.w);
    }
}

// ------------------------- pooling ---------------------------------------------
__global__ __launch_bounds__(256) void pool_kernel(
    const float* __restrict__ x, const float* __restrict__ pr,
    const float* __restrict__ pc,
    float* __restrict__ pooled_r, float* __restrict__ pooled_c)
{
    int idx = blockIdx.x * 256 + threadIdx.x;
    int c = idx & 255;
    int t = idx >> 8;
    int rc = t % LL;
    int b = t / LL;
    float sr = 0.f, sc = 0.f;
    #pragma unroll 8
    for (int i = 0; i < LL; i++) {
        sr += x[((size_t)(b * NQ) + i * LL + rc) * CC + c];
        sc += x[((size_t)(b * NQ) + rc * LL + i) * CC + c];
    }
    pooled_r[idx] = sr * (1.0f / LL) + pr[idx];
    pooled_c[idx] = sc * (1.0f / LL) + pc[idx];
}

// ------------------------- tf32 GEMM (templated tiles, batched) -----------------
struct GemmJob {
    const float* A;    // [M,K]
    const float* B;    // [N,K]
    const float* bias;
    float* C;          // [M,N]
    float alpha;
    int relu;
};
struct GemmArgs { GemmJob j[3]; };

// BM x BN block, 8 warps of WM x WN, K-tile 16, double-buffered.
template<int BM, int BN, int WM, int WN>
__global__ __launch_bounds__(256, 2) void gemm_tf32(GemmArgs args, int M, int N, int K)
{
    constexpr int MT = WM / 16, NT = WN / 8;
    constexpr int SA = BM * 20, SB = BN * 20, STG = SA + SB;
    constexpr int AU = BM / 64;   // uint4 loads per thread for A
    constexpr int BU = BN / 64;
    __shared__ uint32_t sm[2 * STG];

    const GemmJob jb = args.j[blockIdx.z];
    int bm = blockIdx.y * BM, bn = blockIdx.x * BN;
    int tid = threadIdx.x, warp = tid >> 5, lane = tid & 31;
    constexpr int WARPS_M = BM / WM;
    int wm = warp % WARPS_M, wn = warp / WARPS_M;
    int g = lane >> 2, tq = lane & 3;
    int R0 = wm * WM, N0 = wn * WN;

    float acc[MT][NT][4];
    #pragma unroll
    for (int mt = 0; mt < MT; mt++)
        #pragma unroll
        for (int nt = 0; nt < NT; nt++)
            #pragma unroll
            for (int i = 0; i < 4; i++) acc[mt][nt][i] = 0.f;

    int KT = K >> 4;
    float4 rA[AU], rB[BU];
    int arow[AU], akq[AU], brow[BU], bkq[BU];
    #pragma unroll
    for (int i = 0; i < AU; i++) {
        int idx = tid + i * 256;
        arow[i] = idx >> 2; akq[i] = (idx & 3) * 4;
    }
    #pragma unroll
    for (int i = 0; i < BU; i++) {
        int idx = tid + i * 256;
        brow[i] = idx >> 2; bkq[i] = (idx & 3) * 4;
    }

    // prologue: load tile 0
    #pragma unroll
    for (int i = 0; i < AU; i++) {
        rA[i] = make_float4(0.f, 0.f, 0.f, 0.f);
        if (bm + arow[i] < M)
            rA[i] = *(const float4*)(jb.A + (size_t)(bm + arow[i]) * K + akq[i]);
    }
    #pragma unroll
    for (int i = 0; i < BU; i++)
        rB[i] = *(const float4*)(jb.B + (size_t)(bn + brow[i]) * K + bkq[i]);
    #pragma unroll
    for (int i = 0; i < AU; i++) {
        uint32_t* d = sm + arow[i] * 20 + akq[i];
        d[0] = f2tf32(rA[i].x); d[1] = f2tf32(rA[i].y);
        d[2] = f2tf32(rA[i].z); d[3] = f2tf32(rA[i].w);
    }
    #pragma unroll
    for (int i = 0; i < BU; i++) {
        uint32_t* d = sm + SA + brow[i] * 20 + bkq[i];
        d[0] = f2tf32(rB[i].x); d[1] = f2tf32(rB[i].y);
        d[2] = f2tf32(rB[i].z); d[3] = f2tf32(rB[i].w);
    }
    __syncthreads();

    for (int kt = 0; kt < KT; kt++) {
        int s = kt & 1;
        if (kt + 1 < KT) {
            int k0 = (kt + 1) * 16;
            #pragma unroll
            for (int i = 0; i < AU; i++)
                if (bm + arow[i] < M)
                    rA[i] = *(const float4*)(jb.A + (size_t)(bm + arow[i]) * K + k0 + akq[i]);
            #pragma unroll
            for (int i = 0; i < BU; i++)
                rB[i] = *(const float4*)(jb.B + (size_t)(bn + brow[i]) * K + k0 + bkq[i]);
        }
        const uint32_t* sA = sm + s * STG;
        const uint32_t* sB = sA + SA;
        #pragma unroll
        for (int ks = 0; ks < 2; ks++) {
            int ko = ks * 8;
            uint32_t aF[MT][4], bF[NT][2];
            #pragma unroll
            for (int mt = 0; mt < MT; mt++) {
                int r = R0 + mt * 16 + g;
                aF[mt][0] = sA[r * 20 + ko + tq];
                aF[mt][1] = sA[(r + 8) * 20 + ko + tq];
                aF[mt][2] = sA[r * 20 + ko + tq + 4];
                aF[mt][3] = sA[(r + 8) * 20 + ko + tq + 4];
            }
            #pragma unroll
            for (int nt = 0; nt < NT; nt++) {
                int rn = N0 + nt * 8 + g;
                bF[nt][0] = sB[rn * 20 + ko + tq];
                bF[nt][1] = sB[rn * 20 + ko + tq + 4];
            }
            #pragma unroll
            for (int mt = 0; mt < MT; mt++)
                #pragma unroll
                for (int nt = 0; nt < NT; nt++)
                    mma_tf32(acc[mt][nt], aF[mt], bF[nt]);
        }
        if (kt + 1 < KT) {
            uint32_t* dA = sm + (s ^ 1) * STG;
            uint32_t* dB = dA + SA;
            #pragma unroll
            for (int i = 0; i < AU; i++) {
                uint32_t* d = dA + arow[i] * 20 + akq[i];
                d[0] = f2tf32(rA[i].x); d[1] = f2tf32(rA[i].y);
                d[2] = f2tf32(rA[i].z); d[3] = f2tf32(rA[i].w);
            }
            #pragma unroll
            for (int i = 0; i < BU; i++) {
                uint32_t* d = dB + brow[i] * 20 + bkq[i];
                d[0] = f2tf32(rB[i].x); d[1] = f2tf32(rB[i].y);
                d[2] = f2tf32(rB[i].z); d[3] = f2tf32(rB[i].w);
            }
            __syncthreads();
        }
    }

    #pragma unroll
    for (int mt = 0; mt < MT; mt++)
        #pragma unroll
        for (int nt = 0; nt < NT; nt++) {
            int r = bm + R0 + mt * 16 + g;
            int cn = bn + N0 + nt * 8 + tq * 2;
            float b0 = jb.bias[cn], b1 = jb.bias[cn + 1];
            float o0 = (acc[mt][nt][0] + b0) * jb.alpha;
            float o1 = (acc[mt][nt][1] + b1) * jb.alpha;
            float o2 = (acc[mt][nt][2] + b0) * jb.alpha;
            float o3 = (acc[mt][nt][3] + b1) * jb.alpha;
            if (jb.relu) {
                o0 = fmaxf(o0, 0.f); o1 = fmaxf(o1, 0.f);
                o2 = fmaxf(o2, 0.f); o3 = fmaxf(o3, 0.f);
            }
            if (r < M)
                *(float2*)(jb.C + (size_t)r * N + cn) = make_float2(o0, o1);
            if (r + 8 < M)
                *(float2*)(jb.C + (size_t)(r + 8) * N + cn) = make_float2(o2, o3);
        }
}

// ------------------------- scores (tf32) ----------------------------------------
__global__ __launch_bounds__(128) void scores_tc(
    const float* __restrict__ qr, const float* __restrict__ qc,
    const float* __restrict__ kr, const float* __restrict__ kc,
    const unsigned char* __restrict__ mask,
    float* __restrict__ awr, float* __restrict__ awc)
{
    __shared__ uint32_t Qs[64 * 36];
    __shared__ uint32_t Ks[32 * 72];
    __shared__ unsigned char Ms[LL];
    int z = blockIdx.z;
    int b = z & 1, which = z >> 1;
    const float* q  = which ? qc : qr;
    const float* kk = which ? kc : kr;
    float* aw       = which ? awc : awr;
    int mstride     = which ? LL : 1;
    int n = blockIdx.y, q0 = blockIdx.x * 64;
    int tid = threadIdx.x, warp = tid >> 5, lane = tid & 31;
    int g = lane >> 2, tq = lane & 3;

    {
        int rq = tid >> 1, hf = (tid & 1) * 16;
        const float* qp = q + ((size_t)(b * NQ + q0 + rq)) * CC + n * HD + hf;
        #pragma unroll
        for (int j = 0; j < 4; j++) {
            float4 v = *(const float4*)(qp + j * 4);
            Qs[rq * 36 + hf + j * 4 + 0] = f2tf32(v.x);
            Qs[rq * 36 + hf + j * 4 + 1] = f2tf32(v.y);
            Qs[rq * 36 + hf + j * 4 + 2] = f2tf32(v.z);
            Qs[rq * 36 + hf + j * 4 + 3] = f2tf32(v.w);
        }
    }
    for (int i = tid; i < LL * HD; i += 128) {
        int l = i >> 5, d = i & 31;
        Ks[d * 72 + l] = f2tf32(kk[((size_t)(b * LL + l)) * CC + n * HD + d]);
    }
    if (tid < LL) Ms[tid] = mask[b * NQ + tid * mstride];
    __syncthreads();

    uint32_t a[4][4];
    int rb = warp * 16;
    #pragma unroll
    for (int ks = 0; ks < 4; ks++) {
        a[ks][0] = Qs[(rb + g) * 36 + ks * 8 + tq];
        a[ks][1] = Qs[(rb + g + 8) * 36 + ks * 8 + tq];
        a[ks][2] = Qs[(rb + g) * 36 + ks * 8 + tq + 4];
        a[ks][3] = Qs[(rb + g + 8) * 36 + ks * 8 + tq + 4];
    }
    float c[7][4];
    #pragma unroll
    for (int nt = 0; nt < 7; nt++)
        #pragma unroll
        for (int i = 0; i < 4; i++) c[nt][i] = 0.f;
    #pragma unroll
    for (int nt = 0; nt < 7; nt++)
        #pragma unroll
        for (int ks = 0; ks < 4; ks++) {
            uint32_t bf[2] = { Ks[(ks * 8 + tq) * 72 + nt * 8 + g],
                               Ks[(ks * 8 + tq + 4) * 72 + nt * 8 + g] };
            mma_tf32(c[nt], a[ks], bf);
        }

    float m0 = -3.0e38f, m1 = -3.0e38f;
    #pragma unroll
    for (int nt = 0; nt < 7; nt++) {
        int col = nt * 8 + tq * 2;
        if (Ms[col])     { c[nt][0] = NEGF; c[nt][2] = NEGF; }
        if (Ms[col + 1]) { c[nt][1] = NEGF; c[nt][3] = NEGF; }
        m0 = fmaxf(m0, fmaxf(c[nt][0], c[nt][1]));
        m1 = fmaxf(m1, fmaxf(c[nt][2], c[nt][3]));
    }
    #pragma unroll
    for (int o = 1; o <= 2; o <<= 1) {
        m0 = fmaxf(m0, __shfl_xor_sync(0xffffffffu, m0, o));
        m1 = fmaxf(m1, __shfl_xor_sync(0xffffffffu, m1, o));
    }
    float s0 = 0.f, s1 = 0.f;
    #pragma unroll
    for (int nt = 0; nt < 7; nt++) {
        c[nt][0] = __expf(c[nt][0] - m0);
        c[nt][1] = __expf(c[nt][1] - m0);
        c[nt][2] = __expf(c[nt][2] - m1);
        c[nt][3] = __expf(c[nt][3] - m1);
        s0 += c[nt][0] + c[nt][1];
        s1 += c[nt][2] + c[nt][3];
    }
    #pragma unroll
    for (int o = 1; o <= 2; o <<= 1) {
        s0 += __shfl_xor_sync(0xffffffffu, s0, o);
        s1 += __shfl_xor_sync(0xffffffffu, s1, o);
    }
    float i0 = 1.0f / s0, i1 = 1.0f / s1;
    float* d0 = aw + ((size_t)((b * NH + n)) * NQ + q0 + rb + g) * LL + tq * 2;
    float* d1 = aw + ((size_t)((b * NH + n)) * NQ + q0 + rb + g + 8) * LL + tq * 2;
    #pragma unroll
    for (int nt = 0; nt < 7; nt++) {
        *(float2*)(d0 + nt * 8) = make_float2(c[nt][0] * i0, c[nt][1] * i0);
        *(float2*)(d1 + nt * 8) = make_float2(c[nt][2] * i1, c[nt][3] * i1);
    }
}

// ------------------------- RCDA recombination (tf32) ----------------------------
__global__ __launch_bounds__(128) void combine_tc(
    const float* __restrict__ awr, const float* __restrict__ awc,
    const float* __restrict__ v, float* __restrict__ attn)
{
    __shared__ float    ACs[64 * 57];
    __shared__ uint32_t ub[2 * 56 * 40];

    int b = blockIdx.z, n = blockIdx.y, q0 = blockIdx.x * 64;
    int tid = threadIdx.x, warp = tid >> 5, lane = tid & 31;
    int g = lane >> 2, tq = lane & 3;
    int rb = warp * 16;

    const float* arg = awr + ((size_t)((b * NH + n)) * NQ + q0) * LL;
    const float* acg = awc + ((size_t)((b * NH + n)) * NQ + q0) * LL;
    for (int i = tid; i < 64 * LL; i += 128) {
        int qi = i / LL, k = i % LL;
        ub[qi * 60 + k] = f2tf32(arg[i]);
        ACs[qi * 57 + k] = acg[i];
    }
    __syncthreads();

    uint32_t af[7][4];
    #pragma unroll
    for (int ks = 0; ks < 7; ks++) {
        af[ks][0] = ub[(rb + g) * 60 + ks * 8 + tq];
        af[ks][1] = ub[(rb + g + 8) * 60 + ks * 8 + tq];
        af[ks][2] = ub[(rb + g) * 60 + ks * 8 + tq + 4];
        af[ks][3] = ub[(rb + g + 8) * 60 + ks * 8 + tq + 4];
    }
    __syncthreads();

    float2 vb[7];
    {
        const float* vg = v + ((size_t)(b * NQ)) * CC + n * HD;
        #pragma unroll
        for (int j = 0; j < 7; j++) {
            int i2 = tid + j * 128;
            int w = i2 >> 4, d2 = i2 & 15;
            vb[j] = *(const float2*)(vg + (size_t)w * CC + d2 * 2);
        }
        #pragma unroll
        for (int j = 0; j < 7; j++) {
            int i2 = tid + j * 128;
            int w = i2 >> 4, d2 = i2 & 15;
            ub[w * 40 + d2 * 2]     = f2tf32(vb[j].x);
            ub[w * 40 + d2 * 2 + 1] = f2tf32(vb[j].y);
        }
    }
    __syncthreads();

    float oacc[4][4];
    #pragma unroll
    for (int nt = 0; nt < 4; nt++)
        #pragma unroll
        for (int i = 0; i < 4; i++) oacc[nt][i] = 0.f;

    for (int h = 0; h < LL; h++) {
        int s = h & 1;
        if (h + 1 < LL) {
            const float* vg = v + ((size_t)(b * NQ) + (h + 1) * LL) * CC + n * HD;
            #pragma unroll
            for (int j = 0; j < 7; j++) {
                int i2 = tid + j * 128;
                int w = i2 >> 4, d2 = i2 & 15;
                vb[j] = *(const float2*)(vg + (size_t)w * CC + d2 * 2);
            }
        }
        float p[4][4];
        #pragma unroll
        for (int nt = 0; nt < 4; nt++)
            #pragma unroll
            for (int i = 0; i < 4; i++) p[nt][i] = 0.f;

        const uint32_t* Vst = ub + s * 2240;
        #pragma unroll
        for (int ks = 0; ks < 7; ks++)
            #pragma unroll
            for (int nt = 0; nt < 4; nt++) {
                uint32_t bf[2] = { Vst[(ks * 8 + tq) * 40 + nt * 8 + g],
                                   Vst[(ks * 8 + tq + 4) * 40 + nt * 8 + g] };
                mma_tf32(p[nt], af[ks], bf);
            }

        float ac0 = ACs[(rb + g) * 57 + h];
        float ac1 = ACs[(rb + g + 8) * 57 + h];
        #pragma unroll
        for (int nt = 0; nt < 4; nt++) {
            oacc[nt][0] += ac0 * p[nt][0];
            oacc[nt][1] += ac0 * p[nt][1];
            oacc[nt][2] += ac1 * p[nt][2];
            oacc[nt][3] += ac1 * p[nt][3];
        }
        if (h + 1 < LL) {
            uint32_t* dst = ub + (s ^ 1) * 2240;
            #pragma unroll
            for (int j = 0; j < 7; j++) {
                int i2 = tid + j * 128;
                int w = i2 >> 4, d2 = i2 & 15;
                dst[w * 40 + d2 * 2]     = f2tf32(vb[j].x);
                dst[w * 40 + d2 * 2 + 1] = f2tf32(vb[j].y);
            }
            __syncthreads();
        }
    }

    #pragma unroll
    for (int nt = 0; nt < 4; nt++) {
        int r = q0 + rb + g;
        int col = n * HD + nt * 8 + tq * 2;
        *(float2*)(attn + ((size_t)(b * NQ) + r) * CC + col)
            = make_float2(oacc[nt][0], oacc[nt][1]);
        *(float2*)(attn + ((size_t)(b * NQ) + r + 8) * CC + col)
            = make_float2(oacc[nt][2], oacc[nt][3]);
    }
}

// ------------------------- residual + layernorm --------------------------------
__global__ __launch_bounds__(256) void add_ln(
    const float* __restrict__ A, const float* __restrict__ B,
    const float* __restrict__ gg, const float* __restrict__ be,
    float* __restrict__ out, int transpose_out)
{
    __shared__ float tile[256 * 33];
    int row0 = blockIdx.x * 32;
    int b = row0 / NQ;
    int qg0 = row0 % NQ;
    int tid = threadIdx.x, warp = tid >> 5, lane = tid & 31;

    float4 g0 = *(const float4*)(gg + lane * 4);
    float4 g1 = *(const float4*)(gg + 128 + lane * 4);
    float4 e0 = *(const float4*)(be + lane * 4);
    float4 e1 = *(const float4*)(be + 128 + lane * 4);

    #pragma unroll
    for (int rr = 0; rr < 4; rr++) {
        int rloc = warp * 4 + rr;
        size_t base = (size_t)(row0 + rloc) * CC;
        float4 a0 = *(const float4*)(A + base + lane * 4);
        float4 b0 = *(const float4*)(B + base + lane * 4);
        float4 a1 = *(const float4*)(A + base + 128 + lane * 4);
        float4 b1 = *(const float4*)(B + base + 128 + lane * 4);
        float v0x = a0.x + b0.x, v0y = a0.y + b0.y, v0z = a0.z + b0.z, v0w = a0.w + b0.w;
        float v1x = a1.x + b1.x, v1y = a1.y + b1.y, v1z = a1.z + b1.z, v1w = a1.w + b1.w;
        float s  = v0x + v0y + v0z + v0w + v1x + v1y + v1z + v1w;
        float s2 = v0x*v0x + v0y*v0y + v0z*v0z + v0w*v0w
                 + v1x*v1x + v1y*v1y + v1z*v1z + v1w*v1w;
        #pragma unroll
        for (int o = 16; o; o >>= 1) {
            s  += __shfl_xor_sync(0xffffffffu, s,  o);
            s2 += __shfl_xor_sync(0xffffffffu, s2, o);
        }
        float mean = s * (1.0f / CC);
        float var = s2 * (1.0f / CC) - mean * mean;
        float rstd = rsqrtf(var + 1e-5f);
        float r0x = (v0x - mean) * rstd * g0.x + e0.x;
        float r0y = (v0y - mean) * rstd * g0.y + e0.y;
        float r0z = (v0z - mean) * rstd * g0.z + e0.z;
        float r0w = (v0w - mean) * rstd * g0.w + e0.w;
        float r1x = (v1x - mean) * rstd * g1.x + e1.x;
        float r1y = (v1y - mean) * rstd * g1.y + e1.y;
        float r1z = (v1z - mean) * rstd * g1.z + e1.z;
        float r1w = (v1w - mean) * rstd * g1.w + e1.w;
        if (!transpose_out) {
            *(float4*)(out + base + lane * 4) = make_float4(r0x, r0y, r0z, r0w);
            *(float4*)(out + base + 128 + lane * 4) = make_float4(r1x, r1y, r1z, r1w);
        } else {
            int c = lane * 4;
            tile[(c + 0) * 33 + rloc] = r0x;
            tile[(c + 1) * 33 + rloc] = r0y;
            tile[(c + 2) * 33 + rloc] = r0z;
            tile[(c + 3) * 33 + rloc] = r0w;
            tile[(c + 128) * 33 + rloc] = r1x;
            tile[(c + 129) * 33 + rloc] = r1y;
            tile[(c + 130) * 33 + rloc] = r1z;
            tile[(c + 131) * 33 + rloc] = r1w;
        }
    }
    if (transpose_out) {
        __syncthreads();
        int qv = tid & 31;
        int cb = tid >> 5;
        #pragma unroll 8
        for (int k = 0; k < 32; k++) {
            int c = cb + k * 8;
            out[((size_t)(b * CC + c)) * NQ + qg0 + qv] = tile[c * 33 + qv];
        }
    }
}

// ------------------------- launch ----------------------------------------------
extern "C" void kernel_launch(void* const* d_in, const int* in_sizes, int n_in,
                              void* d_out, int out_size)
{
    const float* src   = (const float*)d_in[0];
    const unsigned char* pm = (const unsigned char*)d_in[1];
    const float* pr    = (const float*)d_in[2];
    const float* pc    = (const float*)d_in[3];
    const float* w_q_row = (const float*)d_in[4];
    const float* b_q_row = (const float*)d_in[5];
    const float* w_q_col = (const float*)d_in[6];
    const float* b_q_col = (const float*)d_in[7];
    const float* w_k_row = (const float*)d_in[8];
    const float* b_k_row = (const float*)d_in[9];
    const float* w_k_col = (const float*)d_in[10];
    const float* b_k_col = (const float*)d_in[11];
    const float* w_v   = (const float*)d_in[12];
    const float* b_v   = (const float*)d_in[13];
    const float* w_out = (const float*)d_in[14];
    const float* b_out = (const float*)d_in[15];
    const float* n1g   = (const float*)d_in[16];
    const float* n1b   = (const float*)d_in[17];
    const float* l1w   = (const float*)d_in[18];
    const float* l1b   = (const float*)d_in[19];
    const float* l2w   = (const float*)d_in[20];
    const float* l2b   = (const float*)d_in[21];
    const float* n2g   = (const float*)d_in[22];
    const float* n2b   = (const float*)d_in[23];
    float* out = (float*)d_out;

    float* F = nullptr;
    cudaGetSymbolAddress((void**)&F, g_f);

    prep_kernel<<<dim3(NQ / 64, CC / 64, BZV), 256>>>(
        src, pr, pc, F + F_X, F + F_XPR, F + F_XPC);

    pool_kernel<<<BZV * LL * CC / 256, 256>>>(
        F + F_X, pr, pc, F + F_PR, F + F_PC);

    // projections (batched z=3): 128x128 tiles, grid 2*49*3 = 294
    {
        GemmArgs a;
        a.j[0] = {F+F_XPR, w_q_row, b_q_row, F+F_QROW, SCALE, 0};
        a.j[1] = {F+F_XPC, w_q_col, b_q_col, F+F_QCOL, SCALE, 0};
        a.j[2] = {F+F_X,   w_v,     b_v,     F+F_V,    1.0f, 0};
        gemm_tf32<128,128,64,32><<<dim3(CC/128, MQ/128, 3), 256>>>(a, MQ, CC, CC);
    }
    // k projections (z=2, M=112 partial tile)
    {
        GemmArgs a;
        a.j[0] = {F+F_PR, w_k_row, b_k_row, F+F_KROW, 1.0f, 0};
        a.j[1] = {F+F_PC, w_k_col, b_k_col, F+F_KCOL, 1.0f, 0};
        a.j[2] = a.j[0];
        gemm_tf32<128,128,64,32><<<dim3(CC/128, 1, 2), 256>>>(a, BZV*LL, CC, CC);
    }

    scores_tc<<<dim3(NQ/64, NH, 4), 128>>>(
        F+F_QROW, F+F_QCOL, F+F_KROW, F+F_KCOL, pm, F+F_AWROW, F+F_AWCOL);

    combine_tc<<<dim3(NQ/64, NH, BZV), 128>>>(
        F+F_AWROW, F+F_AWCOL, F+F_V, F+F_ATTN);

    // out projection: grid 2*49 = 98
    {
        GemmArgs a;
        a.j[0] = {F+F_ATTN, w_out, b_out, F+F_ATTNOUT, 1.0f, 0};
        a.j[1] = a.j[0]; a.j[2] = a.j[0];
        gemm_tf32<128,128,64,32><<<dim3(CC/128, MQ/128, 1), 256>>>(a, MQ, CC, CC);
    }
    add_ln<<<MQ/32, 256>>>(F+F_X, F+F_ATTNOUT, n1g, n1b, F+F_X1, 0);

    // FFN1 (relu): grid 8*49 = 392
    {
        GemmArgs a;
        a.j[0] = {F+F_X1, l1w, l1b, F+F_FFN, 1.0f, 1};
        a.j[1] = a.j[0]; a.j[2] = a.j[0];
        gemm_tf32<128,128,64,32><<<dim3(DFFN/128, MQ/128, 1), 256>>>(a, MQ, DFFN, CC);
    }
    // FFN2: grid 2*49 = 98
    {
        GemmArgs a;
        a.j[0] = {F+F_FFN, l2w, l2b, F+F_Y, 1.0f, 0};
        a.j[1] = a.j[0]; a.j[2] = a.j[0];
        gemm_tf32<128,128,64,32><<<dim3(CC/128, MQ/128, 1), 256>>>(a, MQ, CC, DFFN);
    }
    add_ln<<<MQ/32, 256>>>(F+F_X1, F+F_Y, n2g, n2b, out, 1);
}

// round 7
// speedup vs baseline: 3.4815x; 1.0951x over previous
#include <cuda_runtime.h>
#include <cstdint>
#include <cstddef>

#define NQ    3136
#define CC    256
#define BZV   2
#define NH    8
#define HD    32
#define LL    56
#define DFFN  1024
#define MQ    (BZV*NQ)
#define SCALE 0.17677669529663687f
#define NEGF  (-3.402823466e38f)

// ------------------------- scratch -------------------------------------------
#define SZ_BQC (MQ*CC)
#define SZ_KP  (BZV*LL*CC)
#define SZ_FFN (MQ*DFFN)

#define F_X       ((size_t)0)
#define F_XPR     (F_X    + SZ_BQC)
#define F_XPC     (F_XPR  + SZ_BQC)
#define F_QROW    (F_XPC  + SZ_BQC)
#define F_QCOL    (F_QROW + SZ_BQC)
#define F_V       (F_QCOL + SZ_BQC)
#define F_ATTN    (F_V    + SZ_BQC)
#define F_ATTNOUT (F_ATTN + SZ_BQC)
#define F_X1      (F_ATTNOUT + SZ_BQC)
#define F_Y       (F_X1   + SZ_BQC)
#define F_FFN     (F_Y    + SZ_BQC)
#define F_PR      (F_FFN  + SZ_FFN)
#define F_PC      (F_PR   + SZ_KP)
#define F_KROW    (F_PC   + SZ_KP)
#define F_KCOL    (F_KROW + SZ_KP)
#define F_TOTAL   (F_KCOL + SZ_KP)
__device__ float g_f[F_TOTAL];

// ------------------------- helpers -------------------------------------------
__device__ __forceinline__ uint32_t f2tf32(float x) {
    uint32_t r; asm("cvt.rna.tf32.f32 %0, %1;" : "=r"(r) : "f"(x)); return r;
}
__device__ __forceinline__ void mma_tf32(float (&c)[4], const uint32_t (&a)[4],
                                         const uint32_t (&b)[2]) {
    asm volatile("mma.sync.aligned.m16n8k8.row.col.f32.tf32.tf32.f32 "
        "{%0,%1,%2,%3},{%4,%5,%6,%7},{%8,%9},{%0,%1,%2,%3};"
        : "+f"(c[0]), "+f"(c[1]), "+f"(c[2]), "+f"(c[3])
        : "r"(a[0]), "r"(a[1]), "r"(a[2]), "r"(a[3]), "r"(b[0]), "r"(b[1]));
}

// ------------------------- prep ------------------------------------------------
__global__ __launch_bounds__(256) void prep_kernel(
    const float* __restrict__ src, const float* __restrict__ pr,
    const float* __restrict__ pc, float* __restrict__ x,
    float* __restrict__ xpr, float* __restrict__ xpc)
{
    __shared__ float tile[64 * 65];
    int b = blockIdx.z;
    int q0 = blockIdx.x * 64, c0 = blockIdx.y * 64;
    int tid = threadIdx.x;

    int cl_ = tid >> 2, qs = (tid & 3) * 16;
    const float* sp = src + ((size_t)(b * CC + c0 + cl_)) * NQ + q0 + qs;
    #pragma unroll
    for (int j = 0; j < 4; j++) {
        float4 vv = *(const float4*)(sp + j * 4);
        tile[cl_ * 65 + qs + j * 4 + 0] = vv.x;
        tile[cl_ * 65 + qs + j * 4 + 1] = vv.y;
        tile[cl_ * 65 + qs + j * 4 + 2] = vv.z;
        tile[cl_ * 65 + qs + j * 4 + 3] = vv.w;
    }
    __syncthreads();

    int ql = tid >> 2, cs = (tid & 3) * 16;
    int q = q0 + ql;
    int irow = q / LL, jcol = q % LL;
    const float* prp = pr + (size_t)(b * LL + jcol) * CC + c0 + cs;
    const float* pcp = pc + (size_t)(b * LL + irow) * CC + c0 + cs;
    size_t ob = ((size_t)(b * NQ + q)) * CC + c0 + cs;
    #pragma unroll
    for (int j = 0; j < 4; j++) {
        float v0 = tile[(cs + j * 4 + 0) * 65 + ql];
        float v1 = tile[(cs + j * 4 + 1) * 65 + ql];
        float v2 = tile[(cs + j * 4 + 2) * 65 + ql];
        float v3 = tile[(cs + j * 4 + 3) * 65 + ql];
        float4 p4 = *(const float4*)(prp + j * 4);
        float4 c4 = *(const float4*)(pcp + j * 4);
        *(float4*)(x + ob + j * 4) = make_float4(v0, v1, v2, v3);
        *(float4*)(xpr + ob + j * 4) = make_float4(v0 + p4.x, v1 + p4.y, v2 + p4.z, v3 + p4.w);
        *(float4*)(xpc + ob + j * 4) = make_float4(v0 + c4.x, v1 + c4.y, v2 + c4.z, v3 + c4.w);
    }
}

// ------------------------- pooling ---------------------------------------------
__global__ __launch_bounds__(256) void pool_kernel(
    const float* __restrict__ x, const float* __restrict__ pr,
    const float* __restrict__ pc,
    float* __restrict__ pooled_r, float* __restrict__ pooled_c)
{
    int idx = blockIdx.x * 256 + threadIdx.x;
    int c = idx & 255;
    int t = idx >> 8;
    int rc = t % LL;
    int b = t / LL;
    float sr = 0.f, sc = 0.f;
    #pragma unroll 8
    for (int i = 0; i < LL; i++) {
        sr += x[((size_t)(b * NQ) + i * LL + rc) * CC + c];
        sc += x[((size_t)(b * NQ) + rc * LL + i) * CC + c];
    }
    pooled_r[idx] = sr * (1.0f / LL) + pr[idx];
    pooled_c[idx] = sc * (1.0f / LL) + pc[idx];
}

// ------------------------- tf32 GEMM (batched, per-job M) ------------------------
struct GemmJob {
    const float* A;    // [M,K]
    const float* B;    // [N,K]
    const float* bias;
    float* C;          // [M,N]
    float alpha;
    int relu;
    int M;
};
struct GemmArgs { GemmJob j[5]; };

template<int BM, int BN, int WM, int WN>
__global__ __launch_bounds__(256, 2) void gemm_tf32(GemmArgs args, int N, int K)
{
    constexpr int MT = WM / 16, NT = WN / 8;
    constexpr int SA = BM * 20, SB = BN * 20, STG = SA + SB;
    constexpr int AU = BM / 64;
    constexpr int BU = BN / 64;
    __shared__ uint32_t sm[2 * STG];

    const GemmJob jb = args.j[blockIdx.z];
    int M = jb.M;
    int bm = blockIdx.y * BM, bn = blockIdx.x * BN;
    if (bm >= M) return;
    int tid = threadIdx.x, warp = tid >> 5, lane = tid & 31;
    constexpr int WARPS_M = BM / WM;
    int wm = warp % WARPS_M, wn = warp / WARPS_M;
    int g = lane >> 2, tq = lane & 3;
    int R0 = wm * WM, N0 = wn * WN;

    float acc[MT][NT][4];
    #pragma unroll
    for (int mt = 0; mt < MT; mt++)
        #pragma unroll
        for (int nt = 0; nt < NT; nt++)
            #pragma unroll
            for (int i = 0; i < 4; i++) acc[mt][nt][i] = 0.f;

    int KT = K >> 4;
    float4 rA[AU], rB[BU];
    int arow[AU], akq[AU], brow[BU], bkq[BU];
    #pragma unroll
    for (int i = 0; i < AU; i++) {
        int idx = tid + i * 256;
        arow[i] = idx >> 2; akq[i] = (idx & 3) * 4;
    }
    #pragma unroll
    for (int i = 0; i < BU; i++) {
        int idx = tid + i * 256;
        brow[i] = idx >> 2; bkq[i] = (idx & 3) * 4;
    }

    #pragma unroll
    for (int i = 0; i < AU; i++) {
        rA[i] = make_float4(0.f, 0.f, 0.f, 0.f);
        if (bm + arow[i] < M)
            rA[i] = *(const float4*)(jb.A + (size_t)(bm + arow[i]) * K + akq[i]);
    }
    #pragma unroll
    for (int i = 0; i < BU; i++)
        rB[i] = *(const float4*)(jb.B + (size_t)(bn + brow[i]) * K + bkq[i]);
    #pragma unroll
    for (int i = 0; i < AU; i++) {
        uint32_t* d = sm + arow[i] * 20 + akq[i];
        d[0] = f2tf32(rA[i].x); d[1] = f2tf32(rA[i].y);
        d[2] = f2tf32(rA[i].z); d[3] = f2tf32(rA[i].w);
    }
    #pragma unroll
    for (int i = 0; i < BU; i++) {
        uint32_t* d = sm + SA + brow[i] * 20 + bkq[i];
        d[0] = f2tf32(rB[i].x); d[1] = f2tf32(rB[i].y);
        d[2] = f2tf32(rB[i].z); d[3] = f2tf32(rB[i].w);
    }
    __syncthreads();

    for (int kt = 0; kt < KT; kt++) {
        int s = kt & 1;
        if (kt + 1 < KT) {
            int k0 = (kt + 1) * 16;
            #pragma unroll
            for (int i = 0; i < AU; i++)
                if (bm + arow[i] < M)
                    rA[i] = *(const float4*)(jb.A + (size_t)(bm + arow[i]) * K + k0 + akq[i]);
            #pragma unroll
            for (int i = 0; i < BU; i++)
                rB[i] = *(const float4*)(jb.B + (size_t)(bn + brow[i]) * K + k0 + bkq[i]);
        }
        const uint32_t* sA = sm + s * STG;
        const uint32_t* sB = sA + SA;
        #pragma unroll
        for (int ks = 0; ks < 2; ks++) {
            int ko = ks * 8;
            uint32_t aF[MT][4], bF[NT][2];
            #pragma unroll
            for (int mt = 0; mt < MT; mt++) {
                int r = R0 + mt * 16 + g;
                aF[mt][0] = sA[r * 20 + ko + tq];
                aF[mt][1] = sA[(r + 8) * 20 + ko + tq];
                aF[mt][2] = sA[r * 20 + ko + tq + 4];
                aF[mt][3] = sA[(r + 8) * 20 + ko + tq + 4];
            }
            #pragma unroll
            for (int nt = 0; nt < NT; nt++) {
                int rn = N0 + nt * 8 + g;
                bF[nt][0] = sB[rn * 20 + ko + tq];
                bF[nt][1] = sB[rn * 20 + ko + tq + 4];
            }
            #pragma unroll
            for (int mt = 0; mt < MT; mt++)
                #pragma unroll
                for (int nt = 0; nt < NT; nt++)
                    mma_tf32(acc[mt][nt], aF[mt], bF[nt]);
        }
        if (kt + 1 < KT) {
            uint32_t* dA = sm + (s ^ 1) * STG;
            uint32_t* dB = dA + SA;
            #pragma unroll
            for (int i = 0; i < AU; i++) {
                uint32_t* d = dA + arow[i] * 20 + akq[i];
                d[0] = f2tf32(rA[i].x); d[1] = f2tf32(rA[i].y);
                d[2] = f2tf32(rA[i].z); d[3] = f2tf32(rA[i].w);
            }
            #pragma unroll
            for (int i = 0; i < BU; i++) {
                uint32_t* d = dB + brow[i] * 20 + bkq[i];
                d[0] = f2tf32(rB[i].x); d[1] = f2tf32(rB[i].y);
                d[2] = f2tf32(rB[i].z); d[3] = f2tf32(rB[i].w);
            }
            __syncthreads();
        }
    }

    #pragma unroll
    for (int mt = 0; mt < MT; mt++)
        #pragma unroll
        for (int nt = 0; nt < NT; nt++) {
            int r = bm + R0 + mt * 16 + g;
            int cn = bn + N0 + nt * 8 + tq * 2;
            float b0 = jb.bias[cn], b1 = jb.bias[cn + 1];
            float o0 = (acc[mt][nt][0] + b0) * jb.alpha;
            float o1 = (acc[mt][nt][1] + b1) * jb.alpha;
            float o2 = (acc[mt][nt][2] + b0) * jb.alpha;
            float o3 = (acc[mt][nt][3] + b1) * jb.alpha;
            if (jb.relu) {
                o0 = fmaxf(o0, 0.f); o1 = fmaxf(o1, 0.f);
                o2 = fmaxf(o2, 0.f); o3 = fmaxf(o3, 0.f);
            }
            if (r < M)
                *(float2*)(jb.C + (size_t)r * N + cn) = make_float2(o0, o1);
            if (r + 8 < M)
                *(float2*)(jb.C + (size_t)(r + 8) * N + cn) = make_float2(o2, o3);
        }
}

// ------------------------- fused attention: scores x2 + softmax + combine -------
// Block = (b, head n, 64 queries). 128 threads / 4 warps; warp owns 16 q-rows.
// Dynamic smem layout (u32 units):
//   Qs   [64*36]  = 2304
//   Ks   [32*72]  = 2304
//   ARs  [64*60]  = 3840   (tf32 row-attention weights)
//   ACs  [64*57]  = 3648   (float col-attention weights)
//   ub   [2*2240] = 4480   (V double-buffer, tf32)
#define AT_QS   0
#define AT_KS   2304
#define AT_ARS  (2304+2304)
#define AT_ACS  (AT_ARS+3840)
#define AT_UB   (AT_ACS+3648)
#define AT_TOTAL_U32 (AT_UB + 4480)

__global__ __launch_bounds__(128) void attn_fused(
    const float* __restrict__ qr, const float* __restrict__ qc,
    const float* __restrict__ kr, const float* __restrict__ kc,
    const unsigned char* __restrict__ mask,
    const float* __restrict__ v, float* __restrict__ attn)
{
    extern __shared__ uint32_t dyn[];
    uint32_t* Qs  = dyn + AT_QS;
    uint32_t* Ks  = dyn + AT_KS;
    uint32_t* ARs = dyn + AT_ARS;
    float*    ACs = (float*)(dyn + AT_ACS);
    uint32_t* ub  = dyn + AT_UB;
    __shared__ unsigned char Ms[64];

    int b = blockIdx.z, n = blockIdx.y, q0 = blockIdx.x * 64;
    int tid = threadIdx.x, warp = tid >> 5, lane = tid & 31;
    int g = lane >> 2, tq = lane & 3;
    int rb = warp * 16;

    // ---- phase 1+2: row scores -> ARs, col scores -> ACs ----
    #pragma unroll 1
    for (int which = 0; which < 2; which++) {
        const float* q  = which ? qc : qr;
        const float* kk = which ? kc : kr;
        int mstride     = which ? LL : 1;

        __syncthreads();   // previous consumers of Qs/Ks done
        {
            int rq = tid >> 1, hf = (tid & 1) * 16;
            const float* qp = q + ((size_t)(b * NQ + q0 + rq)) * CC + n * HD + hf;
            #pragma unroll
            for (int j = 0; j < 4; j++) {
                float4 vv = *(const float4*)(qp + j * 4);
                Qs[rq * 36 + hf + j * 4 + 0] = f2tf32(vv.x);
                Qs[rq * 36 + hf + j * 4 + 1] = f2tf32(vv.y);
                Qs[rq * 36 + hf + j * 4 + 2] = f2tf32(vv.z);
                Qs[rq * 36 + hf + j * 4 + 3] = f2tf32(vv.w);
            }
        }
        for (int i = tid; i < LL * HD; i += 128) {
            int l = i >> 5, d = i & 31;
            Ks[d * 72 + l] = f2tf32(kk[((size_t)(b * LL + l)) * CC + n * HD + d]);
        }
        if (tid < LL) Ms[tid] = mask[b * NQ + tid * mstride];
        __syncthreads();

        uint32_t a[4][4];
        #pragma unroll
        for (int ks = 0; ks < 4; ks++) {
            a[ks][0] = Qs[(rb + g) * 36 + ks * 8 + tq];
            a[ks][1] = Qs[(rb + g + 8) * 36 + ks * 8 + tq];
            a[ks][2] = Qs[(rb + g) * 36 + ks * 8 + tq + 4];
            a[ks][3] = Qs[(rb + g + 8) * 36 + ks * 8 + tq + 4];
        }
        float c[7][4];
        #pragma unroll
        for (int nt = 0; nt < 7; nt++)
            #pragma unroll
            for (int i = 0; i < 4; i++) c[nt][i] = 0.f;
        #pragma unroll
        for (int nt = 0; nt < 7; nt++)
            #pragma unroll
            for (int ks = 0; ks < 4; ks++) {
                uint32_t bf[2] = { Ks[(ks * 8 + tq) * 72 + nt * 8 + g],
                                   Ks[(ks * 8 + tq + 4) * 72 + nt * 8 + g] };
                mma_tf32(c[nt], a[ks], bf);
            }

        float m0 = -3.0e38f, m1 = -3.0e38f;
        #pragma unroll
        for (int nt = 0; nt < 7; nt++) {
            int col = nt * 8 + tq * 2;
            if (Ms[col])     { c[nt][0] = NEGF; c[nt][2] = NEGF; }
            if (Ms[col + 1]) { c[nt][1] = NEGF; c[nt][3] = NEGF; }
            m0 = fmaxf(m0, fmaxf(c[nt][0], c[nt][1]));
            m1 = fmaxf(m1, fmaxf(c[nt][2], c[nt][3]));
        }
        #pragma unroll
        for (int o = 1; o <= 2; o <<= 1) {
            m0 = fmaxf(m0, __shfl_xor_sync(0xffffffffu, m0, o));
            m1 = fmaxf(m1, __shfl_xor_sync(0xffffffffu, m1, o));
        }
        float s0 = 0.f, s1 = 0.f;
        #pragma unroll
        for (int nt = 0; nt < 7; nt++) {
            c[nt][0] = __expf(c[nt][0] - m0);
            c[nt][1] = __expf(c[nt][1] - m0);
            c[nt][2] = __expf(c[nt][2] - m1);
            c[nt][3] = __expf(c[nt][3] - m1);
            s0 += c[nt][0] + c[nt][1];
            s1 += c[nt][2] + c[nt][3];
        }
        #pragma unroll
        for (int o = 1; o <= 2; o <<= 1) {
            s0 += __shfl_xor_sync(0xffffffffu, s0, o);
            s1 += __shfl_xor_sync(0xffffffffu, s1, o);
        }
        float i0 = 1.0f / s0, i1 = 1.0f / s1;
        if (which == 0) {
            #pragma unroll
            for (int nt = 0; nt < 7; nt++) {
                int col = nt * 8 + tq * 2;
                ARs[(rb + g) * 60 + col]         = f2tf32(c[nt][0] * i0);
                ARs[(rb + g) * 60 + col + 1]     = f2tf32(c[nt][1] * i0);
                ARs[(rb + g + 8) * 60 + col]     = f2tf32(c[nt][2] * i1);
                ARs[(rb + g + 8) * 60 + col + 1] = f2tf32(c[nt][3] * i1);
            }
        } else {
            #pragma unroll
            for (int nt = 0; nt < 7; nt++) {
                int col = nt * 8 + tq * 2;
                ACs[(rb + g) * 57 + col]         = c[nt][0] * i0;
                ACs[(rb + g) * 57 + col + 1]     = c[nt][1] * i0;
                ACs[(rb + g + 8) * 57 + col]     = c[nt][2] * i1;
                ACs[(rb + g + 8) * 57 + col + 1] = c[nt][3] * i1;
            }
        }
    }
    __syncthreads();

    // ---- phase 3: RCDA recombination ----
    uint32_t af[7][4];
    #pragma unroll
    for (int ks = 0; ks < 7; ks++) {
        af[ks][0] = ARs[(rb + g) * 60 + ks * 8 + tq];
        af[ks][1] = ARs[(rb + g + 8) * 60 + ks * 8 + tq];
        af[ks][2] = ARs[(rb + g) * 60 + ks * 8 + tq + 4];
        af[ks][3] = ARs[(rb + g + 8) * 60 + ks * 8 + tq + 4];
    }

    float2 vb[7];
    {
        const float* vg = v + ((size_t)(b * NQ)) * CC + n * HD;
        #pragma unroll
        for (int j = 0; j < 7; j++) {
            int i2 = tid + j * 128;
            int w = i2 >> 4, d2 = i2 & 15;
            vb[j] = *(const float2*)(vg + (size_t)w * CC + d2 * 2);
        }
        #pragma unroll
        for (int j = 0; j < 7; j++) {
            int i2 = tid + j * 128;
            int w = i2 >> 4, d2 = i2 & 15;
            ub[w * 40 + d2 * 2]     = f2tf32(vb[j].x);
            ub[w * 40 + d2 * 2 + 1] = f2tf32(vb[j].y);
        }
    }
    __syncthreads();

    float oacc[4][4];
    #pragma unroll
    for (int nt = 0; nt < 4; nt++)
        #pragma unroll
        for (int i = 0; i < 4; i++) oacc[nt][i] = 0.f;

    for (int h = 0; h < LL; h++) {
        int s = h & 1;
        if (h + 1 < LL) {
            const float* vg = v + ((size_t)(b * NQ) + (h + 1) * LL) * CC + n * HD;
            #pragma unroll
            for (int j = 0; j < 7; j++) {
                int i2 = tid + j * 128;
                int w = i2 >> 4, d2 = i2 & 15;
                vb[j] = *(const float2*)(vg + (size_t)w * CC + d2 * 2);
            }
        }
        float p[4][4];
        #pragma unroll
        for (int nt = 0; nt < 4; nt++)
            #pragma unroll
            for (int i = 0; i < 4; i++) p[nt][i] = 0.f;

        const uint32_t* Vst = ub + s * 2240;
        #pragma unroll
        for (int ks = 0; ks < 7; ks++)
            #pragma unroll
            for (int nt = 0; nt < 4; nt++) {
                uint32_t bf[2] = { Vst[(ks * 8 + tq) * 40 + nt * 8 + g],
                                   Vst[(ks * 8 + tq + 4) * 40 + nt * 8 + g] };
                mma_tf32(p[nt], af[ks], bf);
            }

        float ac0 = ACs[(rb + g) * 57 + h];
        float ac1 = ACs[(rb + g + 8) * 57 + h];
        #pragma unroll
        for (int nt = 0; nt < 4; nt++) {
            oacc[nt][0] += ac0 * p[nt][0];
            oacc[nt][1] += ac0 * p[nt][1];
            oacc[nt][2] += ac1 * p[nt][2];
            oacc[nt][3] += ac1 * p[nt][3];
        }
        if (h + 1 < LL) {
            uint32_t* dst = ub + (s ^ 1) * 2240;
            #pragma unroll
            for (int j = 0; j < 7; j++) {
                int i2 = tid + j * 128;
                int w = i2 >> 4, d2 = i2 & 15;
                dst[w * 40 + d2 * 2]     = f2tf32(vb[j].x);
                dst[w * 40 + d2 * 2 + 1] = f2tf32(vb[j].y);
            }
            __syncthreads();
        }
    }

    #pragma unroll
    for (int nt = 0; nt < 4; nt++) {
        int r = q0 + rb + g;
        int col = n * HD + nt * 8 + tq * 2;
        *(float2*)(attn + ((size_t)(b * NQ) + r) * CC + col)
            = make_float2(oacc[nt][0], oacc[nt][1]);
        *(float2*)(attn + ((size_t)(b * NQ) + r + 8) * CC + col)
            = make_float2(oacc[nt][2], oacc[nt][3]);
    }
}

// ------------------------- residual + layernorm --------------------------------
__global__ __launch_bounds__(256) void add_ln(
    const float* __restrict__ A, const float* __restrict__ B,
    const float* __restrict__ gg, const float* __restrict__ be,
    float* __restrict__ out, int transpose_out)
{
    __shared__ float tile[256 * 33];
    int row0 = blockIdx.x * 32;
    int b = row0 / NQ;
    int qg0 = row0 % NQ;
    int tid = threadIdx.x, warp = tid >> 5, lane = tid & 31;

    float4 g0 = *(const float4*)(gg + lane * 4);
    float4 g1 = *(const float4*)(gg + 128 + lane * 4);
    float4 e0 = *(const float4*)(be + lane * 4);
    float4 e1 = *(const float4*)(be + 128 + lane * 4);

    #pragma unroll
    for (int rr = 0; rr < 4; rr++) {
        int rloc = warp * 4 + rr;
        size_t base = (size_t)(row0 + rloc) * CC;
        float4 a0 = *(const float4*)(A + base + lane * 4);
        float4 b0 = *(const float4*)(B + base + lane * 4);
        float4 a1 = *(const float4*)(A + base + 128 + lane * 4);
        float4 b1 = *(const float4*)(B + base + 128 + lane * 4);
        float v0x = a0.x + b0.x, v0y = a0.y + b0.y, v0z = a0.z + b0.z, v0w = a0.w + b0.w;
        float v1x = a1.x + b1.x, v1y = a1.y + b1.y, v1z = a1.z + b1.z, v1w = a1.w + b1.w;
        float s  = v0x + v0y + v0z + v0w + v1x + v1y + v1z + v1w;
        float s2 = v0x*v0x + v0y*v0y + v0z*v0z + v0w*v0w
                 + v1x*v1x + v1y*v1y + v1z*v1z + v1w*v1w;
        #pragma unroll
        for (int o = 16; o; o >>= 1) {
            s  += __shfl_xor_sync(0xffffffffu, s,  o);
            s2 += __shfl_xor_sync(0xffffffffu, s2, o);
        }
        float mean = s * (1.0f / CC);
        float var = s2 * (1.0f / CC) - mean * mean;
        float rstd = rsqrtf(var + 1e-5f);
        float r0x = (v0x - mean) * rstd * g0.x + e0.x;
        float r0y = (v0y - mean) * rstd * g0.y + e0.y;
        float r0z = (v0z - mean) * rstd * g0.z + e0.z;
        float r0w = (v0w - mean) * rstd * g0.w + e0.w;
        float r1x = (v1x - mean) * rstd * g1.x + e1.x;
        float r1y = (v1y - mean) * rstd * g1.y + e1.y;
        float r1z = (v1z - mean) * rstd * g1.z + e1.z;
        float r1w = (v1w - mean) * rstd * g1.w + e1.w;
        if (!transpose_out) {
            *(float4*)(out + base + lane * 4) = make_float4(r0x, r0y, r0z, r0w);
            *(float4*)(out + base + 128 + lane * 4) = make_float4(r1x, r1y, r1z, r1w);
        } else {
            int c = lane * 4;
            tile[(c + 0) * 33 + rloc] = r0x;
            tile[(c + 1) * 33 + rloc] = r0y;
            tile[(c + 2) * 33 + rloc] = r0z;
            tile[(c + 3) * 33 + rloc] = r0w;
            tile[(c + 128) * 33 + rloc] = r1x;
            tile[(c + 129) * 33 + rloc] = r1y;
            tile[(c + 130) * 33 + rloc] = r1z;
            tile[(c + 131) * 33 + rloc] = r1w;
        }
    }
    if (transpose_out) {
        __syncthreads();
        int qv = tid & 31;
        int cb = tid >> 5;
        #pragma unroll 8
        for (int k = 0; k < 32; k++) {
            int c = cb + k * 8;
            out[((size_t)(b * CC + c)) * NQ + qg0 + qv] = tile[c * 33 + qv];
        }
    }
}

// ------------------------- launch ----------------------------------------------
extern "C" void kernel_launch(void* const* d_in, const int* in_sizes, int n_in,
                              void* d_out, int out_size)
{
    const float* src   = (const float*)d_in[0];
    const unsigned char* pm = (const unsigned char*)d_in[1];
    const float* pr    = (const float*)d_in[2];
    const float* pc    = (const float*)d_in[3];
    const float* w_q_row = (const float*)d_in[4];
    const float* b_q_row = (const float*)d_in[5];
    const float* w_q_col = (const float*)d_in[6];
    const float* b_q_col = (const float*)d_in[7];
    const float* w_k_row = (const float*)d_in[8];
    const float* b_k_row = (const float*)d_in[9];
    const float* w_k_col = (const float*)d_in[10];
    const float* b_k_col = (const float*)d_in[11];
    const float* w_v   = (const float*)d_in[12];
    const float* b_v   = (const float*)d_in[13];
    const float* w_out = (const float*)d_in[14];
    const float* b_out = (const float*)d_in[15];
    const float* n1g   = (const float*)d_in[16];
    const float* n1b   = (const float*)d_in[17];
    const float* l1w   = (const float*)d_in[18];
    const float* l1b   = (const float*)d_in[19];
    const float* l2w   = (const float*)d_in[20];
    const float* l2b   = (const float*)d_in[21];
    const float* n2g   = (const float*)d_in[22];
    const float* n2b   = (const float*)d_in[23];
    float* out = (float*)d_out;

    float* F = nullptr;
    cudaGetSymbolAddress((void**)&F, g_f);
    cudaFuncSetAttribute(attn_fused, cudaFuncAttributeMaxDynamicSharedMemorySize,
                         AT_TOTAL_U32 * 4);

    prep_kernel<<<dim3(NQ / 64, CC / 64, BZV), 256>>>(
        src, pr, pc, F + F_X, F + F_XPR, F + F_XPC);

    pool_kernel<<<BZV * LL * CC / 256, 256>>>(
        F + F_X, pr, pc, F + F_PR, F + F_PC);

    // all 5 projections in one batched launch (per-job M, early exit)
    {
        GemmArgs a;
        a.j[0] = {F+F_XPR, w_q_row, b_q_row, F+F_QROW, SCALE, 0, MQ};
        a.j[1] = {F+F_XPC, w_q_col, b_q_col, F+F_QCOL, SCALE, 0, MQ};
        a.j[2] = {F+F_X,   w_v,     b_v,     F+F_V,    1.0f, 0, MQ};
        a.j[3] = {F+F_PR,  w_k_row, b_k_row, F+F_KROW, 1.0f, 0, BZV*LL};
        a.j[4] = {F+F_PC,  w_k_col, b_k_col, F+F_KCOL, 1.0f, 0, BZV*LL};
        gemm_tf32<128,128,64,32><<<dim3(CC/128, MQ/128, 5), 256>>>(a, CC, CC);
    }

    attn_fused<<<dim3(NQ/64, NH, BZV), 128, AT_TOTAL_U32 * 4>>>(
        F+F_QROW, F+F_QCOL, F+F_KROW, F+F_KCOL, pm, F+F_V, F+F_ATTN);

    {
        GemmArgs a;
        a.j[0] = {F+F_ATTN, w_out, b_out, F+F_ATTNOUT, 1.0f, 0, MQ};
        a.j[1] = a.j[0]; a.j[2] = a.j[0]; a.j[3] = a.j[0]; a.j[4] = a.j[0];
        gemm_tf32<128,128,64,32><<<dim3(CC/128, MQ/128, 1), 256>>>(a, CC, CC);
    }
    add_ln<<<MQ/32, 256>>>(F+F_X, F+F_ATTNOUT, n1g, n1b, F+F_X1, 0);

    {
        GemmArgs a;
        a.j[0] = {F+F_X1, l1w, l1b, F+F_FFN, 1.0f, 1, MQ};
        a.j[1] = a.j[0]; a.j[2] = a.j[0]; a.j[3] = a.j[0]; a.j[4] = a.j[0];
        gemm_tf32<128,128,64,32><<<dim3(DFFN/128, MQ/128, 1), 256>>>(a, DFFN, CC);
    }
    {
        GemmArgs a;
        a.j[0] = {F+F_FFN, l2w, l2b, F+F_Y, 1.0f, 0, MQ};
        a.j[1] = a.j[0]; a.j[2] = a.j[0]; a.j[3] = a.j[0]; a.j[4] = a.j[0];
        gemm_tf32<128,128,64,32><<<dim3(CC/128, MQ/128, 1), 256>>>(a, CC, DFFN);
    }
    add_ln<<<MQ/32, 256>>>(F+F_X1, F+F_Y, n2g, n2b, out, 1);
}

// round 8
// speedup vs baseline: 3.6229x; 1.0406x over previous
#include <cuda_runtime.h>
#include <cstdint>
#include <cstddef>

#define NQ    3136
#define CC    256
#define BZV   2
#define NH    8
#define HD    32
#define LL    56
#define DFFN  1024
#define MQ    (BZV*NQ)
#define SCALE 0.17677669529663687f
#define NEGF  (-3.402823466e38f)

// ------------------------- scratch -------------------------------------------
#define SZ_BQC (MQ*CC)
#define SZ_KP  (BZV*LL*CC)
#define SZ_FFN (MQ*DFFN)

#define F_X       ((size_t)0)
#define F_XPR     (F_X    + SZ_BQC)
#define F_XPC     (F_XPR  + SZ_BQC)
#define F_QROW    (F_XPC  + SZ_BQC)
#define F_QCOL    (F_QROW + SZ_BQC)
#define F_V       (F_QCOL + SZ_BQC)
#define F_ATTN    (F_V    + SZ_BQC)
#define F_ATTNOUT (F_ATTN + SZ_BQC)
#define F_X1      (F_ATTNOUT + SZ_BQC)
#define F_Y       (F_X1   + SZ_BQC)
#define F_FFN     (F_Y    + SZ_BQC)
#define F_PR      (F_FFN  + SZ_FFN)
#define F_PC      (F_PR   + SZ_KP)
#define F_KROW    (F_PC   + SZ_KP)
#define F_KCOL    (F_KROW + SZ_KP)
#define F_TOTAL   (F_KCOL + SZ_KP)
__device__ float g_f[F_TOTAL];

// ------------------------- helpers -------------------------------------------
__device__ __forceinline__ uint32_t f2tf32(float x) {
    uint32_t r; asm("cvt.rna.tf32.f32 %0, %1;" : "=r"(r) : "f"(x)); return r;
}
__device__ __forceinline__ void mma_tf32(float (&c)[4], const uint32_t (&a)[4],
                                         const uint32_t (&b)[2]) {
    asm volatile("mma.sync.aligned.m16n8k8.row.col.f32.tf32.tf32.f32 "
        "{%0,%1,%2,%3},{%4,%5,%6,%7},{%8,%9},{%0,%1,%2,%3};"
        : "+f"(c[0]), "+f"(c[1]), "+f"(c[2]), "+f"(c[3])
        : "r"(a[0]), "r"(a[1]), "r"(a[2]), "r"(a[3]), "r"(b[0]), "r"(b[1]));
}

// ------------------------- prep ------------------------------------------------
__global__ __launch_bounds__(256) void prep_kernel(
    const float* __restrict__ src, const float* __restrict__ pr,
    const float* __restrict__ pc, float* __restrict__ x,
    float* __restrict__ xpr, float* __restrict__ xpc)
{
    __shared__ float tile[64 * 65];
    int b = blockIdx.z;
    int q0 = blockIdx.x * 64, c0 = blockIdx.y * 64;
    int tid = threadIdx.x;

    int cl_ = tid >> 2, qs = (tid & 3) * 16;
    const float* sp = src + ((size_t)(b * CC + c0 + cl_)) * NQ + q0 + qs;
    #pragma unroll
    for (int j = 0; j < 4; j++) {
        float4 vv = *(const float4*)(sp + j * 4);
        tile[cl_ * 65 + qs + j * 4 + 0] = vv.x;
        tile[cl_ * 65 + qs + j * 4 + 1] = vv.y;
        tile[cl_ * 65 + qs + j * 4 + 2] = vv.z;
        tile[cl_ * 65 + qs + j * 4 + 3] = vv.w;
    }
    __syncthreads();

    int ql = tid >> 2, cs = (tid & 3) * 16;
    int q = q0 + ql;
    int irow = q / LL, jcol = q % LL;
    const float* prp = pr + (size_t)(b * LL + jcol) * CC + c0 + cs;
    const float* pcp = pc + (size_t)(b * LL + irow) * CC + c0 + cs;
    size_t ob = ((size_t)(b * NQ + q)) * CC + c0 + cs;
    #pragma unroll
    for (int j = 0; j < 4; j++) {
        float v0 = tile[(cs + j * 4 + 0) * 65 + ql];
        float v1 = tile[(cs + j * 4 + 1) * 65 + ql];
        float v2 = tile[(cs + j * 4 + 2) * 65 + ql];
        float v3 = tile[(cs + j * 4 + 3) * 65 + ql];
        float4 p4 = *(const float4*)(prp + j * 4);
        float4 c4 = *(const float4*)(pcp + j * 4);
        *(float4*)(x + ob + j * 4) = make_float4(v0, v1, v2, v3);
        *(float4*)(xpr + ob + j * 4) = make_float4(v0 + p4.x, v1 + p4.y, v2 + p4.z, v3 + p4.w);
        *(float4*)(xpc + ob + j * 4) = make_float4(v0 + c4.x, v1 + c4.y, v2 + c4.z, v3 + c4.w);
    }
}

// ------------------------- pooling ---------------------------------------------
__global__ __launch_bounds__(256) void pool_kernel(
    const float* __restrict__ x, const float* __restrict__ pr,
    const float* __restrict__ pc,
    float* __restrict__ pooled_r, float* __restrict__ pooled_c)
{
    int idx = blockIdx.x * 256 + threadIdx.x;
    int c = idx & 255;
    int t = idx >> 8;
    int rc = t % LL;
    int b = t / LL;
    float sr = 0.f, sc = 0.f;
    #pragma unroll 8
    for (int i = 0; i < LL; i++) {
        sr += x[((size_t)(b * NQ) + i * LL + rc) * CC + c];
        sc += x[((size_t)(b * NQ) + rc * LL + i) * CC + c];
    }
    pooled_r[idx] = sr * (1.0f / LL) + pr[idx];
    pooled_c[idx] = sc * (1.0f / LL) + pc[idx];
}

// ------------------------- tf32 GEMM (batched, per-job M) ------------------------
struct GemmJob {
    const float* A;    // [M,K]
    const float* B;    // [N,K]
    const float* bias;
    float* C;          // [M,N]
    float alpha;
    int relu;
    int M;
    int cvt;           // store outputs as tf32 bit patterns
};
struct GemmArgs { GemmJob j[5]; };

template<int BM, int BN, int WM, int WN>
__global__ __launch_bounds__(256, 2) void gemm_tf32(GemmArgs args, int N, int K)
{
    constexpr int MT = WM / 16, NT = WN / 8;
    constexpr int SA = BM * 20, SB = BN * 20, STG = SA + SB;
    constexpr int AU = BM / 64;
    constexpr int BU = BN / 64;
    __shared__ uint32_t sm[2 * STG];

    const GemmJob jb = args.j[blockIdx.z];
    int M = jb.M;
    int bm = blockIdx.y * BM, bn = blockIdx.x * BN;
    if (bm >= M) return;
    int tid = threadIdx.x, warp = tid >> 5, lane = tid & 31;
    constexpr int WARPS_M = BM / WM;
    int wm = warp % WARPS_M, wn = warp / WARPS_M;
    int g = lane >> 2, tq = lane & 3;
    int R0 = wm * WM, N0 = wn * WN;

    float acc[MT][NT][4];
    #pragma unroll
    for (int mt = 0; mt < MT; mt++)
        #pragma unroll
        for (int nt = 0; nt < NT; nt++)
            #pragma unroll
            for (int i = 0; i < 4; i++) acc[mt][nt][i] = 0.f;

    int KT = K >> 4;
    float4 rA[AU], rB[BU];
    int arow[AU], akq[AU], brow[BU], bkq[BU];
    #pragma unroll
    for (int i = 0; i < AU; i++) {
        int idx = tid + i * 256;
        arow[i] = idx >> 2; akq[i] = (idx & 3) * 4;
    }
    #pragma unroll
    for (int i = 0; i < BU; i++) {
        int idx = tid + i * 256;
        brow[i] = idx >> 2; bkq[i] = (idx & 3) * 4;
    }

    #pragma unroll
    for (int i = 0; i < AU; i++) {
        rA[i] = make_float4(0.f, 0.f, 0.f, 0.f);
        if (bm + arow[i] < M)
            rA[i] = *(const float4*)(jb.A + (size_t)(bm + arow[i]) * K + akq[i]);
    }
    #pragma unroll
    for (int i = 0; i < BU; i++)
        rB[i] = *(const float4*)(jb.B + (size_t)(bn + brow[i]) * K + bkq[i]);
    #pragma unroll
    for (int i = 0; i < AU; i++) {
        uint32_t* d = sm + arow[i] * 20 + akq[i];
        d[0] = f2tf32(rA[i].x); d[1] = f2tf32(rA[i].y);
        d[2] = f2tf32(rA[i].z); d[3] = f2tf32(rA[i].w);
    }
    #pragma unroll
    for (int i = 0; i < BU; i++) {
        uint32_t* d = sm + SA + brow[i] * 20 + bkq[i];
        d[0] = f2tf32(rB[i].x); d[1] = f2tf32(rB[i].y);
        d[2] = f2tf32(rB[i].z); d[3] = f2tf32(rB[i].w);
    }
    __syncthreads();

    for (int kt = 0; kt < KT; kt++) {
        int s = kt & 1;
        if (kt + 1 < KT) {
            int k0 = (kt + 1) * 16;
            #pragma unroll
            for (int i = 0; i < AU; i++)
                if (bm + arow[i] < M)
                    rA[i] = *(const float4*)(jb.A + (size_t)(bm + arow[i]) * K + k0 + akq[i]);
            #pragma unroll
            for (int i = 0; i < BU; i++)
                rB[i] = *(const float4*)(jb.B + (size_t)(bn + brow[i]) * K + k0 + bkq[i]);
        }
        const uint32_t* sA = sm + s * STG;
        const uint32_t* sB = sA + SA;
        #pragma unroll
        for (int ks = 0; ks < 2; ks++) {
            int ko = ks * 8;
            uint32_t aF[MT][4], bF[NT][2];
            #pragma unroll
            for (int mt = 0; mt < MT; mt++) {
                int r = R0 + mt * 16 + g;
                aF[mt][0] = sA[r * 20 + ko + tq];
                aF[mt][1] = sA[(r + 8) * 20 + ko + tq];
                aF[mt][2] = sA[r * 20 + ko + tq + 4];
                aF[mt][3] = sA[(r + 8) * 20 + ko + tq + 4];
            }
            #pragma unroll
            for (int nt = 0; nt < NT; nt++) {
                int rn = N0 + nt * 8 + g;
                bF[nt][0] = sB[rn * 20 + ko + tq];
                bF[nt][1] = sB[rn * 20 + ko + tq + 4];
            }
            #pragma unroll
            for (int mt = 0; mt < MT; mt++)
                #pragma unroll
                for (int nt = 0; nt < NT; nt++)
                    mma_tf32(acc[mt][nt], aF[mt], bF[nt]);
        }
        if (kt + 1 < KT) {
            uint32_t* dA = sm + (s ^ 1) * STG;
            uint32_t* dB = dA + SA;
            #pragma unroll
            for (int i = 0; i < AU; i++) {
                uint32_t* d = dA + arow[i] * 20 + akq[i];
                d[0] = f2tf32(rA[i].x); d[1] = f2tf32(rA[i].y);
                d[2] = f2tf32(rA[i].z); d[3] = f2tf32(rA[i].w);
            }
            #pragma unroll
            for (int i = 0; i < BU; i++) {
                uint32_t* d = dB + brow[i] * 20 + bkq[i];
                d[0] = f2tf32(rB[i].x); d[1] = f2tf32(rB[i].y);
                d[2] = f2tf32(rB[i].z); d[3] = f2tf32(rB[i].w);
            }
            __syncthreads();
        }
    }

    #pragma unroll
    for (int mt = 0; mt < MT; mt++)
        #pragma unroll
        for (int nt = 0; nt < NT; nt++) {
            int r = bm + R0 + mt * 16 + g;
            int cn = bn + N0 + nt * 8 + tq * 2;
            float b0 = jb.bias[cn], b1 = jb.bias[cn + 1];
            float o0 = (acc[mt][nt][0] + b0) * jb.alpha;
            float o1 = (acc[mt][nt][1] + b1) * jb.alpha;
            float o2 = (acc[mt][nt][2] + b0) * jb.alpha;
            float o3 = (acc[mt][nt][3] + b1) * jb.alpha;
            if (jb.relu) {
                o0 = fmaxf(o0, 0.f); o1 = fmaxf(o1, 0.f);
                o2 = fmaxf(o2, 0.f); o3 = fmaxf(o3, 0.f);
            }
            if (jb.cvt) {
                o0 = __uint_as_float(f2tf32(o0));
                o1 = __uint_as_float(f2tf32(o1));
                o2 = __uint_as_float(f2tf32(o2));
                o3 = __uint_as_float(f2tf32(o3));
            }
            if (r < M)
                *(float2*)(jb.C + (size_t)r * N + cn) = make_float2(o0, o1);
            if (r + 8 < M)
                *(float2*)(jb.C + (size_t)(r + 8) * N + cn) = make_float2(o2, o3);
        }
}

// ------------------------- fused attention --------------------------------------
// Block = (b, head n, 64 queries), 128 threads / 4 warps.
// Combine phase: warps tiled 2(q) x 2(d); warp = 32 q-rows x 16 d-cols.
// V arrives PRE-CONVERTED to tf32 bit patterns (gemm cvt epilogue).
#define AT_QS   0
#define AT_KS   2304
#define AT_ARS  (2304+2304)
#define AT_ACS  (AT_ARS+3840)
#define AT_UB   (AT_ACS+3648)
#define AT_TOTAL_U32 (AT_UB + 4480)

__global__ __launch_bounds__(128) void attn_fused(
    const float* __restrict__ qr, const float* __restrict__ qc,
    const float* __restrict__ kr, const float* __restrict__ kc,
    const unsigned char* __restrict__ mask,
    const float* __restrict__ v, float* __restrict__ attn)
{
    extern __shared__ uint32_t dyn[];
    uint32_t* Qs  = dyn + AT_QS;
    uint32_t* Ks  = dyn + AT_KS;
    uint32_t* ARs = dyn + AT_ARS;
    float*    ACs = (float*)(dyn + AT_ACS);
    uint32_t* ub  = dyn + AT_UB;
    __shared__ unsigned char Ms[64];

    int b = blockIdx.z, n = blockIdx.y, q0 = blockIdx.x * 64;
    int tid = threadIdx.x, warp = tid >> 5, lane = tid & 31;
    int g = lane >> 2, tq = lane & 3;
    int rb = warp * 16;

    // ---- phase 1+2: row scores -> ARs (tf32), col scores -> ACs (f32) ----
    #pragma unroll 1
    for (int which = 0; which < 2; which++) {
        const float* q  = which ? qc : qr;
        const float* kk = which ? kc : kr;
        int mstride     = which ? LL : 1;

        __syncthreads();
        {
            int rq = tid >> 1, hf = (tid & 1) * 16;
            const float* qp = q + ((size_t)(b * NQ + q0 + rq)) * CC + n * HD + hf;
            #pragma unroll
            for (int j = 0; j < 4; j++) {
                float4 vv = *(const float4*)(qp + j * 4);
                Qs[rq * 36 + hf + j * 4 + 0] = f2tf32(vv.x);
                Qs[rq * 36 + hf + j * 4 + 1] = f2tf32(vv.y);
                Qs[rq * 36 + hf + j * 4 + 2] = f2tf32(vv.z);
                Qs[rq * 36 + hf + j * 4 + 3] = f2tf32(vv.w);
            }
        }
        for (int i = tid; i < LL * HD; i += 128) {
            int l = i >> 5, d = i & 31;
            Ks[d * 72 + l] = f2tf32(kk[((size_t)(b * LL + l)) * CC + n * HD + d]);
        }
        if (tid < LL) Ms[tid] = mask[b * NQ + tid * mstride];
        __syncthreads();

        uint32_t a[4][4];
        #pragma unroll
        for (int ks = 0; ks < 4; ks++) {
            a[ks][0] = Qs[(rb + g) * 36 + ks * 8 + tq];
            a[ks][1] = Qs[(rb + g + 8) * 36 + ks * 8 + tq];
            a[ks][2] = Qs[(rb + g) * 36 + ks * 8 + tq + 4];
            a[ks][3] = Qs[(rb + g + 8) * 36 + ks * 8 + tq + 4];
        }
        float c[7][4];
        #pragma unroll
        for (int nt = 0; nt < 7; nt++)
            #pragma unroll
            for (int i = 0; i < 4; i++) c[nt][i] = 0.f;
        #pragma unroll
        for (int nt = 0; nt < 7; nt++)
            #pragma unroll
            for (int ks = 0; ks < 4; ks++) {
                uint32_t bf[2] = { Ks[(ks * 8 + tq) * 72 + nt * 8 + g],
                                   Ks[(ks * 8 + tq + 4) * 72 + nt * 8 + g] };
                mma_tf32(c[nt], a[ks], bf);
            }

        float m0 = -3.0e38f, m1 = -3.0e38f;
        #pragma unroll
        for (int nt = 0; nt < 7; nt++) {
            int col = nt * 8 + tq * 2;
            if (Ms[col])     { c[nt][0] = NEGF; c[nt][2] = NEGF; }
            if (Ms[col + 1]) { c[nt][1] = NEGF; c[nt][3] = NEGF; }
            m0 = fmaxf(m0, fmaxf(c[nt][0], c[nt][1]));
            m1 = fmaxf(m1, fmaxf(c[nt][2], c[nt][3]));
        }
        #pragma unroll
        for (int o = 1; o <= 2; o <<= 1) {
            m0 = fmaxf(m0, __shfl_xor_sync(0xffffffffu, m0, o));
            m1 = fmaxf(m1, __shfl_xor_sync(0xffffffffu, m1, o));
        }
        float s0 = 0.f, s1 = 0.f;
        #pragma unroll
        for (int nt = 0; nt < 7; nt++) {
            c[nt][0] = __expf(c[nt][0] - m0);
            c[nt][1] = __expf(c[nt][1] - m0);
            c[nt][2] = __expf(c[nt][2] - m1);
            c[nt][3] = __expf(c[nt][3] - m1);
            s0 += c[nt][0] + c[nt][1];
            s1 += c[nt][2] + c[nt][3];
        }
        #pragma unroll
        for (int o = 1; o <= 2; o <<= 1) {
            s0 += __shfl_xor_sync(0xffffffffu, s0, o);
            s1 += __shfl_xor_sync(0xffffffffu, s1, o);
        }
        float i0 = 1.0f / s0, i1 = 1.0f / s1;
        if (which == 0) {
            #pragma unroll
            for (int nt = 0; nt < 7; nt++) {
                int col = nt * 8 + tq * 2;
                ARs[(rb + g) * 60 + col]         = f2tf32(c[nt][0] * i0);
                ARs[(rb + g) * 60 + col + 1]     = f2tf32(c[nt][1] * i0);
                ARs[(rb + g + 8) * 60 + col]     = f2tf32(c[nt][2] * i1);
                ARs[(rb + g + 8) * 60 + col + 1] = f2tf32(c[nt][3] * i1);
            }
        } else {
            #pragma unroll
            for (int nt = 0; nt < 7; nt++) {
                int col = nt * 8 + tq * 2;
                ACs[(rb + g) * 57 + col]         = c[nt][0] * i0;
                ACs[(rb + g) * 57 + col + 1]     = c[nt][1] * i0;
                ACs[(rb + g + 8) * 57 + col]     = c[nt][2] * i1;
                ACs[(rb + g + 8) * 57 + col + 1] = c[nt][3] * i1;
            }
        }
    }
    __syncthreads();

    // ---- phase 3: RCDA recombination (warps 2q x 2d) ----
    int wq = warp & 1, wd = warp >> 1;
    int QB = wq * 32, DB = wd * 16;

    uint32_t af[7][2][4];
    #pragma unroll
    for (int ks = 0; ks < 7; ks++)
        #pragma unroll
        for (int mt = 0; mt < 2; mt++) {
            int r = QB + mt * 16 + g;
            af[ks][mt][0] = ARs[r * 60 + ks * 8 + tq];
            af[ks][mt][1] = ARs[(r + 8) * 60 + ks * 8 + tq];
            af[ks][mt][2] = ARs[r * 60 + ks * 8 + tq + 4];
            af[ks][mt][3] = ARs[(r + 8) * 60 + ks * 8 + tq + 4];
        }

    // V staging (pre-converted tf32 bits): pure 64-bit copies
    uint2 vb[7];
    {
        const uint2* vg = (const uint2*)(v + ((size_t)(b * NQ)) * CC + n * HD);
        #pragma unroll
        for (int j = 0; j < 7; j++) {
            int i2 = tid + j * 128;
            int w = i2 >> 4, d2 = i2 & 15;
            vb[j] = vg[w * (CC / 2) + d2];
        }
        #pragma unroll
        for (int j = 0; j < 7; j++) {
            int i2 = tid + j * 128;
            int w = i2 >> 4, d2 = i2 & 15;
            *(uint2*)(ub + w * 40 + d2 * 2) = vb[j];
        }
    }
    __syncthreads();

    float oacc[2][2][4];
    #pragma unroll
    for (int mt = 0; mt < 2; mt++)
        #pragma unroll
        for (int nt = 0; nt < 2; nt++)
            #pragma unroll
            for (int i = 0; i < 4; i++) oacc[mt][nt][i] = 0.f;

    for (int h = 0; h < LL; h++) {
        int s = h & 1;
        if (h + 1 < LL) {
            const uint2* vg = (const uint2*)(v + ((size_t)(b * NQ) + (h + 1) * LL) * CC + n * HD);
            #pragma unroll
            for (int j = 0; j < 7; j++) {
                int i2 = tid + j * 128;
                int w = i2 >> 4, d2 = i2 & 15;
                vb[j] = vg[w * (CC / 2) + d2];
            }
        }
        float p[2][2][4];
        #pragma unroll
        for (int mt = 0; mt < 2; mt++)
            #pragma unroll
            for (int nt = 0; nt < 2; nt++)
                #pragma unroll
                for (int i = 0; i < 4; i++) p[mt][nt][i] = 0.f;

        const uint32_t* Vst = ub + s * 2240;
        #pragma unroll
        for (int ks = 0; ks < 7; ks++) {
            uint32_t bf[2][2];
            #pragma unroll
            for (int nt = 0; nt < 2; nt++) {
                bf[nt][0] = Vst[(ks * 8 + tq) * 40 + DB + nt * 8 + g];
                bf[nt][1] = Vst[(ks * 8 + tq + 4) * 40 + DB + nt * 8 + g];
            }
            #pragma unroll
            for (int mt = 0; mt < 2; mt++)
                #pragma unroll
                for (int nt = 0; nt < 2; nt++)
                    mma_tf32(p[mt][nt], af[ks][mt], bf[nt]);
        }

        #pragma unroll
        for (int mt = 0; mt < 2; mt++) {
            float ac0 = ACs[(QB + mt * 16 + g) * 57 + h];
            float ac1 = ACs[(QB + mt * 16 + g + 8) * 57 + h];
            #pragma unroll
            for (int nt = 0; nt < 2; nt++) {
                oacc[mt][nt][0] += ac0 * p[mt][nt][0];
                oacc[mt][nt][1] += ac0 * p[mt][nt][1];
                oacc[mt][nt][2] += ac1 * p[mt][nt][2];
                oacc[mt][nt][3] += ac1 * p[mt][nt][3];
            }
        }
        if (h + 1 < LL) {
            uint32_t* dst = ub + (s ^ 1) * 2240;
            #pragma unroll
            for (int j = 0; j < 7; j++) {
                int i2 = tid + j * 128;
                int w = i2 >> 4, d2 = i2 & 15;
                *(uint2*)(dst + w * 40 + d2 * 2) = vb[j];
            }
            __syncthreads();
        }
    }

    #pragma unroll
    for (int mt = 0; mt < 2; mt++)
        #pragma unroll
        for (int nt = 0; nt < 2; nt++) {
            int r = q0 + QB + mt * 16 + g;
            int col = n * HD + DB + nt * 8 + tq * 2;
            *(float2*)(attn + ((size_t)(b * NQ) + r) * CC + col)
                = make_float2(oacc[mt][nt][0], oacc[mt][nt][1]);
            *(float2*)(attn + ((size_t)(b * NQ) + r + 8) * CC + col)
                = make_float2(oacc[mt][nt][2], oacc[mt][nt][3]);
        }
}

// ------------------------- residual + layernorm --------------------------------
__global__ __launch_bounds__(256) void add_ln(
    const float* __restrict__ A, const float* __restrict__ B,
    const float* __restrict__ gg, const float* __restrict__ be,
    float* __restrict__ out, int transpose_out)
{
    __shared__ float tile[256 * 33];
    int row0 = blockIdx.x * 32;
    int b = row0 / NQ;
    int qg0 = row0 % NQ;
    int tid = threadIdx.x, warp = tid >> 5, lane = tid & 31;

    float4 g0 = *(const float4*)(gg + lane * 4);
    float4 g1 = *(const float4*)(gg + 128 + lane * 4);
    float4 e0 = *(const float4*)(be + lane * 4);
    float4 e1 = *(const float4*)(be + 128 + lane * 4);

    #pragma unroll
    for (int rr = 0; rr < 4; rr++) {
        int rloc = warp * 4 + rr;
        size_t base = (size_t)(row0 + rloc) * CC;
        float4 a0 = *(const float4*)(A + base + lane * 4);
        float4 b0 = *(const float4*)(B + base + lane * 4);
        float4 a1 = *(const float4*)(A + base + 128 + lane * 4);
        float4 b1 = *(const float4*)(B + base + 128 + lane * 4);
        float v0x = a0.x + b0.x, v0y = a0.y + b0.y, v0z = a0.z + b0.z, v0w = a0.w + b0.w;
        float v1x = a1.x + b1.x, v1y = a1.y + b1.y, v1z = a1.z + b1.z, v1w = a1.w + b1.w;
        float s  = v0x + v0y + v0z + v0w + v1x + v1y + v1z + v1w;
        float s2 = v0x*v0x + v0y*v0y + v0z*v0z + v0w*v0w
                 + v1x*v1x + v1y*v1y + v1z*v1z + v1w*v1w;
        #pragma unroll
        for (int o = 16; o; o >>= 1) {
            s  += __shfl_xor_sync(0xffffffffu, s,  o);
            s2 += __shfl_xor_sync(0xffffffffu, s2, o);
        }
        float mean = s * (1.0f / CC);
        float var = s2 * (1.0f / CC) - mean * mean;
        float rstd = rsqrtf(var + 1e-5f);
        float r0x = (v0x - mean) * rstd * g0.x + e0.x;
        float r0y = (v0y - mean) * rstd * g0.y + e0.y;
        float r0z = (v0z - mean) * rstd * g0.z + e0.z;
        float r0w = (v0w - mean) * rstd * g0.w + e0.w;
        float r1x = (v1x - mean) * rstd * g1.x + e1.x;
        float r1y = (v1y - mean) * rstd * g1.y + e1.y;
        float r1z = (v1z - mean) * rstd * g1.z + e1.z;
        float r1w = (v1w - mean) * rstd * g1.w + e1.w;
        if (!transpose_out) {
            *(float4*)(out + base + lane * 4) = make_float4(r0x, r0y, r0z, r0w);
            *(float4*)(out + base + 128 + lane * 4) = make_float4(r1x, r1y, r1z, r1w);
        } else {
            int c = lane * 4;
            tile[(c + 0) * 33 + rloc] = r0x;
            tile[(c + 1) * 33 + rloc] = r0y;
            tile[(c + 2) * 33 + rloc] = r0z;
            tile[(c + 3) * 33 + rloc] = r0w;
            tile[(c + 128) * 33 + rloc] = r1x;
            tile[(c + 129) * 33 + rloc] = r1y;
            tile[(c + 130) * 33 + rloc] = r1z;
            tile[(c + 131) * 33 + rloc] = r1w;
        }
    }
    if (transpose_out) {
        __syncthreads();
        int qv = tid & 31;
        int cb = tid >> 5;
        #pragma unroll 8
        for (int k = 0; k < 32; k++) {
            int c = cb + k * 8;
            out[((size_t)(b * CC + c)) * NQ + qg0 + qv] = tile[c * 33 + qv];
        }
    }
}

// ------------------------- launch ----------------------------------------------
extern "C" void kernel_launch(void* const* d_in, const int* in_sizes, int n_in,
                              void* d_out, int out_size)
{
    const float* src   = (const float*)d_in[0];
    const unsigned char* pm = (const unsigned char*)d_in[1];
    const float* pr    = (const float*)d_in[2];
    const float* pc    = (const float*)d_in[3];
    const float* w_q_row = (const float*)d_in[4];
    const float* b_q_row = (const float*)d_in[5];
    const float* w_q_col = (const float*)d_in[6];
    const float* b_q_col = (const float*)d_in[7];
    const float* w_k_row = (const float*)d_in[8];
    const float* b_k_row = (const float*)d_in[9];
    const float* w_k_col = (const float*)d_in[10];
    const float* b_k_col = (const float*)d_in[11];
    const float* w_v   = (const float*)d_in[12];
    const float* b_v   = (const float*)d_in[13];
    const float* w_out = (const float*)d_in[14];
    const float* b_out = (const float*)d_in[15];
    const float* n1g   = (const float*)d_in[16];
    const float* n1b   = (const float*)d_in[17];
    const float* l1w   = (const float*)d_in[18];
    const float* l1b   = (const float*)d_in[19];
    const float* l2w   = (const float*)d_in[20];
    const float* l2b   = (const float*)d_in[21];
    const float* n2g   = (const float*)d_in[22];
    const float* n2b   = (const float*)d_in[23];
    float* out = (float*)d_out;

    float* F = nullptr;
    cudaGetSymbolAddress((void**)&F, g_f);
    cudaFuncSetAttribute(attn_fused, cudaFuncAttributeMaxDynamicSharedMemorySize,
                         AT_TOTAL_U32 * 4);

    prep_kernel<<<dim3(NQ / 64, CC / 64, BZV), 256>>>(
        src, pr, pc, F + F_X, F + F_XPR, F + F_XPC);

    pool_kernel<<<BZV * LL * CC / 256, 256>>>(
        F + F_X, pr, pc, F + F_PR, F + F_PC);

    // all 5 projections in one batched launch; V pre-converted to tf32 bits
    {
        GemmArgs a;
        a.j[0] = {F+F_XPR, w_q_row, b_q_row, F+F_QROW, SCALE, 0, MQ, 0};
        a.j[1] = {F+F_XPC, w_q_col, b_q_col, F+F_QCOL, SCALE, 0, MQ, 0};
        a.j[2] = {F+F_X,   w_v,     b_v,     F+F_V,    1.0f, 0, MQ, 1};
        a.j[3] = {F+F_PR,  w_k_row, b_k_row, F+F_KROW, 1.0f, 0, BZV*LL, 0};
        a.j[4] = {F+F_PC,  w_k_col, b_k_col, F+F_KCOL, 1.0f, 0, BZV*LL, 0};
        gemm_tf32<128,128,64,32><<<dim3(CC/128, MQ/128, 5), 256>>>(a, CC, CC);
    }

    attn_fused<<<dim3(NQ/64, NH, BZV), 128, AT_TOTAL_U32 * 4>>>(
        F+F_QROW, F+F_QCOL, F+F_KROW, F+F_KCOL, pm, F+F_V, F+F_ATTN);

    {
        GemmArgs a;
        a.j[0] = {F+F_ATTN, w_out, b_out, F+F_ATTNOUT, 1.0f, 0, MQ, 0};
        a.j[1] = a.j[0]; a.j[2] = a.j[0]; a.j[3] = a.j[0]; a.j[4] = a.j[0];
        gemm_tf32<128,128,64,32><<<dim3(CC/128, MQ/128, 1), 256>>>(a, CC, CC);
    }
    add_ln<<<MQ/32, 256>>>(F+F_X, F+F_ATTNOUT, n1g, n1b, F+F_X1, 0);

    {
        GemmArgs a;
        a.j[0] = {F+F_X1, l1w, l1b, F+F_FFN, 1.0f, 1, MQ, 0};
        a.j[1] = a.j[0]; a.j[2] = a.j[0]; a.j[3] = a.j[0]; a.j[4] = a.j[0];
        gemm_tf32<128,128,64,32><<<dim3(DFFN/128, MQ/128, 1), 256>>>(a, DFFN, CC);
    }
    {
        GemmArgs a;
        a.j[0] = {F+F_FFN, l2w, l2b, F+F_Y, 1.0f, 0, MQ, 0};
        a.j[1] = a.j[0]; a.j[2] = a.j[0]; a.j[3] = a.j[0]; a.j[4] = a.j[0];
        gemm_tf32<128,128,64,32><<<dim3(CC/128, MQ/128, 1), 256>>>(a, CC, DFFN);
    }
    add_ln<<<MQ/32, 256>>>(F+F_X1, F+F_Y, n2g, n2b, out, 1);
}